// round 4
// baseline (speedup 1.0000x reference)
#include <cuda_runtime.h>
#include <math.h>

#define BB 2
#define LL 1024
#define DM 768
#define NH 12
#define DKK 64
#define FFD 3072
#define PH 32
#define ROWS (BB*LL)

// ---------------- scratch ----------------
__device__ float g_Q[BB*NH*LL*DKK];
__device__ float g_K[BB*NH*LL*DKK];
__device__ float g_V[BB*NH*LL*DKK];
__device__ float g_S[(size_t)BB*NH*LL*LL];
__device__ float g_O[BB*LL*DM];
__device__ float g_Xres[BB*LL*DM];
__device__ float g_X1[BB*LL*DM];
__device__ float g_H1[BB*LL*FFD];

// ---------------- helpers ----------------
__device__ __forceinline__ unsigned tf32u(float x) {
    unsigned u;
    asm("cvt.rna.tf32.f32 %0, %1;" : "=r"(u) : "f"(x));
    return u;
}
__device__ __forceinline__ float tf32f(float x) { return __uint_as_float(tf32u(x)); }

__device__ __forceinline__ void mma_tf32(float* c, const unsigned* a, const unsigned* b) {
    asm volatile(
        "mma.sync.aligned.m16n8k8.row.col.f32.tf32.tf32.f32 "
        "{%0,%1,%2,%3}, {%4,%5,%6,%7}, {%8,%9}, {%0,%1,%2,%3};"
        : "+f"(c[0]), "+f"(c[1]), "+f"(c[2]), "+f"(c[3])
        : "r"(a[0]), "r"(a[1]), "r"(a[2]), "r"(a[3]), "r"(b[0]), "r"(b[1]));
}

__device__ __forceinline__ void cp16(float* dst_smem, const float* src) {
    unsigned d = (unsigned)__cvta_generic_to_shared(dst_smem);
    asm volatile("cp.async.cg.shared.global [%0], [%1], 16;" :: "r"(d), "l"(src));
}
__device__ __forceinline__ void cp_commit() { asm volatile("cp.async.commit_group;"); }
template<int N> __device__ __forceinline__ void cp_wait() {
    asm volatile("cp.async.wait_group %0;" :: "n"(N));
}

// ---------------- tensor-core GEMM (cp.async 2-stage pipeline) ----------------
template<int EPI, bool BT, int BN, int WN>
__global__ __launch_bounds__(256, 2) void tgemm(
    const float* __restrict__ A, int lda, long sAz,
    const float* __restrict__ B, int ldb, long sBz,
    const float* __restrict__ bias,
    const float* __restrict__ Rres,
    float* __restrict__ C, int ldc, long sCz,
    int K, float alpha,
    const float* __restrict__ B1, const float* __restrict__ B2,
    const float* __restrict__ bias1, const float* __restrict__ bias2,
    float* __restrict__ C1, float* __restrict__ C2)
{
    constexpr int NT = WN / 8;
    constexpr int AP = 20;
    constexpr int BP = BN + 4;
    constexpr int ASZ = 128 * AP;
    constexpr int BSZ = BT ? BN * AP : 16 * BP;
    __shared__ float As[2 * ASZ];
    __shared__ float Bs[2 * BSZ];

    const int tid = threadIdx.x;
    const int lane = tid & 31, w = tid >> 5;
    const int wm = w & 1, wn = w >> 1;
    const int g = lane >> 2, t4 = lane & 3;
    const int bz = blockIdx.z;
    int bx = blockIdx.x;
    const int m0 = blockIdx.y * 128;

    const float* Ap = A + (size_t)bz * sAz;
    const float* Bp; const float* biasp = bias; float* Cp;
    if (EPI == 3) {
        int sel = bx / 6; bx -= sel * 6;
        Bp    = sel == 0 ? B    : (sel == 1 ? B1    : B2);
        biasp = sel == 0 ? bias : (sel == 1 ? bias1 : bias2);
        Cp    = sel == 0 ? C    : (sel == 1 ? C1    : C2);
    } else {
        Bp = B + (size_t)bz * sBz;
        Cp = C + (size_t)bz * sCz;
    }
    const int n0 = bx * BN;

    float acc[4][NT][4];
    #pragma unroll
    for (int i = 0; i < 4; i++)
        #pragma unroll
        for (int j = 0; j < NT; j++)
            #pragma unroll
            for (int q = 0; q < 4; q++) acc[i][j][q] = 0.f;

    auto loadA = [&](int kt, int st) {
        #pragma unroll
        for (int i = 0; i < 2; i++) {
            int idx = tid + i * 256;
            int m = idx >> 2, k4 = (idx & 3) << 2;
            cp16(&As[st * ASZ + m * AP + k4], Ap + (size_t)(m0 + m) * lda + kt + k4);
        }
    };
    auto loadB = [&](int kt, int st) {
        if (BT) {
            #pragma unroll
            for (int i = 0; i < 2; i++) {
                int idx = tid + i * 256;
                int n = idx >> 2, k4 = (idx & 3) << 2;
                cp16(&Bs[st * BSZ + n * AP + k4], Bp + (size_t)(n0 + n) * ldb + kt + k4);
            }
        } else if (BN == 128) {
            #pragma unroll
            for (int i = 0; i < 2; i++) {
                int idx = tid + i * 256;
                int k = idx >> 5, n4 = (idx & 31) << 2;
                cp16(&Bs[st * BSZ + k * BP + n4], Bp + (size_t)(kt + k) * ldb + n0 + n4);
            }
        } else {
            int k = tid >> 4, n4 = (tid & 15) << 2;
            cp16(&Bs[st * BSZ + k * BP + n4], Bp + (size_t)(kt + k) * ldb + n0 + n4);
        }
    };
    auto compute = [&](int st) {
        #pragma unroll
        for (int kk = 0; kk < 2; kk++) {
            const int kc = kk * 8 + t4;
            unsigned aF[4][4];
            #pragma unroll
            for (int i = 0; i < 4; i++) {
                int mb = wm * 64 + i * 16 + g;
                aF[i][0] = tf32u(As[st * ASZ + mb * AP + kc]);
                aF[i][1] = tf32u(As[st * ASZ + (mb + 8) * AP + kc]);
                aF[i][2] = tf32u(As[st * ASZ + mb * AP + kc + 4]);
                aF[i][3] = tf32u(As[st * ASZ + (mb + 8) * AP + kc + 4]);
            }
            unsigned bF[NT][2];
            #pragma unroll
            for (int j = 0; j < NT; j++) {
                int nb = wn * WN + j * 8 + g;
                if (BT) {
                    bF[j][0] = tf32u(Bs[st * BSZ + nb * AP + kc]);
                    bF[j][1] = tf32u(Bs[st * BSZ + nb * AP + kc + 4]);
                } else {
                    bF[j][0] = tf32u(Bs[st * BSZ + kc * BP + nb]);
                    bF[j][1] = tf32u(Bs[st * BSZ + (kc + 4) * BP + nb]);
                }
            }
            #pragma unroll
            for (int i = 0; i < 4; i++)
                #pragma unroll
                for (int j = 0; j < NT; j++)
                    mma_tf32(acc[i][j], aF[i], bF[j]);
        }
    };

    const int nt = K >> 4;
    loadA(0, 0); loadB(0, 0); cp_commit();
    for (int t = 0; t < nt; t++) {
        int cur = t & 1;
        if (t + 1 < nt) {
            loadA((t + 1) << 4, (t + 1) & 1);
            loadB((t + 1) << 4, (t + 1) & 1);
            cp_commit();
            cp_wait<1>();
        } else {
            cp_wait<0>();
        }
        __syncthreads();
        compute(cur);
        __syncthreads();
    }

    auto epi = [&](int row, int col, float2 v) {
        if (EPI == 4) {
            float2 old = *(const float2*)(Cp + (size_t)row * ldc + col);
            v.x = fmaf(v.x, alpha, old.x);
            v.y = fmaf(v.y, alpha, old.y);
            *(float2*)(Cp + (size_t)row * ldc + col) = v;
            return;
        }
        float2 bb = *(const float2*)(biasp + col);
        v.x += bb.x; v.y += bb.y;
        if (EPI == 1) { v.x = fmaxf(v.x, 0.f); v.y = fmaxf(v.y, 0.f); }
        if (EPI == 2) {
            float2 r = *(const float2*)(Rres + (size_t)row * ldc + col);
            v.x += r.x; v.y += r.y;
        }
        if (EPI == 3) {
            int h = col >> 6, d = col & 63;
            float* dst = Cp + ((((size_t)(row >> 10) * NH + h) * LL + (row & 1023)) * DKK + d);
            *(float2*)dst = v;
            return;
        }
        *(float2*)(Cp + (size_t)row * ldc + col) = v;
    };

    #pragma unroll
    for (int i = 0; i < 4; i++) {
        int r0 = m0 + wm * 64 + i * 16 + g;
        #pragma unroll
        for (int j = 0; j < NT; j++) {
            int col = n0 + wn * WN + j * 8 + t4 * 2;
            epi(r0,     col, make_float2(acc[i][j][0], acc[i][j][1]));
            epi(r0 + 8, col, make_float2(acc[i][j][2], acc[i][j][3]));
        }
    }
}

// ---------------- flash attention: QK^T + bias + online softmax + PV ----------------
// Grid (1, LL/128, BB*NH). 256 thr, 8 warps: wm = w&3 (m=32 each), wn = w>>2 (n=32 each).
// Pair-interleaved smem layout: entry[(kk*4+c)*STR + r] is float2 {X[r][kk*8+c], X[r][kk*8+c+4]}.
#define QSTR 132
#define KSTR 68
#define FL_QSZ (32*QSTR*2)
#define FL_KSZ (32*KSTR*2)
struct FlashSmem {
    float Qs[FL_QSZ];
    float Ss[FL_QSZ];
    float Ks[FL_KSZ];
    float Vs[FL_KSZ];
    float rowScale[128];
    float rowInv[128];
};
#define FL_SMEM_BYTES sizeof(FlashSmem)

__global__ __launch_bounds__(256, 2) void flash_kernel(
    const float* __restrict__ S, const float* __restrict__ Q,
    const float* __restrict__ K, const float* __restrict__ V,
    float* __restrict__ O)
{
    extern __shared__ char smraw[];
    FlashSmem& sm = *reinterpret_cast<FlashSmem*>(smraw);

    const int tid = threadIdx.x;
    const int lane = tid & 31, w = tid >> 5;
    const int wm = w & 3, wn = w >> 2;
    const int g = lane >> 2, t4 = lane & 3;
    const int bh = blockIdx.z, b = bh / NH, h = bh % NH;
    const int q0 = blockIdx.y * 128;

    const float* Qp = Q + ((size_t)bh * LL + q0) * DKK;
    const float* Kp = K + (size_t)bh * LL * DKK;
    const float* Vp = V + (size_t)bh * LL * DKK;
    const float* Sb = S + ((size_t)bh * LL + q0) * LL;

    // ---- load Q once: scale 1/8, round to tf32, pair-interleave ----
    #pragma unroll
    for (int i = 0; i < 8; i++) {
        int idx = tid + i * 256;
        int r = idx >> 4, d4 = (idx & 15) << 2;
        float4 v = *(const float4*)(Qp + (size_t)r * DKK + d4);
        int kk = d4 >> 3, hh = (d4 >> 2) & 1;
        float* p = sm.Qs + ((kk * 4) * QSTR + r) * 2 + hh;
        p[0]        = tf32f(v.x * 0.125f);
        p[QSTR*2]   = tf32f(v.y * 0.125f);
        p[QSTR*4]   = tf32f(v.z * 0.125f);
        p[QSTR*6]   = tf32f(v.w * 0.125f);
    }

    float accO[2][4][4];
    #pragma unroll
    for (int i = 0; i < 2; i++)
        #pragma unroll
        for (int j = 0; j < 4; j++)
            #pragma unroll
            for (int q = 0; q < 4; q++) accO[i][j][q] = 0.f;

    float rowM = -1e30f, rowL = 0.f;
    const int myrow = tid >> 1, half = tid & 1;

    float4 kvK[4], kvV[4];
    auto ldg_kv = [&](int t) {
        const float* kp = Kp + (size_t)t * 64 * DKK;
        const float* vp = Vp + (size_t)t * 64 * DKK;
        #pragma unroll
        for (int i = 0; i < 4; i++) {
            int idx = tid + i * 256;
            int r = idx >> 4, d4 = (idx & 15) << 2;
            kvK[i] = *(const float4*)(kp + (size_t)r * DKK + d4);
            kvV[i] = *(const float4*)(vp + (size_t)r * DKK + d4);
        }
    };
    auto sts_kv = [&]() {
        #pragma unroll
        for (int i = 0; i < 4; i++) {
            int idx = tid + i * 256;
            int r = idx >> 4, d4 = (idx & 15) << 2;
            // K: pair over d (inner-dim)
            {
                int kk = d4 >> 3, hh = (d4 >> 2) & 1;
                float* p = sm.Ks + ((kk * 4) * KSTR + r) * 2 + hh;
                p[0]       = tf32f(kvK[i].x);
                p[KSTR*2]  = tf32f(kvK[i].y);
                p[KSTR*4]  = tf32f(kvK[i].z);
                p[KSTR*6]  = tf32f(kvK[i].w);
            }
            // V: pair over k (row index r), columns d4..d4+3
            {
                int kk = r >> 3, cc = r & 3, hh = (r >> 2) & 1;
                float* p = sm.Vs + ((kk * 4 + cc) * KSTR + d4) * 2 + hh;
                p[0] = tf32f(kvV[i].x);
                p[2] = tf32f(kvV[i].y);
                p[4] = tf32f(kvV[i].z);
                p[6] = tf32f(kvV[i].w);
            }
        }
    };

    ldg_kv(0);

    for (int t = 0; t < 16; t++) {
        sts_kv();
        __syncthreads();
        if (t + 1 < 16) ldg_kv(t + 1);

        // ---- accS init from bias tile (posbias output in S) ----
        float accS[2][4][4];
        const int k0 = t * 64;
        #pragma unroll
        for (int i = 0; i < 2; i++) {
            int r = wm * 32 + i * 16 + g;
            #pragma unroll
            for (int j = 0; j < 4; j++) {
                int col = k0 + wn * 32 + j * 8 + t4 * 2;
                float2 b0 = *(const float2*)(Sb + (size_t)r * LL + col);
                float2 b1 = *(const float2*)(Sb + (size_t)(r + 8) * LL + col);
                accS[i][j][0] = b0.x; accS[i][j][1] = b0.y;
                accS[i][j][2] = b1.x; accS[i][j][3] = b1.y;
            }
        }

        // ---- QK^T mma ----
        #pragma unroll
        for (int kk = 0; kk < 8; kk++) {
            unsigned aF[2][4];
            #pragma unroll
            for (int i = 0; i < 2; i++) {
                int mb = wm * 32 + i * 16 + g;
                float2 lo = *(const float2*)(sm.Qs + ((kk * 4 + t4) * QSTR + mb) * 2);
                float2 hi = *(const float2*)(sm.Qs + ((kk * 4 + t4) * QSTR + mb + 8) * 2);
                aF[i][0] = __float_as_uint(lo.x);
                aF[i][1] = __float_as_uint(hi.x);
                aF[i][2] = __float_as_uint(lo.y);
                aF[i][3] = __float_as_uint(hi.y);
            }
            unsigned bF[4][2];
            #pragma unroll
            for (int j = 0; j < 4; j++) {
                int nb = wn * 32 + j * 8 + g;
                float2 bb = *(const float2*)(sm.Ks + ((kk * 4 + t4) * KSTR + nb) * 2);
                bF[j][0] = __float_as_uint(bb.x);
                bF[j][1] = __float_as_uint(bb.y);
            }
            #pragma unroll
            for (int i = 0; i < 2; i++)
                #pragma unroll
                for (int j = 0; j < 4; j++)
                    mma_tf32(accS[i][j], aF[i], bF[j]);
        }

        // ---- store scores to Ss (pair layout) ----
        {
            const int cc = (t4 & 1) * 2, hh = t4 >> 1;
            #pragma unroll
            for (int i = 0; i < 2; i++) {
                int r = wm * 32 + i * 16 + g;
                #pragma unroll
                for (int j = 0; j < 4; j++) {
                    int colk = ((wn * 32 + j * 8 + t4 * 2) >> 3);
                    int e = (colk * 4 + cc) * QSTR + r;
                    sm.Ss[e * 2 + hh]               = accS[i][j][0];
                    sm.Ss[(e + QSTR) * 2 + hh]      = accS[i][j][1];
                    sm.Ss[(e + 8) * 2 + hh]         = accS[i][j][2];
                    sm.Ss[(e + QSTR + 8) * 2 + hh]  = accS[i][j][3];
                }
            }
        }
        __syncthreads();

        // ---- online softmax row stats (2 threads per row, 32 cols each) ----
        {
            float2 vals[16];
            float mx = -1e30f;
            #pragma unroll
            for (int e = 0; e < 16; e++) {
                int kk = 4 * half + (e >> 2), cc = e & 3;
                vals[e] = *(const float2*)(sm.Ss + ((kk * 4 + cc) * QSTR + myrow) * 2);
                mx = fmaxf(mx, fmaxf(vals[e].x, vals[e].y));
            }
            mx = fmaxf(mx, __shfl_xor_sync(0xffffffffu, mx, 1));
            float mNew = fmaxf(rowM, mx);
            float scale = __expf(rowM - mNew);
            float sum = 0.f;
            #pragma unroll
            for (int e = 0; e < 16; e++) {
                vals[e].x = __expf(vals[e].x - mNew);
                vals[e].y = __expf(vals[e].y - mNew);
                sum += vals[e].x + vals[e].y;
                int kk = 4 * half + (e >> 2), cc = e & 3;
                *(float2*)(sm.Ss + ((kk * 4 + cc) * QSTR + myrow) * 2) =
                    make_float2(tf32f(vals[e].x), tf32f(vals[e].y));
            }
            sum += __shfl_xor_sync(0xffffffffu, sum, 1);
            rowL = rowL * scale + sum;
            rowM = mNew;
            if (half == 0) sm.rowScale[myrow] = scale;
        }
        __syncthreads();

        // ---- rescale accO ----
        #pragma unroll
        for (int i = 0; i < 2; i++) {
            int r = wm * 32 + i * 16 + g;
            float s0 = sm.rowScale[r], s1 = sm.rowScale[r + 8];
            #pragma unroll
            for (int j = 0; j < 4; j++) {
                accO[i][j][0] *= s0; accO[i][j][1] *= s0;
                accO[i][j][2] *= s1; accO[i][j][3] *= s1;
            }
        }

        // ---- accO += P @ V ----
        #pragma unroll
        for (int kk = 0; kk < 8; kk++) {
            unsigned aF[2][4];
            #pragma unroll
            for (int i = 0; i < 2; i++) {
                int mb = wm * 32 + i * 16 + g;
                float2 lo = *(const float2*)(sm.Ss + ((kk * 4 + t4) * QSTR + mb) * 2);
                float2 hi = *(const float2*)(sm.Ss + ((kk * 4 + t4) * QSTR + mb + 8) * 2);
                aF[i][0] = __float_as_uint(lo.x);
                aF[i][1] = __float_as_uint(hi.x);
                aF[i][2] = __float_as_uint(lo.y);
                aF[i][3] = __float_as_uint(hi.y);
            }
            unsigned bF[4][2];
            #pragma unroll
            for (int j = 0; j < 4; j++) {
                int nb = wn * 32 + j * 8 + g;
                float2 bb = *(const float2*)(sm.Vs + ((kk * 4 + t4) * KSTR + nb) * 2);
                bF[j][0] = __float_as_uint(bb.x);
                bF[j][1] = __float_as_uint(bb.y);
            }
            #pragma unroll
            for (int i = 0; i < 2; i++)
                #pragma unroll
                for (int j = 0; j < 4; j++)
                    mma_tf32(accO[i][j], aF[i], bF[j]);
        }
        __syncthreads();
    }

    if (half == 0) sm.rowInv[myrow] = 1.f / rowL;
    __syncthreads();

    float* Op = O + ((size_t)b * LL + q0) * DM + h * DKK;
    #pragma unroll
    for (int i = 0; i < 2; i++) {
        int r = wm * 32 + i * 16 + g;
        float i0 = sm.rowInv[r], i1 = sm.rowInv[r + 8];
        #pragma unroll
        for (int j = 0; j < 4; j++) {
            int col = wn * 32 + j * 8 + t4 * 2;
            *(float2*)(Op + (size_t)r * DM + col) =
                make_float2(accO[i][j][0] * i0, accO[i][j][1] * i0);
            *(float2*)(Op + (size_t)(r + 8) * DM + col) =
                make_float2(accO[i][j][2] * i1, accO[i][j][3] * i1);
        }
    }
}

// ---------------- relative-position bias MLP -> S (b,h,q,k) ----------------
__global__ __launch_bounds__(256) void posbias_kernel(
    const float* __restrict__ sx, const float* __restrict__ sy,
    const float* __restrict__ P1, const float* __restrict__ pb1,
    const float* __restrict__ P2, const float* __restrict__ pb2,
    float* __restrict__ S)
{
    __shared__ float sP1[2*PH], sPb1[PH], sP2[PH*NH], sPb2[NH];
    __shared__ float qx[16], qy[16], kx[16], ky[16];
    const int b  = blockIdx.z;
    const int q0 = blockIdx.y * 16, k0 = blockIdx.x * 16;
    const int tid = threadIdx.x;

    if (tid < 2*PH) sP1[tid] = P1[tid];
    if (tid < PH)   sPb1[tid] = pb1[tid];
    if (tid < NH)   sPb2[tid] = pb2[tid];
    for (int i = tid; i < PH*NH; i += 256) sP2[i] = P2[i];
    if (tid < 16) {
        qx[tid] = sx[b*LL + q0 + tid];
        qy[tid] = sy[b*LL + q0 + tid];
        kx[tid] = sx[b*LL + k0 + tid];
        ky[tid] = sy[b*LL + k0 + tid];
    }
    __syncthreads();

    const int kq = tid & 15;
    const int qq = tid >> 4;
    float rx = fminf(fmaxf(qx[qq] - kx[kq], -1000.f), 1000.f) * 0.001f;
    float ry = fminf(fmaxf(qy[qq] - ky[kq], -1000.f), 1000.f) * 0.001f;

    float hbuf[PH];
    #pragma unroll
    for (int j = 0; j < PH; j++)
        hbuf[j] = fmaxf(fmaf(rx, sP1[j], fmaf(ry, sP1[PH+j], sPb1[j])), 0.f);

    const int q = q0 + qq, k = k0 + kq;
    #pragma unroll
    for (int h = 0; h < NH; h++) {
        float s = sPb2[h];
        #pragma unroll
        for (int j = 0; j < PH; j++) s = fmaf(hbuf[j], sP2[j*NH + h], s);
        S[((size_t)(b*NH + h) * LL + q) * LL + k] = s;
    }
}

// ---------------- layernorm over last dim (768) ----------------
__global__ __launch_bounds__(256) void layernorm_kernel(
    const float* __restrict__ X, const float* __restrict__ g, const float* __restrict__ be,
    float* __restrict__ Y)
{
    __shared__ float red[256];
    const size_t row = blockIdx.x;
    const float* p = X + row * DM;
    float* o = Y + row * DM;
    const int tid = threadIdx.x;
    float v[3];
    float s = 0.f;
    #pragma unroll
    for (int i = 0; i < 3; i++) { v[i] = p[tid + i*256]; s += v[i]; }
    red[tid] = s; __syncthreads();
    for (int st = 128; st > 0; st >>= 1) { if (tid < st) red[tid] += red[tid+st]; __syncthreads(); }
    float mean = red[0] * (1.f/DM); __syncthreads();
    float sq = 0.f;
    #pragma unroll
    for (int i = 0; i < 3; i++) { float d = v[i] - mean; sq += d*d; }
    red[tid] = sq; __syncthreads();
    for (int st = 128; st > 0; st >>= 1) { if (tid < st) red[tid] += red[tid+st]; __syncthreads(); }
    float rstd = rsqrtf(red[0] * (1.f/DM) + 1e-5f);
    #pragma unroll
    for (int i = 0; i < 3; i++) {
        int c = tid + i*256;
        o[c] = (v[i] - mean) * rstd * g[c] + be[c];
    }
}

// ---------------- launch ----------------
extern "C" void kernel_launch(void* const* d_in, const int* in_sizes, int n_in,
                              void* d_out, int out_size)
{
    const float* src = (const float*)d_in[0];
    const float* sx  = (const float*)d_in[1];
    const float* sy  = (const float*)d_in[2];
    const float* Wq  = (const float*)d_in[3];  const float* bq  = (const float*)d_in[4];
    const float* Wk  = (const float*)d_in[5];  const float* bk  = (const float*)d_in[6];
    const float* Wv  = (const float*)d_in[7];  const float* bv  = (const float*)d_in[8];
    const float* Wo  = (const float*)d_in[9];  const float* bo  = (const float*)d_in[10];
    const float* P1  = (const float*)d_in[11]; const float* pb1 = (const float*)d_in[12];
    const float* P2  = (const float*)d_in[13]; const float* pb2 = (const float*)d_in[14];
    const float* W1  = (const float*)d_in[15]; const float* b1  = (const float*)d_in[16];
    const float* W2  = (const float*)d_in[17]; const float* b2  = (const float*)d_in[18];
    const float* g1  = (const float*)d_in[19]; const float* be1 = (const float*)d_in[20];
    const float* g2  = (const float*)d_in[21]; const float* be2 = (const float*)d_in[22];
    float* out = (float*)d_out;

    float *Q, *K, *V, *S, *O, *Xres, *X1, *H1;
    cudaGetSymbolAddress((void**)&Q,    g_Q);
    cudaGetSymbolAddress((void**)&K,    g_K);
    cudaGetSymbolAddress((void**)&V,    g_V);
    cudaGetSymbolAddress((void**)&S,    g_S);
    cudaGetSymbolAddress((void**)&O,    g_O);
    cudaGetSymbolAddress((void**)&Xres, g_Xres);
    cudaGetSymbolAddress((void**)&X1,   g_X1);
    cudaGetSymbolAddress((void**)&H1,   g_H1);

    cudaFuncSetAttribute(flash_kernel, cudaFuncAttributeMaxDynamicSharedMemorySize,
                         (int)FL_SMEM_BYTES);

    // 1) relative-position bias -> S
    posbias_kernel<<<dim3(LL/16, LL/16, BB), 256>>>(sx, sy, P1, pb1, P2, pb2, S);

    // 2) fused QKV projections, scatter to (b,h,l,d)
    tgemm<3, false, 128, 32><<<dim3(18, ROWS/128, 1), 256>>>(
        src, DM, 0, Wq, DM, 0, bq, nullptr, Q, 0, 0, DM, 1.f,
        Wk, Wv, bk, bv, K, V);

    // 3) flash attention: softmax(QK^T/8 + bias) @ V -> O
    flash_kernel<<<dim3(1, LL/128, BB*NH), 256, FL_SMEM_BYTES>>>(S, Q, K, V, O);

    // 4) Xres = src + O @ Wo + bo ; LN1 -> X1
    tgemm<2, false, 64, 16><<<dim3(DM/64, ROWS/128, 1), 256>>>(
        O, DM, 0, Wo, DM, 0, bo, src, Xres, DM, 0, DM, 1.f,
        nullptr, nullptr, nullptr, nullptr, nullptr, nullptr);
    layernorm_kernel<<<ROWS, 256>>>(Xres, g1, be1, X1);

    // 5) FFN
    tgemm<1, false, 128, 32><<<dim3(FFD/128, ROWS/128, 1), 256>>>(
        X1, DM, 0, W1, FFD, 0, b1, nullptr, H1, FFD, 0, DM, 1.f,
        nullptr, nullptr, nullptr, nullptr, nullptr, nullptr);
    tgemm<2, false, 64, 16><<<dim3(DM/64, ROWS/128, 1), 256>>>(
        H1, FFD, 0, W2, DM, 0, b2, X1, Xres, DM, 0, FFD, 1.f,
        nullptr, nullptr, nullptr, nullptr, nullptr, nullptr);

    // 6) LN2 -> output
    layernorm_kernel<<<ROWS, 256>>>(Xres, g2, be2, out);
}

// round 5
// speedup vs baseline: 1.1006x; 1.1006x over previous
#include <cuda_runtime.h>
#include <math.h>

#define BB 2
#define LL 1024
#define DM 768
#define NH 12
#define DKK 64
#define FFD 3072
#define PH 32
#define ROWS (BB*LL)

// ---------------- scratch ----------------
__device__ float g_Q[BB*NH*LL*DKK];
__device__ float g_K[BB*NH*LL*DKK];
__device__ float g_V[BB*NH*LL*DKK];
__device__ float g_S[(size_t)BB*NH*LL*LL];
__device__ float g_O[BB*LL*DM];
__device__ float g_Xres[BB*LL*DM];
__device__ float g_X1[BB*LL*DM];
__device__ float g_H1[BB*LL*FFD];

// ---------------- helpers ----------------
__device__ __forceinline__ unsigned tf32u(float x) {
    unsigned u;
    asm("cvt.rna.tf32.f32 %0, %1;" : "=r"(u) : "f"(x));
    return u;
}
__device__ __forceinline__ float tf32f(float x) { return __uint_as_float(tf32u(x)); }

__device__ __forceinline__ void mma_tf32(float* c, const unsigned* a, const unsigned* b) {
    asm volatile(
        "mma.sync.aligned.m16n8k8.row.col.f32.tf32.tf32.f32 "
        "{%0,%1,%2,%3}, {%4,%5,%6,%7}, {%8,%9}, {%0,%1,%2,%3};"
        : "+f"(c[0]), "+f"(c[1]), "+f"(c[2]), "+f"(c[3])
        : "r"(a[0]), "r"(a[1]), "r"(a[2]), "r"(a[3]), "r"(b[0]), "r"(b[1]));
}

__device__ __forceinline__ void cp16(float* dst_smem, const float* src) {
    unsigned d = (unsigned)__cvta_generic_to_shared(dst_smem);
    asm volatile("cp.async.cg.shared.global [%0], [%1], 16;" :: "r"(d), "l"(src));
}
__device__ __forceinline__ void cp_commit() { asm volatile("cp.async.commit_group;"); }
template<int N> __device__ __forceinline__ void cp_wait() {
    asm volatile("cp.async.wait_group %0;" :: "n"(N));
}

// ---------------- tensor-core GEMM (cp.async 2-stage pipeline) ----------------
template<int EPI, bool BT, int BN, int WN>
__global__ __launch_bounds__(256, 2) void tgemm(
    const float* __restrict__ A, int lda, long sAz,
    const float* __restrict__ B, int ldb, long sBz,
    const float* __restrict__ bias,
    const float* __restrict__ Rres,
    float* __restrict__ C, int ldc, long sCz,
    int K, float alpha,
    const float* __restrict__ B1, const float* __restrict__ B2,
    const float* __restrict__ bias1, const float* __restrict__ bias2,
    float* __restrict__ C1, float* __restrict__ C2)
{
    constexpr int NT = WN / 8;
    constexpr int AP = 20;
    constexpr int BP = BN + 4;
    constexpr int ASZ = 128 * AP;
    constexpr int BSZ = BT ? BN * AP : 16 * BP;
    __shared__ float As[2 * ASZ];
    __shared__ float Bs[2 * BSZ];

    const int tid = threadIdx.x;
    const int lane = tid & 31, w = tid >> 5;
    const int wm = w & 1, wn = w >> 1;
    const int g = lane >> 2, t4 = lane & 3;
    const int bz = blockIdx.z;
    int bx = blockIdx.x;
    const int m0 = blockIdx.y * 128;

    const float* Ap = A + (size_t)bz * sAz;
    const float* Bp; const float* biasp = bias; float* Cp;
    if (EPI == 3) {
        int sel = bx / 6; bx -= sel * 6;
        Bp    = sel == 0 ? B    : (sel == 1 ? B1    : B2);
        biasp = sel == 0 ? bias : (sel == 1 ? bias1 : bias2);
        Cp    = sel == 0 ? C    : (sel == 1 ? C1    : C2);
    } else {
        Bp = B + (size_t)bz * sBz;
        Cp = C + (size_t)bz * sCz;
    }
    const int n0 = bx * BN;

    float acc[4][NT][4];
    #pragma unroll
    for (int i = 0; i < 4; i++)
        #pragma unroll
        for (int j = 0; j < NT; j++)
            #pragma unroll
            for (int q = 0; q < 4; q++) acc[i][j][q] = 0.f;

    auto loadA = [&](int kt, int st) {
        #pragma unroll
        for (int i = 0; i < 2; i++) {
            int idx = tid + i * 256;
            int m = idx >> 2, k4 = (idx & 3) << 2;
            cp16(&As[st * ASZ + m * AP + k4], Ap + (size_t)(m0 + m) * lda + kt + k4);
        }
    };
    auto loadB = [&](int kt, int st) {
        if (BT) {
            #pragma unroll
            for (int i = 0; i < 2; i++) {
                int idx = tid + i * 256;
                int n = idx >> 2, k4 = (idx & 3) << 2;
                cp16(&Bs[st * BSZ + n * AP + k4], Bp + (size_t)(n0 + n) * ldb + kt + k4);
            }
        } else if (BN == 128) {
            #pragma unroll
            for (int i = 0; i < 2; i++) {
                int idx = tid + i * 256;
                int k = idx >> 5, n4 = (idx & 31) << 2;
                cp16(&Bs[st * BSZ + k * BP + n4], Bp + (size_t)(kt + k) * ldb + n0 + n4);
            }
        } else {
            int k = tid >> 4, n4 = (tid & 15) << 2;
            cp16(&Bs[st * BSZ + k * BP + n4], Bp + (size_t)(kt + k) * ldb + n0 + n4);
        }
    };
    auto compute = [&](int st) {
        #pragma unroll
        for (int kk = 0; kk < 2; kk++) {
            const int kc = kk * 8 + t4;
            unsigned aF[4][4];
            #pragma unroll
            for (int i = 0; i < 4; i++) {
                int mb = wm * 64 + i * 16 + g;
                aF[i][0] = tf32u(As[st * ASZ + mb * AP + kc]);
                aF[i][1] = tf32u(As[st * ASZ + (mb + 8) * AP + kc]);
                aF[i][2] = tf32u(As[st * ASZ + mb * AP + kc + 4]);
                aF[i][3] = tf32u(As[st * ASZ + (mb + 8) * AP + kc + 4]);
            }
            unsigned bF[NT][2];
            #pragma unroll
            for (int j = 0; j < NT; j++) {
                int nb = wn * WN + j * 8 + g;
                if (BT) {
                    bF[j][0] = tf32u(Bs[st * BSZ + nb * AP + kc]);
                    bF[j][1] = tf32u(Bs[st * BSZ + nb * AP + kc + 4]);
                } else {
                    bF[j][0] = tf32u(Bs[st * BSZ + kc * BP + nb]);
                    bF[j][1] = tf32u(Bs[st * BSZ + (kc + 4) * BP + nb]);
                }
            }
            #pragma unroll
            for (int i = 0; i < 4; i++)
                #pragma unroll
                for (int j = 0; j < NT; j++)
                    mma_tf32(acc[i][j], aF[i], bF[j]);
        }
    };

    const int nt = K >> 4;
    loadA(0, 0); loadB(0, 0); cp_commit();
    for (int t = 0; t < nt; t++) {
        int cur = t & 1;
        if (t + 1 < nt) {
            loadA((t + 1) << 4, (t + 1) & 1);
            loadB((t + 1) << 4, (t + 1) & 1);
            cp_commit();
            cp_wait<1>();
        } else {
            cp_wait<0>();
        }
        __syncthreads();
        compute(cur);
        __syncthreads();
    }

    auto epi = [&](int row, int col, float2 v) {
        if (EPI == 4) {
            float2 old = *(const float2*)(Cp + (size_t)row * ldc + col);
            v.x = fmaf(v.x, alpha, old.x);
            v.y = fmaf(v.y, alpha, old.y);
            *(float2*)(Cp + (size_t)row * ldc + col) = v;
            return;
        }
        float2 bb = *(const float2*)(biasp + col);
        v.x += bb.x; v.y += bb.y;
        if (EPI == 1) { v.x = fmaxf(v.x, 0.f); v.y = fmaxf(v.y, 0.f); }
        if (EPI == 2) {
            float2 r = *(const float2*)(Rres + (size_t)row * ldc + col);
            v.x += r.x; v.y += r.y;
        }
        if (EPI == 3) {
            int h = col >> 6, d = col & 63;
            float* dst = Cp + ((((size_t)(row >> 10) * NH + h) * LL + (row & 1023)) * DKK + d);
            *(float2*)dst = v;
            return;
        }
        *(float2*)(Cp + (size_t)row * ldc + col) = v;
    };

    #pragma unroll
    for (int i = 0; i < 4; i++) {
        int r0 = m0 + wm * 64 + i * 16 + g;
        #pragma unroll
        for (int j = 0; j < NT; j++) {
            int col = n0 + wn * WN + j * 8 + t4 * 2;
            epi(r0,     col, make_float2(acc[i][j][0], acc[i][j][1]));
            epi(r0 + 8, col, make_float2(acc[i][j][2], acc[i][j][3]));
        }
    }
}

// ---------------- flash64: QK^T + bias + online softmax + PV -----------------
// Grid (LL/64, BB*NH). 256 thr, 8 warps: wm=w&1 (32 rows), wn=w>>1 (16 cols).
// Q/S pair-interleaved (stride 68); K/V row-major stride 68 (cp.async direct).
#define FQSTR 68
struct Flash64Smem {
    float Qs[32*FQSTR*2];
    float Ss[32*FQSTR*2];
    float Ks[64*FQSTR];
    float Vs[64*FQSTR];
    float rowScale[64];
    float rowInv[64];
};
#define FL64_SMEM_BYTES sizeof(Flash64Smem)

__global__ __launch_bounds__(256, 3) void flash64_kernel(
    const float* __restrict__ S, const float* __restrict__ Q,
    const float* __restrict__ K, const float* __restrict__ V,
    float* __restrict__ O)
{
    extern __shared__ char smraw[];
    Flash64Smem& sm = *reinterpret_cast<Flash64Smem*>(smraw);

    const int tid = threadIdx.x;
    const int lane = tid & 31, w = tid >> 5;
    const int wm = w & 1, wn = w >> 1;
    const int g = lane >> 2, t4 = lane & 3;
    const int bh = blockIdx.y, b = bh / NH, h = bh % NH;
    const int q0 = blockIdx.x * 64;

    const float* Qp = Q + ((size_t)bh * LL + q0) * DKK;
    const float* Kp = K + (size_t)bh * LL * DKK;
    const float* Vp = V + (size_t)bh * LL * DKK;
    const float* Sb = S + ((size_t)bh * LL + q0) * LL;

    auto loadK = [&](int t) {
        #pragma unroll
        for (int i = 0; i < 4; i++) {
            int idx = tid + i * 256;
            int r = idx >> 4, d4 = (idx & 15) << 2;
            cp16(&sm.Ks[r * FQSTR + d4], Kp + (size_t)(t * 64 + r) * DKK + d4);
        }
        cp_commit();
    };
    auto loadV = [&](int t) {
        #pragma unroll
        for (int i = 0; i < 4; i++) {
            int idx = tid + i * 256;
            int r = idx >> 4, d4 = (idx & 15) << 2;
            cp16(&sm.Vs[r * FQSTR + d4], Vp + (size_t)(t * 64 + r) * DKK + d4);
        }
        cp_commit();
    };

    loadK(0);
    loadV(0);

    // Q: load once, scale 1/8, tf32, pair-interleave
    #pragma unroll
    for (int i = 0; i < 4; i++) {
        int idx = tid + i * 256;
        int r = idx >> 4, d4 = (idx & 15) << 2;
        float4 v = *(const float4*)(Qp + (size_t)r * DKK + d4);
        int kk = d4 >> 3, hh = (d4 >> 2) & 1;
        float* p = sm.Qs + ((kk * 4) * FQSTR + r) * 2 + hh;
        p[0]          = tf32f(v.x * 0.125f);
        p[FQSTR*2]    = tf32f(v.y * 0.125f);
        p[FQSTR*4]    = tf32f(v.z * 0.125f);
        p[FQSTR*6]    = tf32f(v.w * 0.125f);
    }

    float accO[2][2][4];
    #pragma unroll
    for (int i = 0; i < 2; i++)
        #pragma unroll
        for (int j = 0; j < 2; j++)
            #pragma unroll
            for (int q = 0; q < 4; q++) accO[i][j][q] = 0.f;

    float rowM = -1e30f, rowL = 0.f;
    const int myrow = tid >> 2, quarter = tid & 3;

    for (int t = 0; t < 16; t++) {
        // bias -> accS fragments (LDG issued before K-wait to share latency)
        float accS[2][2][4];
        const int kb = t * 64;
        #pragma unroll
        for (int i = 0; i < 2; i++) {
            int r = wm * 32 + i * 16 + g;
            #pragma unroll
            for (int j = 0; j < 2; j++) {
                int col = kb + wn * 16 + j * 8 + t4 * 2;
                float2 b0 = *(const float2*)(Sb + (size_t)r * LL + col);
                float2 b1 = *(const float2*)(Sb + (size_t)(r + 8) * LL + col);
                accS[i][j][0] = b0.x; accS[i][j][1] = b0.y;
                accS[i][j][2] = b1.x; accS[i][j][3] = b1.y;
            }
        }

        cp_wait<1>();           // K(t) landed (V(t) still pending)
        __syncthreads();

        // ---- QK^T ----
        #pragma unroll
        for (int ks = 0; ks < 8; ks++) {
            const int kc = ks * 8 + t4;
            unsigned aF[2][4];
            #pragma unroll
            for (int i = 0; i < 2; i++) {
                int mb = wm * 32 + i * 16 + g;
                float2 lo = *(const float2*)(sm.Qs + ((ks * 4 + t4) * FQSTR + mb) * 2);
                float2 hi = *(const float2*)(sm.Qs + ((ks * 4 + t4) * FQSTR + mb + 8) * 2);
                aF[i][0] = __float_as_uint(lo.x); aF[i][1] = __float_as_uint(hi.x);
                aF[i][2] = __float_as_uint(lo.y); aF[i][3] = __float_as_uint(hi.y);
            }
            unsigned bF[2][2];
            #pragma unroll
            for (int j = 0; j < 2; j++) {
                int nb = wn * 16 + j * 8 + g;
                bF[j][0] = tf32u(sm.Ks[nb * FQSTR + kc]);
                bF[j][1] = tf32u(sm.Ks[nb * FQSTR + kc + 4]);
            }
            #pragma unroll
            for (int i = 0; i < 2; i++)
                #pragma unroll
                for (int j = 0; j < 2; j++)
                    mma_tf32(accS[i][j], aF[i], bF[j]);
        }

        // ---- scores -> Ss (pair-interleaved) ----
        {
            const int cc = (t4 & 1) * 2, hh = t4 >> 1;
            #pragma unroll
            for (int i = 0; i < 2; i++) {
                int r = wm * 32 + i * 16 + g;
                #pragma unroll
                for (int j = 0; j < 2; j++) {
                    int colk = (wn * 16 + j * 8 + t4 * 2) >> 3;
                    int e = (colk * 4 + cc) * FQSTR + r;
                    sm.Ss[e * 2 + hh]                 = accS[i][j][0];
                    sm.Ss[(e + FQSTR) * 2 + hh]       = accS[i][j][1];
                    sm.Ss[(e + 8) * 2 + hh]           = accS[i][j][2];
                    sm.Ss[(e + FQSTR + 8) * 2 + hh]   = accS[i][j][3];
                }
            }
        }
        __syncthreads();                 // Ss visible; Ks free
        if (t + 1 < 16) loadK(t + 1);    // overlaps softmax + PV

        // ---- online softmax stats (4 threads per row, 16 cols each) ----
        {
            float2 vals[8];
            float mx = -1e30f;
            #pragma unroll
            for (int e = 0; e < 8; e++) {
                int kk = 2 * quarter + (e >> 2), cc2 = e & 3;
                vals[e] = *(const float2*)(sm.Ss + ((kk * 4 + cc2) * FQSTR + myrow) * 2);
                mx = fmaxf(mx, fmaxf(vals[e].x, vals[e].y));
            }
            mx = fmaxf(mx, __shfl_xor_sync(0xffffffffu, mx, 1));
            mx = fmaxf(mx, __shfl_xor_sync(0xffffffffu, mx, 2));
            float mNew = fmaxf(rowM, mx);
            float scale = __expf(rowM - mNew);
            float sum = 0.f;
            #pragma unroll
            for (int e = 0; e < 8; e++) {
                vals[e].x = __expf(vals[e].x - mNew);
                vals[e].y = __expf(vals[e].y - mNew);
                sum += vals[e].x + vals[e].y;
                int kk = 2 * quarter + (e >> 2), cc2 = e & 3;
                *(float2*)(sm.Ss + ((kk * 4 + cc2) * FQSTR + myrow) * 2) =
                    make_float2(tf32f(vals[e].x), tf32f(vals[e].y));
            }
            sum += __shfl_xor_sync(0xffffffffu, sum, 1);
            sum += __shfl_xor_sync(0xffffffffu, sum, 2);
            rowL = rowL * scale + sum;
            rowM = mNew;
            if (quarter == 0) sm.rowScale[myrow] = scale;
        }
        if (t + 1 < 16) cp_wait<1>(); else cp_wait<0>();   // V(t) landed
        __syncthreads();                 // P + rowScale visible

        // ---- rescale accO ----
        #pragma unroll
        for (int i = 0; i < 2; i++) {
            int r = wm * 32 + i * 16 + g;
            float s0 = sm.rowScale[r], s1 = sm.rowScale[r + 8];
            #pragma unroll
            for (int j = 0; j < 2; j++) {
                accO[i][j][0] *= s0; accO[i][j][1] *= s0;
                accO[i][j][2] *= s1; accO[i][j][3] *= s1;
            }
        }

        // ---- accO += P @ V ----
        #pragma unroll
        for (int ks = 0; ks < 8; ks++) {
            const int kc = ks * 8 + t4;
            unsigned aF[2][4];
            #pragma unroll
            for (int i = 0; i < 2; i++) {
                int mb = wm * 32 + i * 16 + g;
                float2 lo = *(const float2*)(sm.Ss + ((ks * 4 + t4) * FQSTR + mb) * 2);
                float2 hi = *(const float2*)(sm.Ss + ((ks * 4 + t4) * FQSTR + mb + 8) * 2);
                aF[i][0] = __float_as_uint(lo.x); aF[i][1] = __float_as_uint(hi.x);
                aF[i][2] = __float_as_uint(lo.y); aF[i][3] = __float_as_uint(hi.y);
            }
            unsigned bF[2][2];
            #pragma unroll
            for (int j = 0; j < 2; j++) {
                int nb = wn * 16 + j * 8 + g;
                bF[j][0] = tf32u(sm.Vs[kc * FQSTR + nb]);
                bF[j][1] = tf32u(sm.Vs[(kc + 4) * FQSTR + nb]);
            }
            #pragma unroll
            for (int i = 0; i < 2; i++)
                #pragma unroll
                for (int j = 0; j < 2; j++)
                    mma_tf32(accO[i][j], aF[i], bF[j]);
        }
        __syncthreads();                 // Vs free, Ss free
        if (t + 1 < 16) loadV(t + 1);    // overlaps next bias LDG + QK
    }

    if (quarter == 0) sm.rowInv[myrow] = 1.f / rowL;
    __syncthreads();

    float* Op = O + ((size_t)b * LL + q0) * DM + h * DKK;
    #pragma unroll
    for (int i = 0; i < 2; i++) {
        int r = wm * 32 + i * 16 + g;
        float i0 = sm.rowInv[r], i1 = sm.rowInv[r + 8];
        #pragma unroll
        for (int j = 0; j < 2; j++) {
            int col = wn * 16 + j * 8 + t4 * 2;
            *(float2*)(Op + (size_t)r * DM + col) =
                make_float2(accO[i][j][0] * i0, accO[i][j][1] * i0);
            *(float2*)(Op + (size_t)(r + 8) * DM + col) =
                make_float2(accO[i][j][2] * i1, accO[i][j][3] * i1);
        }
    }
}

// ---------------- posbias2: layer-1 scalar, layer-2 via tf32 mma ----------------
// Block = 16q x 16k pairs (256), 256 threads. bias[256 x 12] = H[256 x 32] @ P2[32 x 12].
__global__ __launch_bounds__(256) void posbias2_kernel(
    const float* __restrict__ sx, const float* __restrict__ sy,
    const float* __restrict__ P1, const float* __restrict__ pb1,
    const float* __restrict__ P2, const float* __restrict__ pb2,
    float* __restrict__ S)
{
    constexpr int HSTR = 260;
    constexpr int PSTR = 20;
    __shared__ float Hs[16 * HSTR * 2];
    __shared__ float Ps[16 * PSTR * 2];
    __shared__ float sP1[64], sPb1[32], sPb2[16];
    __shared__ float qx[16], qy[16], kx[16], ky[16];

    const int b = blockIdx.z;
    const int q0 = blockIdx.y * 16, k0 = blockIdx.x * 16;
    const int tid = threadIdx.x;
    const int lane = tid & 31, w = tid >> 5;
    const int g = lane >> 2, t4 = lane & 3;

    if (tid < 64) sP1[tid] = P1[tid];
    if (tid < 32) sPb1[tid] = pb1[tid];
    if (tid < 16) {
        sPb2[tid] = tid < NH ? pb2[tid] : 0.f;
        qx[tid] = sx[b*LL + q0 + tid];
        qy[tid] = sy[b*LL + q0 + tid];
        kx[tid] = sx[b*LL + k0 + tid];
        ky[tid] = sy[b*LL + k0 + tid];
    }
    // stage P2^T [16 x 32] pair-interleaved tf32
    #pragma unroll
    for (int ii = 0; ii < 2; ii++) {
        int v = tid + ii * 256;
        int n = v & 15, k = v >> 4;
        float val = (n < NH) ? P2[k * NH + n] : 0.f;
        int kk = k >> 3, hh = (k >> 2) & 1, cc = k & 3;
        Ps[((kk * 4 + cc) * PSTR + n) * 2 + hh] = tf32f(val);
    }
    __syncthreads();

    // layer 1: one pair per thread -> Hs (tf32, pair-interleaved)
    {
        int qq = tid >> 4, kq = tid & 15;
        float rx = fminf(fmaxf(qx[qq] - kx[kq], -1000.f), 1000.f) * 0.001f;
        float ry = fminf(fmaxf(qy[qq] - ky[kq], -1000.f), 1000.f) * 0.001f;
        #pragma unroll
        for (int kk = 0; kk < 4; kk++)
            #pragma unroll
            for (int cc = 0; cc < 4; cc++) {
                int j0 = kk * 8 + cc, j1 = j0 + 4;
                float h0 = fmaxf(fmaf(rx, sP1[j0], fmaf(ry, sP1[32+j0], sPb1[j0])), 0.f);
                float h1 = fmaxf(fmaf(rx, sP1[j1], fmaf(ry, sP1[32+j1], sPb1[j1])), 0.f);
                *(float2*)(&Hs[((kk * 4 + cc) * HSTR + tid) * 2]) =
                    make_float2(tf32f(h0), tf32f(h1));
            }
    }
    __syncthreads();

    // layer 2 mma: [256x32] @ [32x16]
    float acc[2][2][4];
    #pragma unroll
    for (int i = 0; i < 2; i++)
        #pragma unroll
        for (int j = 0; j < 2; j++)
            #pragma unroll
            for (int q = 0; q < 4; q++) acc[i][j][q] = 0.f;

    #pragma unroll
    for (int ks = 0; ks < 4; ks++) {
        unsigned aF[2][4];
        #pragma unroll
        for (int i = 0; i < 2; i++) {
            int mb = (w * 2 + i) * 16 + g;
            float2 lo = *(const float2*)(&Hs[((ks * 4 + t4) * HSTR + mb) * 2]);
            float2 hi = *(const float2*)(&Hs[((ks * 4 + t4) * HSTR + mb + 8) * 2]);
            aF[i][0] = __float_as_uint(lo.x); aF[i][1] = __float_as_uint(hi.x);
            aF[i][2] = __float_as_uint(lo.y); aF[i][3] = __float_as_uint(hi.y);
        }
        unsigned bF[2][2];
        #pragma unroll
        for (int j = 0; j < 2; j++) {
            float2 bb = *(const float2*)(&Ps[((ks * 4 + t4) * PSTR + j * 8 + g) * 2]);
            bF[j][0] = __float_as_uint(bb.x); bF[j][1] = __float_as_uint(bb.y);
        }
        #pragma unroll
        for (int i = 0; i < 2; i++)
            #pragma unroll
            for (int j = 0; j < 2; j++)
                mma_tf32(acc[i][j], aF[i], bF[j]);
    }

    // store: pair p -> (q = p>>4, k = p&15); col -> head
    #pragma unroll
    for (int i = 0; i < 2; i++) {
        int p0 = (w * 2 + i) * 16 + g;
        int p1 = p0 + 8;
        int q_0 = q0 + (p0 >> 4), k_0 = k0 + (p0 & 15);
        int q_1 = q0 + (p1 >> 4), k_1 = k0 + (p1 & 15);
        #pragma unroll
        for (int j = 0; j < 2; j++) {
            int c0 = j * 8 + t4 * 2, c1 = c0 + 1;
            if (c0 < NH) {
                S[((size_t)(b*NH + c0) * LL + q_0) * LL + k_0] = acc[i][j][0] + sPb2[c0];
                S[((size_t)(b*NH + c0) * LL + q_1) * LL + k_1] = acc[i][j][2] + sPb2[c0];
            }
            if (c1 < NH) {
                S[((size_t)(b*NH + c1) * LL + q_0) * LL + k_0] = acc[i][j][1] + sPb2[c1];
                S[((size_t)(b*NH + c1) * LL + q_1) * LL + k_1] = acc[i][j][3] + sPb2[c1];
            }
        }
    }
}

// ---------------- layernorm over last dim (768) ----------------
__global__ __launch_bounds__(256) void layernorm_kernel(
    const float* __restrict__ X, const float* __restrict__ g, const float* __restrict__ be,
    float* __restrict__ Y)
{
    __shared__ float red[256];
    const size_t row = blockIdx.x;
    const float* p = X + row * DM;
    float* o = Y + row * DM;
    const int tid = threadIdx.x;
    float v[3];
    float s = 0.f;
    #pragma unroll
    for (int i = 0; i < 3; i++) { v[i] = p[tid + i*256]; s += v[i]; }
    red[tid] = s; __syncthreads();
    for (int st = 128; st > 0; st >>= 1) { if (tid < st) red[tid] += red[tid+st]; __syncthreads(); }
    float mean = red[0] * (1.f/DM); __syncthreads();
    float sq = 0.f;
    #pragma unroll
    for (int i = 0; i < 3; i++) { float d = v[i] - mean; sq += d*d; }
    red[tid] = sq; __syncthreads();
    for (int st = 128; st > 0; st >>= 1) { if (tid < st) red[tid] += red[tid+st]; __syncthreads(); }
    float rstd = rsqrtf(red[0] * (1.f/DM) + 1e-5f);
    #pragma unroll
    for (int i = 0; i < 3; i++) {
        int c = tid + i*256;
        o[c] = (v[i] - mean) * rstd * g[c] + be[c];
    }
}

// ---------------- launch ----------------
extern "C" void kernel_launch(void* const* d_in, const int* in_sizes, int n_in,
                              void* d_out, int out_size)
{
    const float* src = (const float*)d_in[0];
    const float* sx  = (const float*)d_in[1];
    const float* sy  = (const float*)d_in[2];
    const float* Wq  = (const float*)d_in[3];  const float* bq  = (const float*)d_in[4];
    const float* Wk  = (const float*)d_in[5];  const float* bk  = (const float*)d_in[6];
    const float* Wv  = (const float*)d_in[7];  const float* bv  = (const float*)d_in[8];
    const float* Wo  = (const float*)d_in[9];  const float* bo  = (const float*)d_in[10];
    const float* P1  = (const float*)d_in[11]; const float* pb1 = (const float*)d_in[12];
    const float* P2  = (const float*)d_in[13]; const float* pb2 = (const float*)d_in[14];
    const float* W1  = (const float*)d_in[15]; const float* b1  = (const float*)d_in[16];
    const float* W2  = (const float*)d_in[17]; const float* b2  = (const float*)d_in[18];
    const float* g1  = (const float*)d_in[19]; const float* be1 = (const float*)d_in[20];
    const float* g2  = (const float*)d_in[21]; const float* be2 = (const float*)d_in[22];
    float* out = (float*)d_out;

    float *Q, *K, *V, *S, *O, *Xres, *X1, *H1;
    cudaGetSymbolAddress((void**)&Q,    g_Q);
    cudaGetSymbolAddress((void**)&K,    g_K);
    cudaGetSymbolAddress((void**)&V,    g_V);
    cudaGetSymbolAddress((void**)&S,    g_S);
    cudaGetSymbolAddress((void**)&O,    g_O);
    cudaGetSymbolAddress((void**)&Xres, g_Xres);
    cudaGetSymbolAddress((void**)&X1,   g_X1);
    cudaGetSymbolAddress((void**)&H1,   g_H1);

    cudaFuncSetAttribute(flash64_kernel, cudaFuncAttributeMaxDynamicSharedMemorySize,
                         (int)FL64_SMEM_BYTES);

    // 1) relative-position bias -> S (layer-2 on tensor cores)
    posbias2_kernel<<<dim3(LL/16, LL/16, BB), 256>>>(sx, sy, P1, pb1, P2, pb2, S);

    // 2) fused QKV projections, scatter to (b,h,l,d)
    tgemm<3, false, 128, 32><<<dim3(18, ROWS/128, 1), 256>>>(
        src, DM, 0, Wq, DM, 0, bq, nullptr, Q, 0, 0, DM, 1.f,
        Wk, Wv, bk, bv, K, V);

    // 3) flash attention: softmax(QK^T/8 + bias) @ V -> O
    flash64_kernel<<<dim3(LL/64, BB*NH), 256, FL64_SMEM_BYTES>>>(S, Q, K, V, O);

    // 4) Xres = src + O @ Wo + bo ; LN1 -> X1
    tgemm<2, false, 64, 16><<<dim3(DM/64, ROWS/128, 1), 256>>>(
        O, DM, 0, Wo, DM, 0, bo, src, Xres, DM, 0, DM, 1.f,
        nullptr, nullptr, nullptr, nullptr, nullptr, nullptr);
    layernorm_kernel<<<ROWS, 256>>>(Xres, g1, be1, X1);

    // 5) FFN
    tgemm<1, false, 128, 32><<<dim3(FFD/128, ROWS/128, 1), 256>>>(
        X1, DM, 0, W1, FFD, 0, b1, nullptr, H1, FFD, 0, DM, 1.f,
        nullptr, nullptr, nullptr, nullptr, nullptr, nullptr);
    tgemm<2, false, 64, 16><<<dim3(DM/64, ROWS/128, 1), 256>>>(
        H1, FFD, 0, W2, DM, 0, b2, X1, Xres, DM, 0, FFD, 1.f,
        nullptr, nullptr, nullptr, nullptr, nullptr, nullptr);

    // 6) LN2 -> output
    layernorm_kernel<<<ROWS, 256>>>(Xres, g2, be2, out);
}

// round 6
// speedup vs baseline: 1.1964x; 1.0871x over previous
#include <cuda_runtime.h>
#include <math.h>

#define BB 2
#define LL 1024
#define DM 768
#define NH 12
#define DKK 64
#define FFD 3072
#define PH 32
#define ROWS (BB*LL)

// ---------------- scratch ----------------
__device__ float g_Q[BB*NH*LL*DKK];
__device__ float g_K[BB*NH*LL*DKK];
__device__ float g_V[BB*NH*LL*DKK];
__device__ float g_S[(size_t)BB*NH*LL*LL];
__device__ float g_O[BB*LL*DM];
__device__ float g_Xres[BB*LL*DM];
__device__ float g_X1[BB*LL*DM];
__device__ float g_H1[BB*LL*FFD];

// ---------------- helpers ----------------
__device__ __forceinline__ unsigned tf32u(float x) {
    unsigned u;
    asm("cvt.rna.tf32.f32 %0, %1;" : "=r"(u) : "f"(x));
    return u;
}
__device__ __forceinline__ float tf32f(float x) { return __uint_as_float(tf32u(x)); }

__device__ __forceinline__ void mma_tf32(float* c, const unsigned* a, const unsigned* b) {
    asm volatile(
        "mma.sync.aligned.m16n8k8.row.col.f32.tf32.tf32.f32 "
        "{%0,%1,%2,%3}, {%4,%5,%6,%7}, {%8,%9}, {%0,%1,%2,%3};"
        : "+f"(c[0]), "+f"(c[1]), "+f"(c[2]), "+f"(c[3])
        : "r"(a[0]), "r"(a[1]), "r"(a[2]), "r"(a[3]), "r"(b[0]), "r"(b[1]));
}

__device__ __forceinline__ void cp16(float* dst_smem, const float* src) {
    unsigned d = (unsigned)__cvta_generic_to_shared(dst_smem);
    asm volatile("cp.async.cg.shared.global [%0], [%1], 16;" :: "r"(d), "l"(src));
}
__device__ __forceinline__ void cp_commit() { asm volatile("cp.async.commit_group;"); }
template<int N> __device__ __forceinline__ void cp_wait() {
    asm volatile("cp.async.wait_group %0;" :: "n"(N));
}

// ---------------- tensor-core GEMM v2: BK=32, 2-stage cp.async ----------------
// C[z] = epi( A[z](M x K) @ op(B[z])(K x N) )
// EPI 1: relu(+bias)  2: +bias +R residual  3: fused QKV scatter
// BN=128: 8 warps = 2(m) x 4(n), warp tile 64x32.  BN=64: 4(m) x 2(n), 32x32.
template<int EPI, bool BT, int BN>
__global__ __launch_bounds__(256, 2) void tgemm(
    const float* __restrict__ A, int lda, long sAz,
    const float* __restrict__ B, int ldb, long sBz,
    const float* __restrict__ bias,
    const float* __restrict__ Rres,
    float* __restrict__ C, int ldc, long sCz,
    int K, float alpha,
    const float* __restrict__ B1, const float* __restrict__ B2,
    const float* __restrict__ bias1, const float* __restrict__ bias2,
    float* __restrict__ C1, float* __restrict__ C2)
{
    constexpr int NWM = (BN == 128) ? 2 : 4;     // warps along M
    constexpr int MI  = (BN == 128) ? 4 : 2;     // 16-row m-tiles per warp
    constexpr int AP  = 36;                      // A row stride (32 k + 4)
    constexpr int BP  = BN + 8;                  // ==8 mod 32 -> conflict-free B LDS
    constexpr int ASZ = 128 * AP;
    constexpr int BSZ = BT ? BN * AP : 32 * BP;
    extern __shared__ float dynsm[];
    float* As = dynsm;
    float* Bs = dynsm + 2 * ASZ;

    const int tid = threadIdx.x;
    const int lane = tid & 31, w = tid >> 5;
    const int wm = w % NWM, wn = w / NWM;
    const int g = lane >> 2, t4 = lane & 3;
    const int bz = blockIdx.z;
    int bx = blockIdx.x;
    const int m0 = blockIdx.y * 128;

    const float* Ap = A + (size_t)bz * sAz;
    const float* Bp; const float* biasp = bias; float* Cp;
    if (EPI == 3) {
        int sel = bx / 6; bx -= sel * 6;
        Bp    = sel == 0 ? B    : (sel == 1 ? B1    : B2);
        biasp = sel == 0 ? bias : (sel == 1 ? bias1 : bias2);
        Cp    = sel == 0 ? C    : (sel == 1 ? C1    : C2);
    } else {
        Bp = B + (size_t)bz * sBz;
        Cp = C + (size_t)bz * sCz;
    }
    const int n0 = bx * BN;

    float acc[MI][4][4];
    #pragma unroll
    for (int i = 0; i < MI; i++)
        #pragma unroll
        for (int j = 0; j < 4; j++)
            #pragma unroll
            for (int q = 0; q < 4; q++) acc[i][j][q] = 0.f;

    auto loadA = [&](int kt, int st) {
        #pragma unroll
        for (int i = 0; i < 4; i++) {
            int idx = tid + i * 256;
            int m = idx >> 3, k4 = (idx & 7) << 2;
            cp16(&As[st * ASZ + m * AP + k4], Ap + (size_t)(m0 + m) * lda + kt + k4);
        }
    };
    auto loadB = [&](int kt, int st) {
        if (BT) {
            #pragma unroll
            for (int i = 0; i < BN / 32; i++) {
                int idx = tid + i * 256;
                int n = idx >> 3, k4 = (idx & 7) << 2;
                cp16(&Bs[st * BSZ + n * AP + k4], Bp + (size_t)(n0 + n) * ldb + kt + k4);
            }
        } else if (BN == 128) {
            #pragma unroll
            for (int i = 0; i < 4; i++) {
                int idx = tid + i * 256;
                int k = idx >> 5, n4 = (idx & 31) << 2;
                cp16(&Bs[st * BSZ + k * BP + n4], Bp + (size_t)(kt + k) * ldb + n0 + n4);
            }
        } else {
            #pragma unroll
            for (int i = 0; i < 2; i++) {
                int idx = tid + i * 256;
                int k = idx >> 4, n4 = (idx & 15) << 2;
                cp16(&Bs[st * BSZ + k * BP + n4], Bp + (size_t)(kt + k) * ldb + n0 + n4);
            }
        }
    };
    auto compute = [&](int st) {
        #pragma unroll
        for (int kk = 0; kk < 4; kk++) {
            const int kc = kk * 8 + t4;
            unsigned aF[MI][4];
            #pragma unroll
            for (int i = 0; i < MI; i++) {
                int mb = wm * (MI * 16) + i * 16 + g;
                aF[i][0] = tf32u(As[st * ASZ + mb * AP + kc]);
                aF[i][1] = tf32u(As[st * ASZ + (mb + 8) * AP + kc]);
                aF[i][2] = tf32u(As[st * ASZ + mb * AP + kc + 4]);
                aF[i][3] = tf32u(As[st * ASZ + (mb + 8) * AP + kc + 4]);
            }
            unsigned bF[4][2];
            #pragma unroll
            for (int j = 0; j < 4; j++) {
                int nb = wn * 32 + j * 8 + g;
                if (BT) {
                    bF[j][0] = tf32u(Bs[st * BSZ + nb * AP + kc]);
                    bF[j][1] = tf32u(Bs[st * BSZ + nb * AP + kc + 4]);
                } else {
                    bF[j][0] = tf32u(Bs[st * BSZ + kc * BP + nb]);
                    bF[j][1] = tf32u(Bs[st * BSZ + (kc + 4) * BP + nb]);
                }
            }
            #pragma unroll
            for (int i = 0; i < MI; i++)
                #pragma unroll
                for (int j = 0; j < 4; j++)
                    mma_tf32(acc[i][j], aF[i], bF[j]);
        }
    };

    const int nt = K >> 5;
    loadA(0, 0); loadB(0, 0); cp_commit();
    for (int t = 0; t < nt; t++) {
        int cur = t & 1;
        if (t + 1 < nt) {
            loadA((t + 1) << 5, (t + 1) & 1);
            loadB((t + 1) << 5, (t + 1) & 1);
            cp_commit();
            cp_wait<1>();
        } else {
            cp_wait<0>();
        }
        __syncthreads();
        compute(cur);
        __syncthreads();
    }

    auto epi = [&](int row, int col, float2 v) {
        float2 bb = *(const float2*)(biasp + col);
        v.x += bb.x; v.y += bb.y;
        if (EPI == 1) { v.x = fmaxf(v.x, 0.f); v.y = fmaxf(v.y, 0.f); }
        if (EPI == 2) {
            float2 r = *(const float2*)(Rres + (size_t)row * ldc + col);
            v.x += r.x; v.y += r.y;
        }
        if (EPI == 3) {
            int h = col >> 6, d = col & 63;
            float* dst = Cp + ((((size_t)(row >> 10) * NH + h) * LL + (row & 1023)) * DKK + d);
            *(float2*)dst = v;
            return;
        }
        *(float2*)(Cp + (size_t)row * ldc + col) = v;
    };

    #pragma unroll
    for (int i = 0; i < MI; i++) {
        int r0 = m0 + wm * (MI * 16) + i * 16 + g;
        #pragma unroll
        for (int j = 0; j < 4; j++) {
            int col = n0 + wn * 32 + j * 8 + t4 * 2;
            epi(r0,     col, make_float2(acc[i][j][0], acc[i][j][1]));
            epi(r0 + 8, col, make_float2(acc[i][j][2], acc[i][j][3]));
        }
    }
}

#define TG128_SMEM ((2*128*36 + 2*32*136) * 4)
#define TG64_SMEM  ((2*128*36 + 2*32*72) * 4)

// ---------------- flash64: QK^T + bias + online softmax + PV -----------------
#define FQSTR 68
struct Flash64Smem {
    float Qs[32*FQSTR*2];
    float Ss[32*FQSTR*2];
    float Ks[64*FQSTR];
    float Vs[64*FQSTR];
    float rowScale[64];
    float rowInv[64];
};
#define FL64_SMEM_BYTES sizeof(Flash64Smem)

__global__ __launch_bounds__(256, 3) void flash64_kernel(
    const float* __restrict__ S, const float* __restrict__ Q,
    const float* __restrict__ K, const float* __restrict__ V,
    float* __restrict__ O)
{
    extern __shared__ char smraw[];
    Flash64Smem& sm = *reinterpret_cast<Flash64Smem*>(smraw);

    const int tid = threadIdx.x;
    const int lane = tid & 31, w = tid >> 5;
    const int wm = w & 1, wn = w >> 1;
    const int g = lane >> 2, t4 = lane & 3;
    const int bh = blockIdx.y, b = bh / NH, h = bh % NH;
    const int q0 = blockIdx.x * 64;

    const float* Qp = Q + ((size_t)bh * LL + q0) * DKK;
    const float* Kp = K + (size_t)bh * LL * DKK;
    const float* Vp = V + (size_t)bh * LL * DKK;
    const float* Sb = S + ((size_t)bh * LL + q0) * LL;

    auto loadK = [&](int t) {
        #pragma unroll
        for (int i = 0; i < 4; i++) {
            int idx = tid + i * 256;
            int r = idx >> 4, d4 = (idx & 15) << 2;
            cp16(&sm.Ks[r * FQSTR + d4], Kp + (size_t)(t * 64 + r) * DKK + d4);
        }
        cp_commit();
    };
    auto loadV = [&](int t) {
        #pragma unroll
        for (int i = 0; i < 4; i++) {
            int idx = tid + i * 256;
            int r = idx >> 4, d4 = (idx & 15) << 2;
            cp16(&sm.Vs[r * FQSTR + d4], Vp + (size_t)(t * 64 + r) * DKK + d4);
        }
        cp_commit();
    };

    loadK(0);
    loadV(0);

    #pragma unroll
    for (int i = 0; i < 4; i++) {
        int idx = tid + i * 256;
        int r = idx >> 4, d4 = (idx & 15) << 2;
        float4 v = *(const float4*)(Qp + (size_t)r * DKK + d4);
        int kk = d4 >> 3, hh = (d4 >> 2) & 1;
        float* p = sm.Qs + ((kk * 4) * FQSTR + r) * 2 + hh;
        p[0]          = tf32f(v.x * 0.125f);
        p[FQSTR*2]    = tf32f(v.y * 0.125f);
        p[FQSTR*4]    = tf32f(v.z * 0.125f);
        p[FQSTR*6]    = tf32f(v.w * 0.125f);
    }

    float accO[2][2][4];
    #pragma unroll
    for (int i = 0; i < 2; i++)
        #pragma unroll
        for (int j = 0; j < 2; j++)
            #pragma unroll
            for (int q = 0; q < 4; q++) accO[i][j][q] = 0.f;

    float rowM = -1e30f, rowL = 0.f;
    const int myrow = tid >> 2, quarter = tid & 3;

    for (int t = 0; t < 16; t++) {
        float accS[2][2][4];
        const int kb = t * 64;
        #pragma unroll
        for (int i = 0; i < 2; i++) {
            int r = wm * 32 + i * 16 + g;
            #pragma unroll
            for (int j = 0; j < 2; j++) {
                int col = kb + wn * 16 + j * 8 + t4 * 2;
                float2 b0 = *(const float2*)(Sb + (size_t)r * LL + col);
                float2 b1 = *(const float2*)(Sb + (size_t)(r + 8) * LL + col);
                accS[i][j][0] = b0.x; accS[i][j][1] = b0.y;
                accS[i][j][2] = b1.x; accS[i][j][3] = b1.y;
            }
        }

        cp_wait<1>();
        __syncthreads();

        #pragma unroll
        for (int ks = 0; ks < 8; ks++) {
            const int kc = ks * 8 + t4;
            unsigned aF[2][4];
            #pragma unroll
            for (int i = 0; i < 2; i++) {
                int mb = wm * 32 + i * 16 + g;
                float2 lo = *(const float2*)(sm.Qs + ((ks * 4 + t4) * FQSTR + mb) * 2);
                float2 hi = *(const float2*)(sm.Qs + ((ks * 4 + t4) * FQSTR + mb + 8) * 2);
                aF[i][0] = __float_as_uint(lo.x); aF[i][1] = __float_as_uint(hi.x);
                aF[i][2] = __float_as_uint(lo.y); aF[i][3] = __float_as_uint(hi.y);
            }
            unsigned bF[2][2];
            #pragma unroll
            for (int j = 0; j < 2; j++) {
                int nb = wn * 16 + j * 8 + g;
                bF[j][0] = tf32u(sm.Ks[nb * FQSTR + kc]);
                bF[j][1] = tf32u(sm.Ks[nb * FQSTR + kc + 4]);
            }
            #pragma unroll
            for (int i = 0; i < 2; i++)
                #pragma unroll
                for (int j = 0; j < 2; j++)
                    mma_tf32(accS[i][j], aF[i], bF[j]);
        }

        {
            const int cc = (t4 & 1) * 2, hh = t4 >> 1;
            #pragma unroll
            for (int i = 0; i < 2; i++) {
                int r = wm * 32 + i * 16 + g;
                #pragma unroll
                for (int j = 0; j < 2; j++) {
                    int colk = (wn * 16 + j * 8 + t4 * 2) >> 3;
                    int e = (colk * 4 + cc) * FQSTR + r;
                    sm.Ss[e * 2 + hh]                 = accS[i][j][0];
                    sm.Ss[(e + FQSTR) * 2 + hh]       = accS[i][j][1];
                    sm.Ss[(e + 8) * 2 + hh]           = accS[i][j][2];
                    sm.Ss[(e + FQSTR + 8) * 2 + hh]   = accS[i][j][3];
                }
            }
        }
        __syncthreads();
        if (t + 1 < 16) loadK(t + 1);

        {
            float2 vals[8];
            float mx = -1e30f;
            #pragma unroll
            for (int e = 0; e < 8; e++) {
                int kk = 2 * quarter + (e >> 2), cc2 = e & 3;
                vals[e] = *(const float2*)(sm.Ss + ((kk * 4 + cc2) * FQSTR + myrow) * 2);
                mx = fmaxf(mx, fmaxf(vals[e].x, vals[e].y));
            }
            mx = fmaxf(mx, __shfl_xor_sync(0xffffffffu, mx, 1));
            mx = fmaxf(mx, __shfl_xor_sync(0xffffffffu, mx, 2));
            float mNew = fmaxf(rowM, mx);
            float scale = __expf(rowM - mNew);
            float sum = 0.f;
            #pragma unroll
            for (int e = 0; e < 8; e++) {
                vals[e].x = __expf(vals[e].x - mNew);
                vals[e].y = __expf(vals[e].y - mNew);
                sum += vals[e].x + vals[e].y;
                int kk = 2 * quarter + (e >> 2), cc2 = e & 3;
                *(float2*)(sm.Ss + ((kk * 4 + cc2) * FQSTR + myrow) * 2) =
                    make_float2(tf32f(vals[e].x), tf32f(vals[e].y));
            }
            sum += __shfl_xor_sync(0xffffffffu, sum, 1);
            sum += __shfl_xor_sync(0xffffffffu, sum, 2);
            rowL = rowL * scale + sum;
            rowM = mNew;
            if (quarter == 0) sm.rowScale[myrow] = scale;
        }
        if (t + 1 < 16) cp_wait<1>(); else cp_wait<0>();
        __syncthreads();

        #pragma unroll
        for (int i = 0; i < 2; i++) {
            int r = wm * 32 + i * 16 + g;
            float s0 = sm.rowScale[r], s1 = sm.rowScale[r + 8];
            #pragma unroll
            for (int j = 0; j < 2; j++) {
                accO[i][j][0] *= s0; accO[i][j][1] *= s0;
                accO[i][j][2] *= s1; accO[i][j][3] *= s1;
            }
        }

        #pragma unroll
        for (int ks = 0; ks < 8; ks++) {
            const int kc = ks * 8 + t4;
            unsigned aF[2][4];
            #pragma unroll
            for (int i = 0; i < 2; i++) {
                int mb = wm * 32 + i * 16 + g;
                float2 lo = *(const float2*)(sm.Ss + ((ks * 4 + t4) * FQSTR + mb) * 2);
                float2 hi = *(const float2*)(sm.Ss + ((ks * 4 + t4) * FQSTR + mb + 8) * 2);
                aF[i][0] = __float_as_uint(lo.x); aF[i][1] = __float_as_uint(hi.x);
                aF[i][2] = __float_as_uint(lo.y); aF[i][3] = __float_as_uint(hi.y);
            }
            unsigned bF[2][2];
            #pragma unroll
            for (int j = 0; j < 2; j++) {
                int nb = wn * 16 + j * 8 + g;
                bF[j][0] = tf32u(sm.Vs[kc * FQSTR + nb]);
                bF[j][1] = tf32u(sm.Vs[(kc + 4) * FQSTR + nb]);
            }
            #pragma unroll
            for (int i = 0; i < 2; i++)
                #pragma unroll
                for (int j = 0; j < 2; j++)
                    mma_tf32(accO[i][j], aF[i], bF[j]);
        }
        __syncthreads();
        if (t + 1 < 16) loadV(t + 1);
    }

    if (quarter == 0) sm.rowInv[myrow] = 1.f / rowL;
    __syncthreads();

    float* Op = O + ((size_t)b * LL + q0) * DM + h * DKK;
    #pragma unroll
    for (int i = 0; i < 2; i++) {
        int r = wm * 32 + i * 16 + g;
        float i0 = sm.rowInv[r], i1 = sm.rowInv[r + 8];
        #pragma unroll
        for (int j = 0; j < 2; j++) {
            int col = wn * 16 + j * 8 + t4 * 2;
            *(float2*)(Op + (size_t)r * DM + col) =
                make_float2(accO[i][j][0] * i0, accO[i][j][1] * i0);
            *(float2*)(Op + (size_t)(r + 8) * DM + col) =
                make_float2(accO[i][j][2] * i1, accO[i][j][3] * i1);
        }
    }
}

// ---------------- posbias2: layer-1 scalar, layer-2 via tf32 mma ----------------
__global__ __launch_bounds__(256) void posbias2_kernel(
    const float* __restrict__ sx, const float* __restrict__ sy,
    const float* __restrict__ P1, const float* __restrict__ pb1,
    const float* __restrict__ P2, const float* __restrict__ pb2,
    float* __restrict__ S)
{
    constexpr int HSTR = 260;
    constexpr int PSTR = 20;
    __shared__ float Hs[16 * HSTR * 2];
    __shared__ float Ps[16 * PSTR * 2];
    __shared__ float sP1[64], sPb1[32], sPb2[16];
    __shared__ float qx[16], qy[16], kx[16], ky[16];

    const int b = blockIdx.z;
    const int q0 = blockIdx.y * 16, k0 = blockIdx.x * 16;
    const int tid = threadIdx.x;
    const int lane = tid & 31, w = tid >> 5;
    const int g = lane >> 2, t4 = lane & 3;

    if (tid < 64) sP1[tid] = P1[tid];
    if (tid < 32) sPb1[tid] = pb1[tid];
    if (tid < 16) {
        sPb2[tid] = tid < NH ? pb2[tid] : 0.f;
        qx[tid] = sx[b*LL + q0 + tid];
        qy[tid] = sy[b*LL + q0 + tid];
        kx[tid] = sx[b*LL + k0 + tid];
        ky[tid] = sy[b*LL + k0 + tid];
    }
    #pragma unroll
    for (int ii = 0; ii < 2; ii++) {
        int v = tid + ii * 256;
        int n = v & 15, k = v >> 4;
        float val = (n < NH) ? P2[k * NH + n] : 0.f;
        int kk = k >> 3, hh = (k >> 2) & 1, cc = k & 3;
        Ps[((kk * 4 + cc) * PSTR + n) * 2 + hh] = tf32f(val);
    }
    __syncthreads();

    {
        int qq = tid >> 4, kq = tid & 15;
        float rx = fminf(fmaxf(qx[qq] - kx[kq], -1000.f), 1000.f) * 0.001f;
        float ry = fminf(fmaxf(qy[qq] - ky[kq], -1000.f), 1000.f) * 0.001f;
        #pragma unroll
        for (int kk = 0; kk < 4; kk++)
            #pragma unroll
            for (int cc = 0; cc < 4; cc++) {
                int j0 = kk * 8 + cc, j1 = j0 + 4;
                float h0 = fmaxf(fmaf(rx, sP1[j0], fmaf(ry, sP1[32+j0], sPb1[j0])), 0.f);
                float h1 = fmaxf(fmaf(rx, sP1[j1], fmaf(ry, sP1[32+j1], sPb1[j1])), 0.f);
                *(float2*)(&Hs[((kk * 4 + cc) * HSTR + tid) * 2]) =
                    make_float2(tf32f(h0), tf32f(h1));
            }
    }
    __syncthreads();

    float acc[2][2][4];
    #pragma unroll
    for (int i = 0; i < 2; i++)
        #pragma unroll
        for (int j = 0; j < 2; j++)
            #pragma unroll
            for (int q = 0; q < 4; q++) acc[i][j][q] = 0.f;

    #pragma unroll
    for (int ks = 0; ks < 4; ks++) {
        unsigned aF[2][4];
        #pragma unroll
        for (int i = 0; i < 2; i++) {
            int mb = (w * 2 + i) * 16 + g;
            float2 lo = *(const float2*)(&Hs[((ks * 4 + t4) * HSTR + mb) * 2]);
            float2 hi = *(const float2*)(&Hs[((ks * 4 + t4) * HSTR + mb + 8) * 2]);
            aF[i][0] = __float_as_uint(lo.x); aF[i][1] = __float_as_uint(hi.x);
            aF[i][2] = __float_as_uint(lo.y); aF[i][3] = __float_as_uint(hi.y);
        }
        unsigned bF[2][2];
        #pragma unroll
        for (int j = 0; j < 2; j++) {
            float2 bb = *(const float2*)(&Ps[((ks * 4 + t4) * PSTR + j * 8 + g) * 2]);
            bF[j][0] = __float_as_uint(bb.x); bF[j][1] = __float_as_uint(bb.y);
        }
        #pragma unroll
        for (int i = 0; i < 2; i++)
            #pragma unroll
            for (int j = 0; j < 2; j++)
                mma_tf32(acc[i][j], aF[i], bF[j]);
    }

    #pragma unroll
    for (int i = 0; i < 2; i++) {
        int p0 = (w * 2 + i) * 16 + g;
        int p1 = p0 + 8;
        int q_0 = q0 + (p0 >> 4), k_0 = k0 + (p0 & 15);
        int q_1 = q0 + (p1 >> 4), k_1 = k0 + (p1 & 15);
        #pragma unroll
        for (int j = 0; j < 2; j++) {
            int c0 = j * 8 + t4 * 2, c1 = c0 + 1;
            if (c0 < NH) {
                S[((size_t)(b*NH + c0) * LL + q_0) * LL + k_0] = acc[i][j][0] + sPb2[c0];
                S[((size_t)(b*NH + c0) * LL + q_1) * LL + k_1] = acc[i][j][2] + sPb2[c0];
            }
            if (c1 < NH) {
                S[((size_t)(b*NH + c1) * LL + q_0) * LL + k_0] = acc[i][j][1] + sPb2[c1];
                S[((size_t)(b*NH + c1) * LL + q_1) * LL + k_1] = acc[i][j][3] + sPb2[c1];
            }
        }
    }
}

// ---------------- layernorm over last dim (768) ----------------
__global__ __launch_bounds__(256) void layernorm_kernel(
    const float* __restrict__ X, const float* __restrict__ g, const float* __restrict__ be,
    float* __restrict__ Y)
{
    __shared__ float red[256];
    const size_t row = blockIdx.x;
    const float* p = X + row * DM;
    float* o = Y + row * DM;
    const int tid = threadIdx.x;
    float v[3];
    float s = 0.f;
    #pragma unroll
    for (int i = 0; i < 3; i++) { v[i] = p[tid + i*256]; s += v[i]; }
    red[tid] = s; __syncthreads();
    for (int st = 128; st > 0; st >>= 1) { if (tid < st) red[tid] += red[tid+st]; __syncthreads(); }
    float mean = red[0] * (1.f/DM); __syncthreads();
    float sq = 0.f;
    #pragma unroll
    for (int i = 0; i < 3; i++) { float d = v[i] - mean; sq += d*d; }
    red[tid] = sq; __syncthreads();
    for (int st = 128; st > 0; st >>= 1) { if (tid < st) red[tid] += red[tid+st]; __syncthreads(); }
    float rstd = rsqrtf(red[0] * (1.f/DM) + 1e-5f);
    #pragma unroll
    for (int i = 0; i < 3; i++) {
        int c = tid + i*256;
        o[c] = (v[i] - mean) * rstd * g[c] + be[c];
    }
}

// ---------------- launch ----------------
extern "C" void kernel_launch(void* const* d_in, const int* in_sizes, int n_in,
                              void* d_out, int out_size)
{
    const float* src = (const float*)d_in[0];
    const float* sx  = (const float*)d_in[1];
    const float* sy  = (const float*)d_in[2];
    const float* Wq  = (const float*)d_in[3];  const float* bq  = (const float*)d_in[4];
    const float* Wk  = (const float*)d_in[5];  const float* bk  = (const float*)d_in[6];
    const float* Wv  = (const float*)d_in[7];  const float* bv  = (const float*)d_in[8];
    const float* Wo  = (const float*)d_in[9];  const float* bo  = (const float*)d_in[10];
    const float* P1  = (const float*)d_in[11]; const float* pb1 = (const float*)d_in[12];
    const float* P2  = (const float*)d_in[13]; const float* pb2 = (const float*)d_in[14];
    const float* W1  = (const float*)d_in[15]; const float* b1  = (const float*)d_in[16];
    const float* W2  = (const float*)d_in[17]; const float* b2  = (const float*)d_in[18];
    const float* g1  = (const float*)d_in[19]; const float* be1 = (const float*)d_in[20];
    const float* g2  = (const float*)d_in[21]; const float* be2 = (const float*)d_in[22];
    float* out = (float*)d_out;

    float *Q, *K, *V, *S, *O, *Xres, *X1, *H1;
    cudaGetSymbolAddress((void**)&Q,    g_Q);
    cudaGetSymbolAddress((void**)&K,    g_K);
    cudaGetSymbolAddress((void**)&V,    g_V);
    cudaGetSymbolAddress((void**)&S,    g_S);
    cudaGetSymbolAddress((void**)&O,    g_O);
    cudaGetSymbolAddress((void**)&Xres, g_Xres);
    cudaGetSymbolAddress((void**)&X1,   g_X1);
    cudaGetSymbolAddress((void**)&H1,   g_H1);

    cudaFuncSetAttribute(flash64_kernel, cudaFuncAttributeMaxDynamicSharedMemorySize,
                         (int)FL64_SMEM_BYTES);
    cudaFuncSetAttribute(tgemm<3, false, 128>, cudaFuncAttributeMaxDynamicSharedMemorySize,
                         TG128_SMEM);
    cudaFuncSetAttribute(tgemm<1, false, 128>, cudaFuncAttributeMaxDynamicSharedMemorySize,
                         TG128_SMEM);
    cudaFuncSetAttribute(tgemm<2, false, 64>, cudaFuncAttributeMaxDynamicSharedMemorySize,
                         TG64_SMEM);

    // 1) relative-position bias -> S
    posbias2_kernel<<<dim3(LL/16, LL/16, BB), 256>>>(sx, sy, P1, pb1, P2, pb2, S);

    // 2) fused QKV projections, scatter to (b,h,l,d)
    tgemm<3, false, 128><<<dim3(18, ROWS/128, 1), 256, TG128_SMEM>>>(
        src, DM, 0, Wq, DM, 0, bq, nullptr, Q, 0, 0, DM, 1.f,
        Wk, Wv, bk, bv, K, V);

    // 3) flash attention: softmax(QK^T/8 + bias) @ V -> O
    flash64_kernel<<<dim3(LL/64, BB*NH), 256, FL64_SMEM_BYTES>>>(S, Q, K, V, O);

    // 4) Xres = src + O @ Wo + bo ; LN1 -> X1
    tgemm<2, false, 64><<<dim3(DM/64, ROWS/128, 1), 256, TG64_SMEM>>>(
        O, DM, 0, Wo, DM, 0, bo, src, Xres, DM, 0, DM, 1.f,
        nullptr, nullptr, nullptr, nullptr, nullptr, nullptr);
    layernorm_kernel<<<ROWS, 256>>>(Xres, g1, be1, X1);

    // 5) FFN
    tgemm<1, false, 128><<<dim3(FFD/128, ROWS/128, 1), 256, TG128_SMEM>>>(
        X1, DM, 0, W1, FFD, 0, b1, nullptr, H1, FFD, 0, DM, 1.f,
        nullptr, nullptr, nullptr, nullptr, nullptr, nullptr);
    tgemm<2, false, 64><<<dim3(DM/64, ROWS/128, 1), 256, TG64_SMEM>>>(
        H1, FFD, 0, W2, DM, 0, b2, X1, Xres, DM, 0, FFD, 1.f,
        nullptr, nullptr, nullptr, nullptr, nullptr, nullptr);

    // 6) LN2 -> output
    layernorm_kernel<<<ROWS, 256>>>(Xres, g2, be2, out);
}

// round 7
// speedup vs baseline: 1.2711x; 1.0624x over previous
#include <cuda_runtime.h>
#include <math.h>

#define BB 2
#define LL 1024
#define DM 768
#define NH 12
#define DKK 64
#define FFD 3072
#define PH 32
#define ROWS (BB*LL)

// ---------------- scratch ----------------
__device__ float g_Q[BB*NH*LL*DKK];
__device__ float g_K[BB*NH*LL*DKK];
__device__ float g_V[BB*NH*LL*DKK];
__device__ float g_S[(size_t)BB*NH*LL*LL];
__device__ float g_O[BB*LL*DM];
__device__ float g_Xres[BB*LL*DM];
__device__ float g_X1[BB*LL*DM];
__device__ float g_H1[BB*LL*FFD];

// ---------------- helpers ----------------
__device__ __forceinline__ unsigned tf32u(float x) {
    unsigned u;
    asm("cvt.rna.tf32.f32 %0, %1;" : "=r"(u) : "f"(x));
    return u;
}
__device__ __forceinline__ float tf32f(float x) { return __uint_as_float(tf32u(x)); }

// mma consumes raw fp32 bits as tf32 (HW truncates low mantissa bits)
__device__ __forceinline__ void mma_tf32(float* c, const unsigned* a, const unsigned* b) {
    asm volatile(
        "mma.sync.aligned.m16n8k8.row.col.f32.tf32.tf32.f32 "
        "{%0,%1,%2,%3}, {%4,%5,%6,%7}, {%8,%9}, {%0,%1,%2,%3};"
        : "+f"(c[0]), "+f"(c[1]), "+f"(c[2]), "+f"(c[3])
        : "r"(a[0]), "r"(a[1]), "r"(a[2]), "r"(a[3]), "r"(b[0]), "r"(b[1]));
}

__device__ __forceinline__ void cp16(float* dst_smem, const float* src) {
    unsigned d = (unsigned)__cvta_generic_to_shared(dst_smem);
    asm volatile("cp.async.cg.shared.global [%0], [%1], 16;" :: "r"(d), "l"(src));
}
__device__ __forceinline__ void cp_commit() { asm volatile("cp.async.commit_group;"); }
template<int N> __device__ __forceinline__ void cp_wait() {
    asm volatile("cp.async.wait_group %0;" :: "n"(N));
}

// ---------------- tensor-core GEMM v3: BK=32, 3-stage cp.async, 1 sync/tile ----------
// EPI 1: relu(+bias)  2: +bias +R residual  3: fused QKV scatter
// BN=128: 8 warps = 2(m) x 4(n), warp tile 64x32.  BN=64: 4(m) x 2(n), 32x32.
template<int EPI, int BN>
__global__ __launch_bounds__(256, 2) void tgemm(
    const float* __restrict__ A, int lda,
    const float* __restrict__ B, int ldb,
    const float* __restrict__ bias,
    const float* __restrict__ Rres,
    float* __restrict__ C, int ldc,
    int K,
    const float* __restrict__ B1, const float* __restrict__ B2,
    const float* __restrict__ bias1, const float* __restrict__ bias2,
    float* __restrict__ C1, float* __restrict__ C2)
{
    constexpr int NWM = (BN == 128) ? 2 : 4;
    constexpr int MI  = (BN == 128) ? 4 : 2;
    constexpr int AP  = 36;
    constexpr int BP  = BN + 8;
    constexpr int ASZ = 128 * AP;
    constexpr int BSZ = 32 * BP;
    extern __shared__ float dynsm[];
    float* As = dynsm;
    float* Bs = dynsm + 3 * ASZ;

    const int tid = threadIdx.x;
    const int lane = tid & 31, w = tid >> 5;
    const int wm = w % NWM, wn = w / NWM;
    const int g = lane >> 2, t4 = lane & 3;
    int bx = blockIdx.x;
    const int m0 = blockIdx.y * 128;

    const float* Ap = A;
    const float* Bp = B; const float* biasp = bias; float* Cp = C;
    if (EPI == 3) {
        int sel = bx / 6; bx -= sel * 6;
        Bp    = sel == 0 ? B    : (sel == 1 ? B1    : B2);
        biasp = sel == 0 ? bias : (sel == 1 ? bias1 : bias2);
        Cp    = sel == 0 ? C    : (sel == 1 ? C1    : C2);
    }
    const int n0 = bx * BN;

    float acc[MI][4][4];
    #pragma unroll
    for (int i = 0; i < MI; i++)
        #pragma unroll
        for (int j = 0; j < 4; j++)
            #pragma unroll
            for (int q = 0; q < 4; q++) acc[i][j][q] = 0.f;

    auto loadA = [&](int kt, int st) {
        #pragma unroll
        for (int i = 0; i < 4; i++) {
            int idx = tid + i * 256;
            int m = idx >> 3, k4 = (idx & 7) << 2;
            cp16(&As[st * ASZ + m * AP + k4], Ap + (size_t)(m0 + m) * lda + kt + k4);
        }
    };
    auto loadB = [&](int kt, int st) {
        if (BN == 128) {
            #pragma unroll
            for (int i = 0; i < 4; i++) {
                int idx = tid + i * 256;
                int k = idx >> 5, n4 = (idx & 31) << 2;
                cp16(&Bs[st * BSZ + k * BP + n4], Bp + (size_t)(kt + k) * ldb + n0 + n4);
            }
        } else {
            #pragma unroll
            for (int i = 0; i < 2; i++) {
                int idx = tid + i * 256;
                int k = idx >> 4, n4 = (idx & 15) << 2;
                cp16(&Bs[st * BSZ + k * BP + n4], Bp + (size_t)(kt + k) * ldb + n0 + n4);
            }
        }
    };
    auto compute = [&](int st) {
        #pragma unroll
        for (int kk = 0; kk < 4; kk++) {
            const int kc = kk * 8 + t4;
            unsigned aF[MI][4];
            #pragma unroll
            for (int i = 0; i < MI; i++) {
                int mb = wm * (MI * 16) + i * 16 + g;
                aF[i][0] = __float_as_uint(As[st * ASZ + mb * AP + kc]);
                aF[i][1] = __float_as_uint(As[st * ASZ + (mb + 8) * AP + kc]);
                aF[i][2] = __float_as_uint(As[st * ASZ + mb * AP + kc + 4]);
                aF[i][3] = __float_as_uint(As[st * ASZ + (mb + 8) * AP + kc + 4]);
            }
            unsigned bF[4][2];
            #pragma unroll
            for (int j = 0; j < 4; j++) {
                int nb = wn * 32 + j * 8 + g;
                bF[j][0] = __float_as_uint(Bs[st * BSZ + kc * BP + nb]);
                bF[j][1] = __float_as_uint(Bs[st * BSZ + (kc + 4) * BP + nb]);
            }
            #pragma unroll
            for (int i = 0; i < MI; i++)
                #pragma unroll
                for (int j = 0; j < 4; j++)
                    mma_tf32(acc[i][j], aF[i], bF[j]);
        }
    };

    const int nt = K >> 5;
    loadA(0, 0); loadB(0, 0); cp_commit();
    if (nt > 1) { loadA(32, 1); loadB(32, 1); cp_commit(); }
    for (int t = 0; t < nt; t++) {
        if (t + 1 < nt) cp_wait<1>(); else cp_wait<0>();
        __syncthreads();
        compute(t % 3);
        if (t + 2 < nt) {
            int st = (t + 2) % 3;
            loadA((t + 2) << 5, st);
            loadB((t + 2) << 5, st);
            cp_commit();
        }
    }

    auto epi = [&](int row, int col, float2 v) {
        float2 bb = *(const float2*)(biasp + col);
        v.x += bb.x; v.y += bb.y;
        if (EPI == 1) { v.x = fmaxf(v.x, 0.f); v.y = fmaxf(v.y, 0.f); }
        if (EPI == 2) {
            float2 r = *(const float2*)(Rres + (size_t)row * ldc + col);
            v.x += r.x; v.y += r.y;
        }
        if (EPI == 3) {
            int h = col >> 6, d = col & 63;
            float* dst = Cp + ((((size_t)(row >> 10) * NH + h) * LL + (row & 1023)) * DKK + d);
            *(float2*)dst = v;
            return;
        }
        *(float2*)(Cp + (size_t)row * ldc + col) = v;
    };

    #pragma unroll
    for (int i = 0; i < MI; i++) {
        int r0 = m0 + wm * (MI * 16) + i * 16 + g;
        #pragma unroll
        for (int j = 0; j < 4; j++) {
            int col = n0 + wn * 32 + j * 8 + t4 * 2;
            epi(r0,     col, make_float2(acc[i][j][0], acc[i][j][1]));
            epi(r0 + 8, col, make_float2(acc[i][j][2], acc[i][j][3]));
        }
    }
}

#define TG128_SMEM ((3*128*36 + 3*32*136) * 4)
#define TG64_SMEM  ((3*128*36 + 3*32*72) * 4)

// ---------------- flash64: QK^T + bias + online softmax + PV -----------------
#define FQSTR 68
struct Flash64Smem {
    float Qs[32*FQSTR*2];
    float Ss[32*FQSTR*2];
    float Ks[64*FQSTR];
    float Vs[64*FQSTR];
    float rowScale[64];
    float rowInv[64];
};
#define FL64_SMEM_BYTES sizeof(Flash64Smem)

__global__ __launch_bounds__(256, 3) void flash64_kernel(
    const float* __restrict__ S, const float* __restrict__ Q,
    const float* __restrict__ K, const float* __restrict__ V,
    float* __restrict__ O)
{
    extern __shared__ char smraw[];
    Flash64Smem& sm = *reinterpret_cast<Flash64Smem*>(smraw);

    const int tid = threadIdx.x;
    const int lane = tid & 31, w = tid >> 5;
    const int wm = w & 1, wn = w >> 1;
    const int g = lane >> 2, t4 = lane & 3;
    const int bh = blockIdx.y, b = bh / NH, h = bh % NH;
    const int q0 = blockIdx.x * 64;

    const float* Qp = Q + ((size_t)bh * LL + q0) * DKK;
    const float* Kp = K + (size_t)bh * LL * DKK;
    const float* Vp = V + (size_t)bh * LL * DKK;
    const float* Sb = S + ((size_t)bh * LL + q0) * LL;

    auto loadK = [&](int t) {
        #pragma unroll
        for (int i = 0; i < 4; i++) {
            int idx = tid + i * 256;
            int r = idx >> 4, d4 = (idx & 15) << 2;
            cp16(&sm.Ks[r * FQSTR + d4], Kp + (size_t)(t * 64 + r) * DKK + d4);
        }
        cp_commit();
    };
    auto loadV = [&](int t) {
        #pragma unroll
        for (int i = 0; i < 4; i++) {
            int idx = tid + i * 256;
            int r = idx >> 4, d4 = (idx & 15) << 2;
            cp16(&sm.Vs[r * FQSTR + d4], Vp + (size_t)(t * 64 + r) * DKK + d4);
        }
        cp_commit();
    };

    loadK(0);
    loadV(0);

    #pragma unroll
    for (int i = 0; i < 4; i++) {
        int idx = tid + i * 256;
        int r = idx >> 4, d4 = (idx & 15) << 2;
        float4 v = *(const float4*)(Qp + (size_t)r * DKK + d4);
        int kk = d4 >> 3, hh = (d4 >> 2) & 1;
        float* p = sm.Qs + ((kk * 4) * FQSTR + r) * 2 + hh;
        p[0]          = tf32f(v.x * 0.125f);
        p[FQSTR*2]    = tf32f(v.y * 0.125f);
        p[FQSTR*4]    = tf32f(v.z * 0.125f);
        p[FQSTR*6]    = tf32f(v.w * 0.125f);
    }

    float accO[2][2][4];
    #pragma unroll
    for (int i = 0; i < 2; i++)
        #pragma unroll
        for (int j = 0; j < 2; j++)
            #pragma unroll
            for (int q = 0; q < 4; q++) accO[i][j][q] = 0.f;

    float rowM = -1e30f, rowL = 0.f;
    const int myrow = tid >> 2, quarter = tid & 3;

    for (int t = 0; t < 16; t++) {
        float accS[2][2][4];
        const int kb = t * 64;
        #pragma unroll
        for (int i = 0; i < 2; i++) {
            int r = wm * 32 + i * 16 + g;
            #pragma unroll
            for (int j = 0; j < 2; j++) {
                int col = kb + wn * 16 + j * 8 + t4 * 2;
                float2 b0 = *(const float2*)(Sb + (size_t)r * LL + col);
                float2 b1 = *(const float2*)(Sb + (size_t)(r + 8) * LL + col);
                accS[i][j][0] = b0.x; accS[i][j][1] = b0.y;
                accS[i][j][2] = b1.x; accS[i][j][3] = b1.y;
            }
        }

        cp_wait<1>();
        __syncthreads();

        #pragma unroll
        for (int ks = 0; ks < 8; ks++) {
            const int kc = ks * 8 + t4;
            unsigned aF[2][4];
            #pragma unroll
            for (int i = 0; i < 2; i++) {
                int mb = wm * 32 + i * 16 + g;
                float2 lo = *(const float2*)(sm.Qs + ((ks * 4 + t4) * FQSTR + mb) * 2);
                float2 hi = *(const float2*)(sm.Qs + ((ks * 4 + t4) * FQSTR + mb + 8) * 2);
                aF[i][0] = __float_as_uint(lo.x); aF[i][1] = __float_as_uint(hi.x);
                aF[i][2] = __float_as_uint(lo.y); aF[i][3] = __float_as_uint(hi.y);
            }
            unsigned bF[2][2];
            #pragma unroll
            for (int j = 0; j < 2; j++) {
                int nb = wn * 16 + j * 8 + g;
                bF[j][0] = __float_as_uint(sm.Ks[nb * FQSTR + kc]);
                bF[j][1] = __float_as_uint(sm.Ks[nb * FQSTR + kc + 4]);
            }
            #pragma unroll
            for (int i = 0; i < 2; i++)
                #pragma unroll
                for (int j = 0; j < 2; j++)
                    mma_tf32(accS[i][j], aF[i], bF[j]);
        }

        {
            const int cc = (t4 & 1) * 2, hh = t4 >> 1;
            #pragma unroll
            for (int i = 0; i < 2; i++) {
                int r = wm * 32 + i * 16 + g;
                #pragma unroll
                for (int j = 0; j < 2; j++) {
                    int colk = (wn * 16 + j * 8 + t4 * 2) >> 3;
                    int e = (colk * 4 + cc) * FQSTR + r;
                    sm.Ss[e * 2 + hh]                 = accS[i][j][0];
                    sm.Ss[(e + FQSTR) * 2 + hh]       = accS[i][j][1];
                    sm.Ss[(e + 8) * 2 + hh]           = accS[i][j][2];
                    sm.Ss[(e + FQSTR + 8) * 2 + hh]   = accS[i][j][3];
                }
            }
        }
        __syncthreads();
        if (t + 1 < 16) loadK(t + 1);

        {
            float2 vals[8];
            float mx = -1e30f;
            #pragma unroll
            for (int e = 0; e < 8; e++) {
                int kk = 2 * quarter + (e >> 2), cc2 = e & 3;
                vals[e] = *(const float2*)(sm.Ss + ((kk * 4 + cc2) * FQSTR + myrow) * 2);
                mx = fmaxf(mx, fmaxf(vals[e].x, vals[e].y));
            }
            mx = fmaxf(mx, __shfl_xor_sync(0xffffffffu, mx, 1));
            mx = fmaxf(mx, __shfl_xor_sync(0xffffffffu, mx, 2));
            float mNew = fmaxf(rowM, mx);
            float scale = __expf(rowM - mNew);
            float sum = 0.f;
            #pragma unroll
            for (int e = 0; e < 8; e++) {
                vals[e].x = __expf(vals[e].x - mNew);
                vals[e].y = __expf(vals[e].y - mNew);
                sum += vals[e].x + vals[e].y;
                int kk = 2 * quarter + (e >> 2), cc2 = e & 3;
                *(float2*)(sm.Ss + ((kk * 4 + cc2) * FQSTR + myrow) * 2) =
                    make_float2(vals[e].x, vals[e].y);
            }
            sum += __shfl_xor_sync(0xffffffffu, sum, 1);
            sum += __shfl_xor_sync(0xffffffffu, sum, 2);
            rowL = rowL * scale + sum;
            rowM = mNew;
            if (quarter == 0) sm.rowScale[myrow] = scale;
        }
        if (t + 1 < 16) cp_wait<1>(); else cp_wait<0>();
        __syncthreads();

        #pragma unroll
        for (int i = 0; i < 2; i++) {
            int r = wm * 32 + i * 16 + g;
            float s0 = sm.rowScale[r], s1 = sm.rowScale[r + 8];
            #pragma unroll
            for (int j = 0; j < 2; j++) {
                accO[i][j][0] *= s0; accO[i][j][1] *= s0;
                accO[i][j][2] *= s1; accO[i][j][3] *= s1;
            }
        }

        #pragma unroll
        for (int ks = 0; ks < 8; ks++) {
            const int kc = ks * 8 + t4;
            unsigned aF[2][4];
            #pragma unroll
            for (int i = 0; i < 2; i++) {
                int mb = wm * 32 + i * 16 + g;
                float2 lo = *(const float2*)(sm.Ss + ((ks * 4 + t4) * FQSTR + mb) * 2);
                float2 hi = *(const float2*)(sm.Ss + ((ks * 4 + t4) * FQSTR + mb + 8) * 2);
                aF[i][0] = __float_as_uint(lo.x); aF[i][1] = __float_as_uint(hi.x);
                aF[i][2] = __float_as_uint(lo.y); aF[i][3] = __float_as_uint(hi.y);
            }
            unsigned bF[2][2];
            #pragma unroll
            for (int j = 0; j < 2; j++) {
                int nb = wn * 16 + j * 8 + g;
                bF[j][0] = __float_as_uint(sm.Vs[kc * FQSTR + nb]);
                bF[j][1] = __float_as_uint(sm.Vs[(kc + 4) * FQSTR + nb]);
            }
            #pragma unroll
            for (int i = 0; i < 2; i++)
                #pragma unroll
                for (int j = 0; j < 2; j++)
                    mma_tf32(accO[i][j], aF[i], bF[j]);
        }
        __syncthreads();
        if (t + 1 < 16) loadV(t + 1);
    }

    if (quarter == 0) sm.rowInv[myrow] = 1.f / rowL;
    __syncthreads();

    float* Op = O + ((size_t)b * LL + q0) * DM + h * DKK;
    #pragma unroll
    for (int i = 0; i < 2; i++) {
        int r = wm * 32 + i * 16 + g;
        float i0 = sm.rowInv[r], i1 = sm.rowInv[r + 8];
        #pragma unroll
        for (int j = 0; j < 2; j++) {
            int col = wn * 16 + j * 8 + t4 * 2;
            *(float2*)(Op + (size_t)r * DM + col) =
                make_float2(accO[i][j][0] * i0, accO[i][j][1] * i0);
            *(float2*)(Op + (size_t)(r + 8) * DM + col) =
                make_float2(accO[i][j][2] * i1, accO[i][j][3] * i1);
        }
    }
}

// ---------------- posbias2: layer-1 scalar, layer-2 via tf32 mma ----------------
__global__ __launch_bounds__(256) void posbias2_kernel(
    const float* __restrict__ sx, const float* __restrict__ sy,
    const float* __restrict__ P1, const float* __restrict__ pb1,
    const float* __restrict__ P2, const float* __restrict__ pb2,
    float* __restrict__ S)
{
    constexpr int HSTR = 260;
    constexpr int PSTR = 20;
    __shared__ float Hs[16 * HSTR * 2];
    __shared__ float Ps[16 * PSTR * 2];
    __shared__ float sP1[64], sPb1[32], sPb2[16];
    __shared__ float qx[16], qy[16], kx[16], ky[16];

    const int b = blockIdx.z;
    const int q0 = blockIdx.y * 16, k0 = blockIdx.x * 16;
    const int tid = threadIdx.x;
    const int lane = tid & 31, w = tid >> 5;
    const int g = lane >> 2, t4 = lane & 3;

    if (tid < 64) sP1[tid] = P1[tid];
    if (tid < 32) sPb1[tid] = pb1[tid];
    if (tid < 16) {
        sPb2[tid] = tid < NH ? pb2[tid] : 0.f;
        qx[tid] = sx[b*LL + q0 + tid];
        qy[tid] = sy[b*LL + q0 + tid];
        kx[tid] = sx[b*LL + k0 + tid];
        ky[tid] = sy[b*LL + k0 + tid];
    }
    #pragma unroll
    for (int ii = 0; ii < 2; ii++) {
        int v = tid + ii * 256;
        int n = v & 15, k = v >> 4;
        float val = (n < NH) ? P2[k * NH + n] : 0.f;
        int kk = k >> 3, hh = (k >> 2) & 1, cc = k & 3;
        Ps[((kk * 4 + cc) * PSTR + n) * 2 + hh] = val;
    }
    __syncthreads();

    {
        int qq = tid >> 4, kq = tid & 15;
        float rx = fminf(fmaxf(qx[qq] - kx[kq], -1000.f), 1000.f) * 0.001f;
        float ry = fminf(fmaxf(qy[qq] - ky[kq], -1000.f), 1000.f) * 0.001f;
        #pragma unroll
        for (int kk = 0; kk < 4; kk++)
            #pragma unroll
            for (int cc = 0; cc < 4; cc++) {
                int j0 = kk * 8 + cc, j1 = j0 + 4;
                float h0 = fmaxf(fmaf(rx, sP1[j0], fmaf(ry, sP1[32+j0], sPb1[j0])), 0.f);
                float h1 = fmaxf(fmaf(rx, sP1[j1], fmaf(ry, sP1[32+j1], sPb1[j1])), 0.f);
                *(float2*)(&Hs[((kk * 4 + cc) * HSTR + tid) * 2]) = make_float2(h0, h1);
            }
    }
    __syncthreads();

    float acc[2][2][4];
    #pragma unroll
    for (int i = 0; i < 2; i++)
        #pragma unroll
        for (int j = 0; j < 2; j++)
            #pragma unroll
            for (int q = 0; q < 4; q++) acc[i][j][q] = 0.f;

    #pragma unroll
    for (int ks = 0; ks < 4; ks++) {
        unsigned aF[2][4];
        #pragma unroll
        for (int i = 0; i < 2; i++) {
            int mb = (w * 2 + i) * 16 + g;
            float2 lo = *(const float2*)(&Hs[((ks * 4 + t4) * HSTR + mb) * 2]);
            float2 hi = *(const float2*)(&Hs[((ks * 4 + t4) * HSTR + mb + 8) * 2]);
            aF[i][0] = __float_as_uint(lo.x); aF[i][1] = __float_as_uint(hi.x);
            aF[i][2] = __float_as_uint(lo.y); aF[i][3] = __float_as_uint(hi.y);
        }
        unsigned bF[2][2];
        #pragma unroll
        for (int j = 0; j < 2; j++) {
            float2 bb = *(const float2*)(&Ps[((ks * 4 + t4) * PSTR + j * 8 + g) * 2]);
            bF[j][0] = __float_as_uint(bb.x); bF[j][1] = __float_as_uint(bb.y);
        }
        #pragma unroll
        for (int i = 0; i < 2; i++)
            #pragma unroll
            for (int j = 0; j < 2; j++)
                mma_tf32(acc[i][j], aF[i], bF[j]);
    }

    #pragma unroll
    for (int i = 0; i < 2; i++) {
        int p0 = (w * 2 + i) * 16 + g;
        int p1 = p0 + 8;
        int q_0 = q0 + (p0 >> 4), k_0 = k0 + (p0 & 15);
        int q_1 = q0 + (p1 >> 4), k_1 = k0 + (p1 & 15);
        #pragma unroll
        for (int j = 0; j < 2; j++) {
            int c0 = j * 8 + t4 * 2, c1 = c0 + 1;
            if (c0 < NH) {
                S[((size_t)(b*NH + c0) * LL + q_0) * LL + k_0] = acc[i][j][0] + sPb2[c0];
                S[((size_t)(b*NH + c0) * LL + q_1) * LL + k_1] = acc[i][j][2] + sPb2[c0];
            }
            if (c1 < NH) {
                S[((size_t)(b*NH + c1) * LL + q_0) * LL + k_0] = acc[i][j][1] + sPb2[c1];
                S[((size_t)(b*NH + c1) * LL + q_1) * LL + k_1] = acc[i][j][3] + sPb2[c1];
            }
        }
    }
}

// ---------------- layernorm over last dim (768) ----------------
__global__ __launch_bounds__(256) void layernorm_kernel(
    const float* __restrict__ X, const float* __restrict__ g, const float* __restrict__ be,
    float* __restrict__ Y)
{
    __shared__ float red[256];
    const size_t row = blockIdx.x;
    const float* p = X + row * DM;
    float* o = Y + row * DM;
    const int tid = threadIdx.x;
    float v[3];
    float s = 0.f;
    #pragma unroll
    for (int i = 0; i < 3; i++) { v[i] = p[tid + i*256]; s += v[i]; }
    red[tid] = s; __syncthreads();
    for (int st = 128; st > 0; st >>= 1) { if (tid < st) red[tid] += red[tid+st]; __syncthreads(); }
    float mean = red[0] * (1.f/DM); __syncthreads();
    float sq = 0.f;
    #pragma unroll
    for (int i = 0; i < 3; i++) { float d = v[i] - mean; sq += d*d; }
    red[tid] = sq; __syncthreads();
    for (int st = 128; st > 0; st >>= 1) { if (tid < st) red[tid] += red[tid+st]; __syncthreads(); }
    float rstd = rsqrtf(red[0] * (1.f/DM) + 1e-5f);
    #pragma unroll
    for (int i = 0; i < 3; i++) {
        int c = tid + i*256;
        o[c] = (v[i] - mean) * rstd * g[c] + be[c];
    }
}

// ---------------- launch ----------------
extern "C" void kernel_launch(void* const* d_in, const int* in_sizes, int n_in,
                              void* d_out, int out_size)
{
    const float* src = (const float*)d_in[0];
    const float* sx  = (const float*)d_in[1];
    const float* sy  = (const float*)d_in[2];
    const float* Wq  = (const float*)d_in[3];  const float* bq  = (const float*)d_in[4];
    const float* Wk  = (const float*)d_in[5];  const float* bk  = (const float*)d_in[6];
    const float* Wv  = (const float*)d_in[7];  const float* bv  = (const float*)d_in[8];
    const float* Wo  = (const float*)d_in[9];  const float* bo  = (const float*)d_in[10];
    const float* P1  = (const float*)d_in[11]; const float* pb1 = (const float*)d_in[12];
    const float* P2  = (const float*)d_in[13]; const float* pb2 = (const float*)d_in[14];
    const float* W1  = (const float*)d_in[15]; const float* b1  = (const float*)d_in[16];
    const float* W2  = (const float*)d_in[17]; const float* b2  = (const float*)d_in[18];
    const float* g1  = (const float*)d_in[19]; const float* be1 = (const float*)d_in[20];
    const float* g2  = (const float*)d_in[21]; const float* be2 = (const float*)d_in[22];
    float* out = (float*)d_out;

    float *Q, *K, *V, *S, *O, *Xres, *X1, *H1;
    cudaGetSymbolAddress((void**)&Q,    g_Q);
    cudaGetSymbolAddress((void**)&K,    g_K);
    cudaGetSymbolAddress((void**)&V,    g_V);
    cudaGetSymbolAddress((void**)&S,    g_S);
    cudaGetSymbolAddress((void**)&O,    g_O);
    cudaGetSymbolAddress((void**)&Xres, g_Xres);
    cudaGetSymbolAddress((void**)&X1,   g_X1);
    cudaGetSymbolAddress((void**)&H1,   g_H1);

    cudaFuncSetAttribute(flash64_kernel, cudaFuncAttributeMaxDynamicSharedMemorySize,
                         (int)FL64_SMEM_BYTES);
    cudaFuncSetAttribute(tgemm<3, 128>, cudaFuncAttributeMaxDynamicSharedMemorySize,
                         TG128_SMEM);
    cudaFuncSetAttribute(tgemm<1, 128>, cudaFuncAttributeMaxDynamicSharedMemorySize,
                         TG128_SMEM);
    cudaFuncSetAttribute(tgemm<2, 64>, cudaFuncAttributeMaxDynamicSharedMemorySize,
                         TG64_SMEM);

    // 1) relative-position bias -> S
    posbias2_kernel<<<dim3(LL/16, LL/16, BB), 256>>>(sx, sy, P1, pb1, P2, pb2, S);

    // 2) fused QKV projections, scatter to (b,h,l,d)
    tgemm<3, 128><<<dim3(18, ROWS/128, 1), 256, TG128_SMEM>>>(
        src, DM, Wq, DM, bq, nullptr, Q, 0, DM,
        Wk, Wv, bk, bv, K, V);

    // 3) flash attention: softmax(QK^T/8 + bias) @ V -> O
    flash64_kernel<<<dim3(LL/64, BB*NH), 256, FL64_SMEM_BYTES>>>(S, Q, K, V, O);

    // 4) Xres = src + O @ Wo + bo ; LN1 -> X1
    tgemm<2, 64><<<dim3(DM/64, ROWS/128, 1), 256, TG64_SMEM>>>(
        O, DM, Wo, DM, bo, src, Xres, DM, DM,
        nullptr, nullptr, nullptr, nullptr, nullptr, nullptr);
    layernorm_kernel<<<ROWS, 256>>>(Xres, g1, be1, X1);

    // 5) FFN
    tgemm<1, 128><<<dim3(FFD/128, ROWS/128, 1), 256, TG128_SMEM>>>(
        X1, DM, W1, FFD, b1, nullptr, H1, FFD, DM,
        nullptr, nullptr, nullptr, nullptr, nullptr, nullptr);
    tgemm<2, 64><<<dim3(DM/64, ROWS/128, 1), 256, TG64_SMEM>>>(
        H1, FFD, W2, DM, b2, X1, Xres, DM, FFD,
        nullptr, nullptr, nullptr, nullptr, nullptr, nullptr);

    // 6) LN2 -> output
    layernorm_kernel<<<ROWS, 256>>>(Xres, g2, be2, out);
}

// round 8
// speedup vs baseline: 1.2713x; 1.0001x over previous
#include <cuda_runtime.h>
#include <math.h>

#define BB 2
#define LL 1024
#define DM 768
#define NH 12
#define DKK 64
#define FFD 3072
#define PH 32
#define ROWS (BB*LL)

// ---------------- scratch ----------------
__device__ float g_Q[BB*NH*LL*DKK];
__device__ float g_K[BB*NH*LL*DKK];
__device__ float g_V[BB*NH*LL*DKK];
__device__ float g_S[(size_t)BB*NH*LL*LL];
__device__ float g_O[BB*LL*DM];
__device__ float g_Xres[BB*LL*DM];
__device__ float g_X1[BB*LL*DM];
__device__ float g_H1[BB*LL*FFD];

// ---------------- helpers ----------------
__device__ __forceinline__ unsigned tf32u(float x) {
    unsigned u;
    asm("cvt.rna.tf32.f32 %0, %1;" : "=r"(u) : "f"(x));
    return u;
}
__device__ __forceinline__ float tf32f(float x) { return __uint_as_float(tf32u(x)); }

// mma consumes raw fp32 bits as tf32 (HW truncates low mantissa bits)
__device__ __forceinline__ void mma_tf32(float* c, const unsigned* a, const unsigned* b) {
    asm volatile(
        "mma.sync.aligned.m16n8k8.row.col.f32.tf32.tf32.f32 "
        "{%0,%1,%2,%3}, {%4,%5,%6,%7}, {%8,%9}, {%0,%1,%2,%3};"
        : "+f"(c[0]), "+f"(c[1]), "+f"(c[2]), "+f"(c[3])
        : "r"(a[0]), "r"(a[1]), "r"(a[2]), "r"(a[3]), "r"(b[0]), "r"(b[1]));
}

__device__ __forceinline__ void cp16(float* dst_smem, const float* src) {
    unsigned d = (unsigned)__cvta_generic_to_shared(dst_smem);
    asm volatile("cp.async.cg.shared.global [%0], [%1], 16;" :: "r"(d), "l"(src));
}
__device__ __forceinline__ void cp_commit() { asm volatile("cp.async.commit_group;"); }
template<int N> __device__ __forceinline__ void cp_wait() {
    asm volatile("cp.async.wait_group %0;" :: "n"(N));
}

// ---------------- tensor-core GEMM v4: BK=32, 3-stage cp.async, templated tile ------
// EPI 1: relu(+bias)  2: +bias +R residual  3: fused QKV scatter
// 8 warps = 2(m) x 4(n). Warp tile (BM/2) x (BN/4).
template<int EPI, int BM, int BN>
__global__ __launch_bounds__(256, (BM == 64 && BN == 64) ? 3 : 2) void tgemm(
    const float* __restrict__ A, int lda,
    const float* __restrict__ B, int ldb,
    const float* __restrict__ bias,
    const float* __restrict__ Rres,
    float* __restrict__ C, int ldc,
    int K,
    const float* __restrict__ B1, const float* __restrict__ B2,
    const float* __restrict__ bias1, const float* __restrict__ bias2,
    float* __restrict__ C1, float* __restrict__ C2)
{
    constexpr int MI  = BM / 32;            // 16-row m-tiles per warp
    constexpr int NT  = BN / 32;            // 8-col n-tiles per warp
    constexpr int WNS = BN / 4;             // warp n-span
    constexpr int AP  = 36;
    constexpr int BP  = BN + 8;
    constexpr int ASZ = BM * AP;
    constexpr int BSZ = 32 * BP;
    extern __shared__ float dynsm[];
    float* As = dynsm;
    float* Bs = dynsm + 3 * ASZ;

    const int tid = threadIdx.x;
    const int lane = tid & 31, w = tid >> 5;
    const int wm = w & 1, wn = w >> 1;
    const int g = lane >> 2, t4 = lane & 3;
    int bx = blockIdx.x;
    const int m0 = blockIdx.y * BM;

    const float* Ap = A;
    const float* Bp = B; const float* biasp = bias; float* Cp = C;
    if (EPI == 3) {
        int sel = bx / 6; bx -= sel * 6;
        Bp    = sel == 0 ? B    : (sel == 1 ? B1    : B2);
        biasp = sel == 0 ? bias : (sel == 1 ? bias1 : bias2);
        Cp    = sel == 0 ? C    : (sel == 1 ? C1    : C2);
    }
    const int n0 = bx * BN;

    float acc[MI][NT][4];
    #pragma unroll
    for (int i = 0; i < MI; i++)
        #pragma unroll
        for (int j = 0; j < NT; j++)
            #pragma unroll
            for (int q = 0; q < 4; q++) acc[i][j][q] = 0.f;

    auto loadA = [&](int kt, int st) {
        #pragma unroll
        for (int i = 0; i < BM / 32; i++) {
            int idx = tid + i * 256;
            int m = idx >> 3, k4 = (idx & 7) << 2;
            cp16(&As[st * ASZ + m * AP + k4], Ap + (size_t)(m0 + m) * lda + kt + k4);
        }
    };
    auto loadB = [&](int kt, int st) {
        if (BN == 128) {
            #pragma unroll
            for (int i = 0; i < 4; i++) {
                int idx = tid + i * 256;
                int k = idx >> 5, n4 = (idx & 31) << 2;
                cp16(&Bs[st * BSZ + k * BP + n4], Bp + (size_t)(kt + k) * ldb + n0 + n4);
            }
        } else {
            #pragma unroll
            for (int i = 0; i < 2; i++) {
                int idx = tid + i * 256;
                int k = idx >> 4, n4 = (idx & 15) << 2;
                cp16(&Bs[st * BSZ + k * BP + n4], Bp + (size_t)(kt + k) * ldb + n0 + n4);
            }
        }
    };
    auto compute = [&](int st) {
        #pragma unroll
        for (int kk = 0; kk < 4; kk++) {
            const int kc = kk * 8 + t4;
            unsigned aF[MI][4];
            #pragma unroll
            for (int i = 0; i < MI; i++) {
                int mb = wm * (MI * 16) + i * 16 + g;
                aF[i][0] = __float_as_uint(As[st * ASZ + mb * AP + kc]);
                aF[i][1] = __float_as_uint(As[st * ASZ + (mb + 8) * AP + kc]);
                aF[i][2] = __float_as_uint(As[st * ASZ + mb * AP + kc + 4]);
                aF[i][3] = __float_as_uint(As[st * ASZ + (mb + 8) * AP + kc + 4]);
            }
            unsigned bF[NT][2];
            #pragma unroll
            for (int j = 0; j < NT; j++) {
                int nb = wn * WNS + j * 8 + g;
                bF[j][0] = __float_as_uint(Bs[st * BSZ + kc * BP + nb]);
                bF[j][1] = __float_as_uint(Bs[st * BSZ + (kc + 4) * BP + nb]);
            }
            #pragma unroll
            for (int i = 0; i < MI; i++)
                #pragma unroll
                for (int j = 0; j < NT; j++)
                    mma_tf32(acc[i][j], aF[i], bF[j]);
        }
    };

    const int nt = K >> 5;
    loadA(0, 0); loadB(0, 0); cp_commit();
    if (nt > 1) { loadA(32, 1); loadB(32, 1); cp_commit(); }
    for (int t = 0; t < nt; t++) {
        if (t + 1 < nt) cp_wait<1>(); else cp_wait<0>();
        __syncthreads();
        compute(t % 3);
        if (t + 2 < nt) {
            int st = (t + 2) % 3;
            loadA((t + 2) << 5, st);
            loadB((t + 2) << 5, st);
            cp_commit();
        }
    }

    auto epi = [&](int row, int col, float2 v) {
        float2 bb = *(const float2*)(biasp + col);
        v.x += bb.x; v.y += bb.y;
        if (EPI == 1) { v.x = fmaxf(v.x, 0.f); v.y = fmaxf(v.y, 0.f); }
        if (EPI == 2) {
            float2 r = *(const float2*)(Rres + (size_t)row * ldc + col);
            v.x += r.x; v.y += r.y;
        }
        if (EPI == 3) {
            int h = col >> 6, d = col & 63;
            float* dst = Cp + ((((size_t)(row >> 10) * NH + h) * LL + (row & 1023)) * DKK + d);
            *(float2*)dst = v;
            return;
        }
        *(float2*)(Cp + (size_t)row * ldc + col) = v;
    };

    #pragma unroll
    for (int i = 0; i < MI; i++) {
        int r0 = m0 + wm * (MI * 16) + i * 16 + g;
        #pragma unroll
        for (int j = 0; j < NT; j++) {
            int col = n0 + wn * WNS + j * 8 + t4 * 2;
            epi(r0,     col, make_float2(acc[i][j][0], acc[i][j][1]));
            epi(r0 + 8, col, make_float2(acc[i][j][2], acc[i][j][3]));
        }
    }
}

#define TG_SMEM(BM, BN) (3 * ((BM) * 36 + 32 * ((BN) + 8)) * 4)

// ---------------- flash64: QK^T + bias + online softmax + PV -----------------
#define FQSTR 68
struct Flash64Smem {
    float Qs[32*FQSTR*2];
    float Ss[32*FQSTR*2];
    float Ks[64*FQSTR];
    float Vs[64*FQSTR];
    float rowScale[64];
    float rowInv[64];
};
#define FL64_SMEM_BYTES sizeof(Flash64Smem)

__global__ __launch_bounds__(256, 3) void flash64_kernel(
    const float* __restrict__ S, const float* __restrict__ Q,
    const float* __restrict__ K, const float* __restrict__ V,
    float* __restrict__ O)
{
    extern __shared__ char smraw[];
    Flash64Smem& sm = *reinterpret_cast<Flash64Smem*>(smraw);

    const int tid = threadIdx.x;
    const int lane = tid & 31, w = tid >> 5;
    const int wm = w & 1, wn = w >> 1;
    const int g = lane >> 2, t4 = lane & 3;
    const int bh = blockIdx.y, b = bh / NH, h = bh % NH;
    const int q0 = blockIdx.x * 64;

    const float* Qp = Q + ((size_t)bh * LL + q0) * DKK;
    const float* Kp = K + (size_t)bh * LL * DKK;
    const float* Vp = V + (size_t)bh * LL * DKK;
    const float* Sb = S + ((size_t)bh * LL + q0) * LL;

    auto loadK = [&](int t) {
        #pragma unroll
        for (int i = 0; i < 4; i++) {
            int idx = tid + i * 256;
            int r = idx >> 4, d4 = (idx & 15) << 2;
            cp16(&sm.Ks[r * FQSTR + d4], Kp + (size_t)(t * 64 + r) * DKK + d4);
        }
        cp_commit();
    };
    auto loadV = [&](int t) {
        #pragma unroll
        for (int i = 0; i < 4; i++) {
            int idx = tid + i * 256;
            int r = idx >> 4, d4 = (idx & 15) << 2;
            cp16(&sm.Vs[r * FQSTR + d4], Vp + (size_t)(t * 64 + r) * DKK + d4);
        }
        cp_commit();
    };

    loadK(0);
    loadV(0);

    #pragma unroll
    for (int i = 0; i < 4; i++) {
        int idx = tid + i * 256;
        int r = idx >> 4, d4 = (idx & 15) << 2;
        float4 v = *(const float4*)(Qp + (size_t)r * DKK + d4);
        int kk = d4 >> 3, hh = (d4 >> 2) & 1;
        float* p = sm.Qs + ((kk * 4) * FQSTR + r) * 2 + hh;
        p[0]          = tf32f(v.x * 0.125f);
        p[FQSTR*2]    = tf32f(v.y * 0.125f);
        p[FQSTR*4]    = tf32f(v.z * 0.125f);
        p[FQSTR*6]    = tf32f(v.w * 0.125f);
    }

    float accO[2][2][4];
    #pragma unroll
    for (int i = 0; i < 2; i++)
        #pragma unroll
        for (int j = 0; j < 2; j++)
            #pragma unroll
            for (int q = 0; q < 4; q++) accO[i][j][q] = 0.f;

    float rowM = -1e30f, rowL = 0.f;
    const int myrow = tid >> 2, quarter = tid & 3;

    for (int t = 0; t < 16; t++) {
        float accS[2][2][4];
        const int kb = t * 64;
        #pragma unroll
        for (int i = 0; i < 2; i++) {
            int r = wm * 32 + i * 16 + g;
            #pragma unroll
            for (int j = 0; j < 2; j++) {
                int col = kb + wn * 16 + j * 8 + t4 * 2;
                float2 b0 = *(const float2*)(Sb + (size_t)r * LL + col);
                float2 b1 = *(const float2*)(Sb + (size_t)(r + 8) * LL + col);
                accS[i][j][0] = b0.x; accS[i][j][1] = b0.y;
                accS[i][j][2] = b1.x; accS[i][j][3] = b1.y;
            }
        }

        cp_wait<1>();
        __syncthreads();

        #pragma unroll
        for (int ks = 0; ks < 8; ks++) {
            const int kc = ks * 8 + t4;
            unsigned aF[2][4];
            #pragma unroll
            for (int i = 0; i < 2; i++) {
                int mb = wm * 32 + i * 16 + g;
                float2 lo = *(const float2*)(sm.Qs + ((ks * 4 + t4) * FQSTR + mb) * 2);
                float2 hi = *(const float2*)(sm.Qs + ((ks * 4 + t4) * FQSTR + mb + 8) * 2);
                aF[i][0] = __float_as_uint(lo.x); aF[i][1] = __float_as_uint(hi.x);
                aF[i][2] = __float_as_uint(lo.y); aF[i][3] = __float_as_uint(hi.y);
            }
            unsigned bF[2][2];
            #pragma unroll
            for (int j = 0; j < 2; j++) {
                int nb = wn * 16 + j * 8 + g;
                bF[j][0] = __float_as_uint(sm.Ks[nb * FQSTR + kc]);
                bF[j][1] = __float_as_uint(sm.Ks[nb * FQSTR + kc + 4]);
            }
            #pragma unroll
            for (int i = 0; i < 2; i++)
                #pragma unroll
                for (int j = 0; j < 2; j++)
                    mma_tf32(accS[i][j], aF[i], bF[j]);
        }

        {
            const int cc = (t4 & 1) * 2, hh = t4 >> 1;
            #pragma unroll
            for (int i = 0; i < 2; i++) {
                int r = wm * 32 + i * 16 + g;
                #pragma unroll
                for (int j = 0; j < 2; j++) {
                    int colk = (wn * 16 + j * 8 + t4 * 2) >> 3;
                    int e = (colk * 4 + cc) * FQSTR + r;
                    sm.Ss[e * 2 + hh]                 = accS[i][j][0];
                    sm.Ss[(e + FQSTR) * 2 + hh]       = accS[i][j][1];
                    sm.Ss[(e + 8) * 2 + hh]           = accS[i][j][2];
                    sm.Ss[(e + FQSTR + 8) * 2 + hh]   = accS[i][j][3];
                }
            }
        }
        __syncthreads();
        if (t + 1 < 16) loadK(t + 1);

        {
            float2 vals[8];
            float mx = -1e30f;
            #pragma unroll
            for (int e = 0; e < 8; e++) {
                int kk = 2 * quarter + (e >> 2), cc2 = e & 3;
                vals[e] = *(const float2*)(sm.Ss + ((kk * 4 + cc2) * FQSTR + myrow) * 2);
                mx = fmaxf(mx, fmaxf(vals[e].x, vals[e].y));
            }
            mx = fmaxf(mx, __shfl_xor_sync(0xffffffffu, mx, 1));
            mx = fmaxf(mx, __shfl_xor_sync(0xffffffffu, mx, 2));
            float mNew = fmaxf(rowM, mx);
            float scale = __expf(rowM - mNew);
            float sum = 0.f;
            #pragma unroll
            for (int e = 0; e < 8; e++) {
                vals[e].x = __expf(vals[e].x - mNew);
                vals[e].y = __expf(vals[e].y - mNew);
                sum += vals[e].x + vals[e].y;
                int kk = 2 * quarter + (e >> 2), cc2 = e & 3;
                *(float2*)(sm.Ss + ((kk * 4 + cc2) * FQSTR + myrow) * 2) =
                    make_float2(vals[e].x, vals[e].y);
            }
            sum += __shfl_xor_sync(0xffffffffu, sum, 1);
            sum += __shfl_xor_sync(0xffffffffu, sum, 2);
            rowL = rowL * scale + sum;
            rowM = mNew;
            if (quarter == 0) sm.rowScale[myrow] = scale;
        }
        if (t + 1 < 16) cp_wait<1>(); else cp_wait<0>();
        __syncthreads();

        #pragma unroll
        for (int i = 0; i < 2; i++) {
            int r = wm * 32 + i * 16 + g;
            float s0 = sm.rowScale[r], s1 = sm.rowScale[r + 8];
            #pragma unroll
            for (int j = 0; j < 2; j++) {
                accO[i][j][0] *= s0; accO[i][j][1] *= s0;
                accO[i][j][2] *= s1; accO[i][j][3] *= s1;
            }
        }

        #pragma unroll
        for (int ks = 0; ks < 8; ks++) {
            const int kc = ks * 8 + t4;
            unsigned aF[2][4];
            #pragma unroll
            for (int i = 0; i < 2; i++) {
                int mb = wm * 32 + i * 16 + g;
                float2 lo = *(const float2*)(sm.Ss + ((ks * 4 + t4) * FQSTR + mb) * 2);
                float2 hi = *(const float2*)(sm.Ss + ((ks * 4 + t4) * FQSTR + mb + 8) * 2);
                aF[i][0] = __float_as_uint(lo.x); aF[i][1] = __float_as_uint(hi.x);
                aF[i][2] = __float_as_uint(lo.y); aF[i][3] = __float_as_uint(hi.y);
            }
            unsigned bF[2][2];
            #pragma unroll
            for (int j = 0; j < 2; j++) {
                int nb = wn * 16 + j * 8 + g;
                bF[j][0] = __float_as_uint(sm.Vs[kc * FQSTR + nb]);
                bF[j][1] = __float_as_uint(sm.Vs[(kc + 4) * FQSTR + nb]);
            }
            #pragma unroll
            for (int i = 0; i < 2; i++)
                #pragma unroll
                for (int j = 0; j < 2; j++)
                    mma_tf32(accO[i][j], aF[i], bF[j]);
        }
        __syncthreads();
        if (t + 1 < 16) loadV(t + 1);
    }

    if (quarter == 0) sm.rowInv[myrow] = 1.f / rowL;
    __syncthreads();

    float* Op = O + ((size_t)b * LL + q0) * DM + h * DKK;
    #pragma unroll
    for (int i = 0; i < 2; i++) {
        int r = wm * 32 + i * 16 + g;
        float i0 = sm.rowInv[r], i1 = sm.rowInv[r + 8];
        #pragma unroll
        for (int j = 0; j < 2; j++) {
            int col = wn * 16 + j * 8 + t4 * 2;
            *(float2*)(Op + (size_t)r * DM + col) =
                make_float2(accO[i][j][0] * i0, accO[i][j][1] * i0);
            *(float2*)(Op + (size_t)(r + 8) * DM + col) =
                make_float2(accO[i][j][2] * i1, accO[i][j][3] * i1);
        }
    }
}

// ---------------- posbias2: layer-1 scalar, layer-2 via tf32 mma ----------------
__global__ __launch_bounds__(256) void posbias2_kernel(
    const float* __restrict__ sx, const float* __restrict__ sy,
    const float* __restrict__ P1, const float* __restrict__ pb1,
    const float* __restrict__ P2, const float* __restrict__ pb2,
    float* __restrict__ S)
{
    constexpr int HSTR = 260;
    constexpr int PSTR = 20;
    __shared__ float Hs[16 * HSTR * 2];
    __shared__ float Ps[16 * PSTR * 2];
    __shared__ float sP1[64], sPb1[32], sPb2[16];
    __shared__ float qx[16], qy[16], kx[16], ky[16];

    const int b = blockIdx.z;
    const int q0 = blockIdx.y * 16, k0 = blockIdx.x * 16;
    const int tid = threadIdx.x;
    const int lane = tid & 31, w = tid >> 5;
    const int g = lane >> 2, t4 = lane & 3;

    if (tid < 64) sP1[tid] = P1[tid];
    if (tid < 32) sPb1[tid] = pb1[tid];
    if (tid < 16) {
        sPb2[tid] = tid < NH ? pb2[tid] : 0.f;
        qx[tid] = sx[b*LL + q0 + tid];
        qy[tid] = sy[b*LL + q0 + tid];
        kx[tid] = sx[b*LL + k0 + tid];
        ky[tid] = sy[b*LL + k0 + tid];
    }
    #pragma unroll
    for (int ii = 0; ii < 2; ii++) {
        int v = tid + ii * 256;
        int n = v & 15, k = v >> 4;
        float val = (n < NH) ? P2[k * NH + n] : 0.f;
        int kk = k >> 3, hh = (k >> 2) & 1, cc = k & 3;
        Ps[((kk * 4 + cc) * PSTR + n) * 2 + hh] = val;
    }
    __syncthreads();

    {
        int qq = tid >> 4, kq = tid & 15;
        float rx = fminf(fmaxf(qx[qq] - kx[kq], -1000.f), 1000.f) * 0.001f;
        float ry = fminf(fmaxf(qy[qq] - ky[kq], -1000.f), 1000.f) * 0.001f;
        #pragma unroll
        for (int kk = 0; kk < 4; kk++)
            #pragma unroll
            for (int cc = 0; cc < 4; cc++) {
                int j0 = kk * 8 + cc, j1 = j0 + 4;
                float h0 = fmaxf(fmaf(rx, sP1[j0], fmaf(ry, sP1[32+j0], sPb1[j0])), 0.f);
                float h1 = fmaxf(fmaf(rx, sP1[j1], fmaf(ry, sP1[32+j1], sPb1[j1])), 0.f);
                *(float2*)(&Hs[((kk * 4 + cc) * HSTR + tid) * 2]) = make_float2(h0, h1);
            }
    }
    __syncthreads();

    float acc[2][2][4];
    #pragma unroll
    for (int i = 0; i < 2; i++)
        #pragma unroll
        for (int j = 0; j < 2; j++)
            #pragma unroll
            for (int q = 0; q < 4; q++) acc[i][j][q] = 0.f;

    #pragma unroll
    for (int ks = 0; ks < 4; ks++) {
        unsigned aF[2][4];
        #pragma unroll
        for (int i = 0; i < 2; i++) {
            int mb = (w * 2 + i) * 16 + g;
            float2 lo = *(const float2*)(&Hs[((ks * 4 + t4) * HSTR + mb) * 2]);
            float2 hi = *(const float2*)(&Hs[((ks * 4 + t4) * HSTR + mb + 8) * 2]);
            aF[i][0] = __float_as_uint(lo.x); aF[i][1] = __float_as_uint(hi.x);
            aF[i][2] = __float_as_uint(lo.y); aF[i][3] = __float_as_uint(hi.y);
        }
        unsigned bF[2][2];
        #pragma unroll
        for (int j = 0; j < 2; j++) {
            float2 bb = *(const float2*)(&Ps[((ks * 4 + t4) * PSTR + j * 8 + g) * 2]);
            bF[j][0] = __float_as_uint(bb.x); bF[j][1] = __float_as_uint(bb.y);
        }
        #pragma unroll
        for (int i = 0; i < 2; i++)
            #pragma unroll
            for (int j = 0; j < 2; j++)
                mma_tf32(acc[i][j], aF[i], bF[j]);
    }

    #pragma unroll
    for (int i = 0; i < 2; i++) {
        int p0 = (w * 2 + i) * 16 + g;
        int p1 = p0 + 8;
        int q_0 = q0 + (p0 >> 4), k_0 = k0 + (p0 & 15);
        int q_1 = q0 + (p1 >> 4), k_1 = k0 + (p1 & 15);
        #pragma unroll
        for (int j = 0; j < 2; j++) {
            int c0 = j * 8 + t4 * 2, c1 = c0 + 1;
            if (c0 < NH) {
                S[((size_t)(b*NH + c0) * LL + q_0) * LL + k_0] = acc[i][j][0] + sPb2[c0];
                S[((size_t)(b*NH + c0) * LL + q_1) * LL + k_1] = acc[i][j][2] + sPb2[c0];
            }
            if (c1 < NH) {
                S[((size_t)(b*NH + c1) * LL + q_0) * LL + k_0] = acc[i][j][1] + sPb2[c1];
                S[((size_t)(b*NH + c1) * LL + q_1) * LL + k_1] = acc[i][j][3] + sPb2[c1];
            }
        }
    }
}

// ---------------- layernorm over last dim (768) ----------------
__global__ __launch_bounds__(256) void layernorm_kernel(
    const float* __restrict__ X, const float* __restrict__ g, const float* __restrict__ be,
    float* __restrict__ Y)
{
    __shared__ float red[256];
    const size_t row = blockIdx.x;
    const float* p = X + row * DM;
    float* o = Y + row * DM;
    const int tid = threadIdx.x;
    float v[3];
    float s = 0.f;
    #pragma unroll
    for (int i = 0; i < 3; i++) { v[i] = p[tid + i*256]; s += v[i]; }
    red[tid] = s; __syncthreads();
    for (int st = 128; st > 0; st >>= 1) { if (tid < st) red[tid] += red[tid+st]; __syncthreads(); }
    float mean = red[0] * (1.f/DM); __syncthreads();
    float sq = 0.f;
    #pragma unroll
    for (int i = 0; i < 3; i++) { float d = v[i] - mean; sq += d*d; }
    red[tid] = sq; __syncthreads();
    for (int st = 128; st > 0; st >>= 1) { if (tid < st) red[tid] += red[tid+st]; __syncthreads(); }
    float rstd = rsqrtf(red[0] * (1.f/DM) + 1e-5f);
    #pragma unroll
    for (int i = 0; i < 3; i++) {
        int c = tid + i*256;
        o[c] = (v[i] - mean) * rstd * g[c] + be[c];
    }
}

// ---------------- launch ----------------
extern "C" void kernel_launch(void* const* d_in, const int* in_sizes, int n_in,
                              void* d_out, int out_size)
{
    const float* src = (const float*)d_in[0];
    const float* sx  = (const float*)d_in[1];
    const float* sy  = (const float*)d_in[2];
    const float* Wq  = (const float*)d_in[3];  const float* bq  = (const float*)d_in[4];
    const float* Wk  = (const float*)d_in[5];  const float* bk  = (const float*)d_in[6];
    const float* Wv  = (const float*)d_in[7];  const float* bv  = (const float*)d_in[8];
    const float* Wo  = (const float*)d_in[9];  const float* bo  = (const float*)d_in[10];
    const float* P1  = (const float*)d_in[11]; const float* pb1 = (const float*)d_in[12];
    const float* P2  = (const float*)d_in[13]; const float* pb2 = (const float*)d_in[14];
    const float* W1  = (const float*)d_in[15]; const float* b1  = (const float*)d_in[16];
    const float* W2  = (const float*)d_in[17]; const float* b2  = (const float*)d_in[18];
    const float* g1  = (const float*)d_in[19]; const float* be1 = (const float*)d_in[20];
    const float* g2  = (const float*)d_in[21]; const float* be2 = (const float*)d_in[22];
    float* out = (float*)d_out;

    float *Q, *K, *V, *S, *O, *Xres, *X1, *H1;
    cudaGetSymbolAddress((void**)&Q,    g_Q);
    cudaGetSymbolAddress((void**)&K,    g_K);
    cudaGetSymbolAddress((void**)&V,    g_V);
    cudaGetSymbolAddress((void**)&S,    g_S);
    cudaGetSymbolAddress((void**)&O,    g_O);
    cudaGetSymbolAddress((void**)&Xres, g_Xres);
    cudaGetSymbolAddress((void**)&X1,   g_X1);
    cudaGetSymbolAddress((void**)&H1,   g_H1);

    cudaFuncSetAttribute(flash64_kernel, cudaFuncAttributeMaxDynamicSharedMemorySize,
                         (int)FL64_SMEM_BYTES);
    cudaFuncSetAttribute(tgemm<3, 128, 128>, cudaFuncAttributeMaxDynamicSharedMemorySize,
                         TG_SMEM(128, 128));
    cudaFuncSetAttribute(tgemm<1, 64, 128>, cudaFuncAttributeMaxDynamicSharedMemorySize,
                         TG_SMEM(64, 128));
    cudaFuncSetAttribute(tgemm<2, 64, 64>, cudaFuncAttributeMaxDynamicSharedMemorySize,
                         TG_SMEM(64, 64));

    // 1) relative-position bias -> S
    posbias2_kernel<<<dim3(LL/16, LL/16, BB), 256>>>(sx, sy, P1, pb1, P2, pb2, S);

    // 2) fused QKV projections, scatter to (b,h,l,d)
    tgemm<3, 128, 128><<<dim3(18, ROWS/128, 1), 256, TG_SMEM(128, 128)>>>(
        src, DM, Wq, DM, bq, nullptr, Q, 0, DM,
        Wk, Wv, bk, bv, K, V);

    // 3) flash attention: softmax(QK^T/8 + bias) @ V -> O
    flash64_kernel<<<dim3(LL/64, BB*NH), 256, FL64_SMEM_BYTES>>>(S, Q, K, V, O);

    // 4) Xres = src + O @ Wo + bo ; LN1 -> X1
    tgemm<2, 64, 64><<<dim3(DM/64, ROWS/64, 1), 256, TG_SMEM(64, 64)>>>(
        O, DM, Wo, DM, bo, src, Xres, DM, DM,
        nullptr, nullptr, nullptr, nullptr, nullptr, nullptr);
    layernorm_kernel<<<ROWS, 256>>>(Xres, g1, be1, X1);

    // 5) FFN
    tgemm<1, 64, 128><<<dim3(FFD/128, ROWS/64, 1), 256, TG_SMEM(64, 128)>>>(
        X1, DM, W1, FFD, b1, nullptr, H1, FFD, DM,
        nullptr, nullptr, nullptr, nullptr, nullptr, nullptr);
    tgemm<2, 64, 64><<<dim3(DM/64, ROWS/64, 1), 256, TG_SMEM(64, 64)>>>(
        H1, FFD, W2, DM, b2, X1, Xres, DM, FFD,
        nullptr, nullptr, nullptr, nullptr, nullptr, nullptr);

    // 6) LN2 -> output
    layernorm_kernel<<<ROWS, 256>>>(Xres, g2, be2, out);
}

// round 9
// speedup vs baseline: 1.3015x; 1.0238x over previous
#include <cuda_runtime.h>
#include <math.h>

#define BB 2
#define LL 1024
#define DM 768
#define NH 12
#define DKK 64
#define FFD 3072
#define PH 32
#define ROWS (BB*LL)

// ---------------- scratch ----------------
__device__ float g_Q[BB*NH*LL*DKK];
__device__ float g_K[BB*NH*LL*DKK];
__device__ float g_V[BB*NH*LL*DKK];
__device__ float g_S[(size_t)BB*NH*LL*LL];
__device__ float g_O[BB*LL*DM];
__device__ float g_Xres[BB*LL*DM];
__device__ float g_X1[BB*LL*DM];
__device__ float g_H1[BB*LL*FFD];

// ---------------- helpers ----------------
__device__ __forceinline__ unsigned tf32u(float x) {
    unsigned u;
    asm("cvt.rna.tf32.f32 %0, %1;" : "=r"(u) : "f"(x));
    return u;
}
__device__ __forceinline__ float tf32f(float x) { return __uint_as_float(tf32u(x)); }

// mma consumes raw fp32 bits as tf32 (HW truncates low mantissa bits)
__device__ __forceinline__ void mma_tf32(float* c, const unsigned* a, const unsigned* b) {
    asm volatile(
        "mma.sync.aligned.m16n8k8.row.col.f32.tf32.tf32.f32 "
        "{%0,%1,%2,%3}, {%4,%5,%6,%7}, {%8,%9}, {%0,%1,%2,%3};"
        : "+f"(c[0]), "+f"(c[1]), "+f"(c[2]), "+f"(c[3])
        : "r"(a[0]), "r"(a[1]), "r"(a[2]), "r"(a[3]), "r"(b[0]), "r"(b[1]));
}

__device__ __forceinline__ void cp16(float* dst_smem, const float* src) {
    unsigned d = (unsigned)__cvta_generic_to_shared(dst_smem);
    asm volatile("cp.async.cg.shared.global [%0], [%1], 16;" :: "r"(d), "l"(src));
}
__device__ __forceinline__ void cp_commit() { asm volatile("cp.async.commit_group;"); }
template<int N> __device__ __forceinline__ void cp_wait() {
    asm volatile("cp.async.wait_group %0;" :: "n"(N));
}

// ---------------- tensor-core GEMM v5: BK=32, 3-stage cp.async, reg-pipelined frags --
// EPI 1: relu(+bias)  2: +bias +R residual  3: fused QKV scatter
// 8 warps = 2(m) x 4(n). Warp tile (BM/2) x (BN/4).
template<int EPI, int BM, int BN>
__global__ __launch_bounds__(256, (BM == 64 && BN == 64) ? 3 : 2) void tgemm(
    const float* __restrict__ A, int lda,
    const float* __restrict__ B, int ldb,
    const float* __restrict__ bias,
    const float* __restrict__ Rres,
    float* __restrict__ C, int ldc,
    int K,
    const float* __restrict__ B1, const float* __restrict__ B2,
    const float* __restrict__ bias1, const float* __restrict__ bias2,
    float* __restrict__ C1, float* __restrict__ C2)
{
    constexpr int MI  = BM / 32;            // 16-row m-tiles per warp
    constexpr int NT  = BN / 32;            // 8-col n-tiles per warp
    constexpr int WNS = BN / 4;             // warp n-span
    constexpr bool PIPE_A = (BM == 64);     // double-buffer A frags only for small tile
    constexpr int AP  = 36;
    constexpr int BP  = BN + 8;
    constexpr int ASZ = BM * AP;
    constexpr int BSZ = 32 * BP;
    extern __shared__ float dynsm[];
    float* As = dynsm;
    float* Bs = dynsm + 3 * ASZ;

    const int tid = threadIdx.x;
    const int lane = tid & 31, w = tid >> 5;
    const int wm = w & 1, wn = w >> 1;
    const int g = lane >> 2, t4 = lane & 3;
    int bx = blockIdx.x;
    const int m0 = blockIdx.y * BM;

    const float* Ap = A;
    const float* Bp = B; const float* biasp = bias; float* Cp = C;
    if (EPI == 3) {
        int sel = bx / 6; bx -= sel * 6;
        Bp    = sel == 0 ? B    : (sel == 1 ? B1    : B2);
        biasp = sel == 0 ? bias : (sel == 1 ? bias1 : bias2);
        Cp    = sel == 0 ? C    : (sel == 1 ? C1    : C2);
    }
    const int n0 = bx * BN;

    float acc[MI][NT][4];
    #pragma unroll
    for (int i = 0; i < MI; i++)
        #pragma unroll
        for (int j = 0; j < NT; j++)
            #pragma unroll
            for (int q = 0; q < 4; q++) acc[i][j][q] = 0.f;

    auto loadA = [&](int kt, int st) {
        #pragma unroll
        for (int i = 0; i < BM / 32; i++) {
            int idx = tid + i * 256;
            int m = idx >> 3, k4 = (idx & 7) << 2;
            cp16(&As[st * ASZ + m * AP + k4], Ap + (size_t)(m0 + m) * lda + kt + k4);
        }
    };
    auto loadB = [&](int kt, int st) {
        if (BN == 128) {
            #pragma unroll
            for (int i = 0; i < 4; i++) {
                int idx = tid + i * 256;
                int k = idx >> 5, n4 = (idx & 31) << 2;
                cp16(&Bs[st * BSZ + k * BP + n4], Bp + (size_t)(kt + k) * ldb + n0 + n4);
            }
        } else {
            #pragma unroll
            for (int i = 0; i < 2; i++) {
                int idx = tid + i * 256;
                int k = idx >> 4, n4 = (idx & 15) << 2;
                cp16(&Bs[st * BSZ + k * BP + n4], Bp + (size_t)(kt + k) * ldb + n0 + n4);
            }
        }
    };
    auto ldA = [&](int st, int kk, unsigned (&aF)[MI][4]) {
        const int kc = kk * 8 + t4;
        #pragma unroll
        for (int i = 0; i < MI; i++) {
            int mb = wm * (MI * 16) + i * 16 + g;
            aF[i][0] = __float_as_uint(As[st * ASZ + mb * AP + kc]);
            aF[i][1] = __float_as_uint(As[st * ASZ + (mb + 8) * AP + kc]);
            aF[i][2] = __float_as_uint(As[st * ASZ + mb * AP + kc + 4]);
            aF[i][3] = __float_as_uint(As[st * ASZ + (mb + 8) * AP + kc + 4]);
        }
    };
    auto ldB = [&](int st, int kk, unsigned (&bF)[NT][2]) {
        const int kc = kk * 8 + t4;
        #pragma unroll
        for (int j = 0; j < NT; j++) {
            int nb = wn * WNS + j * 8 + g;
            bF[j][0] = __float_as_uint(Bs[st * BSZ + kc * BP + nb]);
            bF[j][1] = __float_as_uint(Bs[st * BSZ + (kc + 4) * BP + nb]);
        }
    };
    auto compute = [&](int st) {
        unsigned aF[PIPE_A ? 2 : 1][MI][4];
        unsigned bF[2][NT][2];
        if (PIPE_A) ldA(st, 0, aF[0]);
        ldB(st, 0, bF[0]);
        #pragma unroll
        for (int kk = 0; kk < 4; kk++) {
            const int ca = PIPE_A ? (kk & 1) : 0;
            const int cb = kk & 1;
            if (!PIPE_A) ldA(st, kk, aF[0]);
            if (kk < 3) {
                if (PIPE_A) ldA(st, kk + 1, aF[ca ^ 1]);
                ldB(st, kk + 1, bF[cb ^ 1]);
            }
            #pragma unroll
            for (int i = 0; i < MI; i++)
                #pragma unroll
                for (int j = 0; j < NT; j++)
                    mma_tf32(acc[i][j], aF[ca][i], bF[cb][j]);
        }
    };

    const int nt = K >> 5;
    loadA(0, 0); loadB(0, 0); cp_commit();
    if (nt > 1) { loadA(32, 1); loadB(32, 1); cp_commit(); }
    for (int t = 0; t < nt; t++) {
        if (t + 1 < nt) cp_wait<1>(); else cp_wait<0>();
        __syncthreads();
        compute(t % 3);
        if (t + 2 < nt) {
            int st = (t + 2) % 3;
            loadA((t + 2) << 5, st);
            loadB((t + 2) << 5, st);
            cp_commit();
        }
    }

    auto epi = [&](int row, int col, float2 v) {
        float2 bb = *(const float2*)(biasp + col);
        v.x += bb.x; v.y += bb.y;
        if (EPI == 1) { v.x = fmaxf(v.x, 0.f); v.y = fmaxf(v.y, 0.f); }
        if (EPI == 2) {
            float2 r = *(const float2*)(Rres + (size_t)row * ldc + col);
            v.x += r.x; v.y += r.y;
        }
        if (EPI == 3) {
            int h = col >> 6, d = col & 63;
            float* dst = Cp + ((((size_t)(row >> 10) * NH + h) * LL + (row & 1023)) * DKK + d);
            *(float2*)dst = v;
            return;
        }
        *(float2*)(Cp + (size_t)row * ldc + col) = v;
    };

    #pragma unroll
    for (int i = 0; i < MI; i++) {
        int r0 = m0 + wm * (MI * 16) + i * 16 + g;
        #pragma unroll
        for (int j = 0; j < NT; j++) {
            int col = n0 + wn * WNS + j * 8 + t4 * 2;
            epi(r0,     col, make_float2(acc[i][j][0], acc[i][j][1]));
            epi(r0 + 8, col, make_float2(acc[i][j][2], acc[i][j][3]));
        }
    }
}

#define TG_SMEM(BM, BN) (3 * ((BM) * 36 + 32 * ((BN) + 8)) * 4)

// ---------------- flash64: QK^T + bias + online softmax + PV -----------------
#define FQSTR 68
struct Flash64Smem {
    float Qs[32*FQSTR*2];
    float Ss[32*FQSTR*2];
    float Ks[64*FQSTR];
    float Vs[64*FQSTR];
    float rowScale[64];
    float rowInv[64];
};
#define FL64_SMEM_BYTES sizeof(Flash64Smem)

__global__ __launch_bounds__(256, 3) void flash64_kernel(
    const float* __restrict__ S, const float* __restrict__ Q,
    const float* __restrict__ K, const float* __restrict__ V,
    float* __restrict__ O)
{
    extern __shared__ char smraw[];
    Flash64Smem& sm = *reinterpret_cast<Flash64Smem*>(smraw);

    const int tid = threadIdx.x;
    const int lane = tid & 31, w = tid >> 5;
    const int wm = w & 1, wn = w >> 1;
    const int g = lane >> 2, t4 = lane & 3;
    const int bh = blockIdx.y, b = bh / NH, h = bh % NH;
    const int q0 = blockIdx.x * 64;

    const float* Qp = Q + ((size_t)bh * LL + q0) * DKK;
    const float* Kp = K + (size_t)bh * LL * DKK;
    const float* Vp = V + (size_t)bh * LL * DKK;
    const float* Sb = S + ((size_t)bh * LL + q0) * LL;

    auto loadK = [&](int t) {
        #pragma unroll
        for (int i = 0; i < 4; i++) {
            int idx = tid + i * 256;
            int r = idx >> 4, d4 = (idx & 15) << 2;
            cp16(&sm.Ks[r * FQSTR + d4], Kp + (size_t)(t * 64 + r) * DKK + d4);
        }
        cp_commit();
    };
    auto loadV = [&](int t) {
        #pragma unroll
        for (int i = 0; i < 4; i++) {
            int idx = tid + i * 256;
            int r = idx >> 4, d4 = (idx & 15) << 2;
            cp16(&sm.Vs[r * FQSTR + d4], Vp + (size_t)(t * 64 + r) * DKK + d4);
        }
        cp_commit();
    };

    loadK(0);
    loadV(0);

    #pragma unroll
    for (int i = 0; i < 4; i++) {
        int idx = tid + i * 256;
        int r = idx >> 4, d4 = (idx & 15) << 2;
        float4 v = *(const float4*)(Qp + (size_t)r * DKK + d4);
        int kk = d4 >> 3, hh = (d4 >> 2) & 1;
        float* p = sm.Qs + ((kk * 4) * FQSTR + r) * 2 + hh;
        p[0]          = tf32f(v.x * 0.125f);
        p[FQSTR*2]    = tf32f(v.y * 0.125f);
        p[FQSTR*4]    = tf32f(v.z * 0.125f);
        p[FQSTR*6]    = tf32f(v.w * 0.125f);
    }

    float accO[2][2][4];
    #pragma unroll
    for (int i = 0; i < 2; i++)
        #pragma unroll
        for (int j = 0; j < 2; j++)
            #pragma unroll
            for (int q = 0; q < 4; q++) accO[i][j][q] = 0.f;

    float rowM = -1e30f, rowL = 0.f;
    const int myrow = tid >> 2, quarter = tid & 3;

    for (int t = 0; t < 16; t++) {
        float accS[2][2][4];
        const int kb = t * 64;
        #pragma unroll
        for (int i = 0; i < 2; i++) {
            int r = wm * 32 + i * 16 + g;
            #pragma unroll
            for (int j = 0; j < 2; j++) {
                int col = kb + wn * 16 + j * 8 + t4 * 2;
                float2 b0 = *(const float2*)(Sb + (size_t)r * LL + col);
                float2 b1 = *(const float2*)(Sb + (size_t)(r + 8) * LL + col);
                accS[i][j][0] = b0.x; accS[i][j][1] = b0.y;
                accS[i][j][2] = b1.x; accS[i][j][3] = b1.y;
            }
        }

        cp_wait<1>();
        __syncthreads();

        #pragma unroll
        for (int ks = 0; ks < 8; ks++) {
            const int kc = ks * 8 + t4;
            unsigned aF[2][4];
            #pragma unroll
            for (int i = 0; i < 2; i++) {
                int mb = wm * 32 + i * 16 + g;
                float2 lo = *(const float2*)(sm.Qs + ((ks * 4 + t4) * FQSTR + mb) * 2);
                float2 hi = *(const float2*)(sm.Qs + ((ks * 4 + t4) * FQSTR + mb + 8) * 2);
                aF[i][0] = __float_as_uint(lo.x); aF[i][1] = __float_as_uint(hi.x);
                aF[i][2] = __float_as_uint(lo.y); aF[i][3] = __float_as_uint(hi.y);
            }
            unsigned bF[2][2];
            #pragma unroll
            for (int j = 0; j < 2; j++) {
                int nb = wn * 16 + j * 8 + g;
                bF[j][0] = __float_as_uint(sm.Ks[nb * FQSTR + kc]);
                bF[j][1] = __float_as_uint(sm.Ks[nb * FQSTR + kc + 4]);
            }
            #pragma unroll
            for (int i = 0; i < 2; i++)
                #pragma unroll
                for (int j = 0; j < 2; j++)
                    mma_tf32(accS[i][j], aF[i], bF[j]);
        }

        {
            const int cc = (t4 & 1) * 2, hh = t4 >> 1;
            #pragma unroll
            for (int i = 0; i < 2; i++) {
                int r = wm * 32 + i * 16 + g;
                #pragma unroll
                for (int j = 0; j < 2; j++) {
                    int colk = (wn * 16 + j * 8 + t4 * 2) >> 3;
                    int e = (colk * 4 + cc) * FQSTR + r;
                    sm.Ss[e * 2 + hh]                 = accS[i][j][0];
                    sm.Ss[(e + FQSTR) * 2 + hh]       = accS[i][j][1];
                    sm.Ss[(e + 8) * 2 + hh]           = accS[i][j][2];
                    sm.Ss[(e + FQSTR + 8) * 2 + hh]   = accS[i][j][3];
                }
            }
        }
        __syncthreads();
        if (t + 1 < 16) loadK(t + 1);

        {
            float2 vals[8];
            float mx = -1e30f;
            #pragma unroll
            for (int e = 0; e < 8; e++) {
                int kk = 2 * quarter + (e >> 2), cc2 = e & 3;
                vals[e] = *(const float2*)(sm.Ss + ((kk * 4 + cc2) * FQSTR + myrow) * 2);
                mx = fmaxf(mx, fmaxf(vals[e].x, vals[e].y));
            }
            mx = fmaxf(mx, __shfl_xor_sync(0xffffffffu, mx, 1));
            mx = fmaxf(mx, __shfl_xor_sync(0xffffffffu, mx, 2));
            float mNew = fmaxf(rowM, mx);
            float scale = __expf(rowM - mNew);
            float sum = 0.f;
            #pragma unroll
            for (int e = 0; e < 8; e++) {
                vals[e].x = __expf(vals[e].x - mNew);
                vals[e].y = __expf(vals[e].y - mNew);
                sum += vals[e].x + vals[e].y;
                int kk = 2 * quarter + (e >> 2), cc2 = e & 3;
                *(float2*)(sm.Ss + ((kk * 4 + cc2) * FQSTR + myrow) * 2) =
                    make_float2(vals[e].x, vals[e].y);
            }
            sum += __shfl_xor_sync(0xffffffffu, sum, 1);
            sum += __shfl_xor_sync(0xffffffffu, sum, 2);
            rowL = rowL * scale + sum;
            rowM = mNew;
            if (quarter == 0) sm.rowScale[myrow] = scale;
        }
        if (t + 1 < 16) cp_wait<1>(); else cp_wait<0>();
        __syncthreads();

        #pragma unroll
        for (int i = 0; i < 2; i++) {
            int r = wm * 32 + i * 16 + g;
            float s0 = sm.rowScale[r], s1 = sm.rowScale[r + 8];
            #pragma unroll
            for (int j = 0; j < 2; j++) {
                accO[i][j][0] *= s0; accO[i][j][1] *= s0;
                accO[i][j][2] *= s1; accO[i][j][3] *= s1;
            }
        }

        #pragma unroll
        for (int ks = 0; ks < 8; ks++) {
            const int kc = ks * 8 + t4;
            unsigned aF[2][4];
            #pragma unroll
            for (int i = 0; i < 2; i++) {
                int mb = wm * 32 + i * 16 + g;
                float2 lo = *(const float2*)(sm.Ss + ((ks * 4 + t4) * FQSTR + mb) * 2);
                float2 hi = *(const float2*)(sm.Ss + ((ks * 4 + t4) * FQSTR + mb + 8) * 2);
                aF[i][0] = __float_as_uint(lo.x); aF[i][1] = __float_as_uint(hi.x);
                aF[i][2] = __float_as_uint(lo.y); aF[i][3] = __float_as_uint(hi.y);
            }
            unsigned bF[2][2];
            #pragma unroll
            for (int j = 0; j < 2; j++) {
                int nb = wn * 16 + j * 8 + g;
                bF[j][0] = __float_as_uint(sm.Vs[kc * FQSTR + nb]);
                bF[j][1] = __float_as_uint(sm.Vs[(kc + 4) * FQSTR + nb]);
            }
            #pragma unroll
            for (int i = 0; i < 2; i++)
                #pragma unroll
                for (int j = 0; j < 2; j++)
                    mma_tf32(accO[i][j], aF[i], bF[j]);
        }
        __syncthreads();
        if (t + 1 < 16) loadV(t + 1);
    }

    if (quarter == 0) sm.rowInv[myrow] = 1.f / rowL;
    __syncthreads();

    float* Op = O + ((size_t)b * LL + q0) * DM + h * DKK;
    #pragma unroll
    for (int i = 0; i < 2; i++) {
        int r = wm * 32 + i * 16 + g;
        float i0 = sm.rowInv[r], i1 = sm.rowInv[r + 8];
        #pragma unroll
        for (int j = 0; j < 2; j++) {
            int col = wn * 16 + j * 8 + t4 * 2;
            *(float2*)(Op + (size_t)r * DM + col) =
                make_float2(accO[i][j][0] * i0, accO[i][j][1] * i0);
            *(float2*)(Op + (size_t)(r + 8) * DM + col) =
                make_float2(accO[i][j][2] * i1, accO[i][j][3] * i1);
        }
    }
}

// ---------------- posbias2: layer-1 scalar, layer-2 via tf32 mma ----------------
__global__ __launch_bounds__(256) void posbias2_kernel(
    const float* __restrict__ sx, const float* __restrict__ sy,
    const float* __restrict__ P1, const float* __restrict__ pb1,
    const float* __restrict__ P2, const float* __restrict__ pb2,
    float* __restrict__ S)
{
    constexpr int HSTR = 260;
    constexpr int PSTR = 20;
    __shared__ float Hs[16 * HSTR * 2];
    __shared__ float Ps[16 * PSTR * 2];
    __shared__ float sP1[64], sPb1[32], sPb2[16];
    __shared__ float qx[16], qy[16], kx[16], ky[16];

    const int b = blockIdx.z;
    const int q0 = blockIdx.y * 16, k0 = blockIdx.x * 16;
    const int tid = threadIdx.x;
    const int lane = tid & 31, w = tid >> 5;
    const int g = lane >> 2, t4 = lane & 3;

    if (tid < 64) sP1[tid] = P1[tid];
    if (tid < 32) sPb1[tid] = pb1[tid];
    if (tid < 16) {
        sPb2[tid] = tid < NH ? pb2[tid] : 0.f;
        qx[tid] = sx[b*LL + q0 + tid];
        qy[tid] = sy[b*LL + q0 + tid];
        kx[tid] = sx[b*LL + k0 + tid];
        ky[tid] = sy[b*LL + k0 + tid];
    }
    #pragma unroll
    for (int ii = 0; ii < 2; ii++) {
        int v = tid + ii * 256;
        int n = v & 15, k = v >> 4;
        float val = (n < NH) ? P2[k * NH + n] : 0.f;
        int kk = k >> 3, hh = (k >> 2) & 1, cc = k & 3;
        Ps[((kk * 4 + cc) * PSTR + n) * 2 + hh] = val;
    }
    __syncthreads();

    {
        int qq = tid >> 4, kq = tid & 15;
        float rx = fminf(fmaxf(qx[qq] - kx[kq], -1000.f), 1000.f) * 0.001f;
        float ry = fminf(fmaxf(qy[qq] - ky[kq], -1000.f), 1000.f) * 0.001f;
        #pragma unroll
        for (int kk = 0; kk < 4; kk++)
            #pragma unroll
            for (int cc = 0; cc < 4; cc++) {
                int j0 = kk * 8 + cc, j1 = j0 + 4;
                float h0 = fmaxf(fmaf(rx, sP1[j0], fmaf(ry, sP1[32+j0], sPb1[j0])), 0.f);
                float h1 = fmaxf(fmaf(rx, sP1[j1], fmaf(ry, sP1[32+j1], sPb1[j1])), 0.f);
                *(float2*)(&Hs[((kk * 4 + cc) * HSTR + tid) * 2]) = make_float2(h0, h1);
            }
    }
    __syncthreads();

    float acc[2][2][4];
    #pragma unroll
    for (int i = 0; i < 2; i++)
        #pragma unroll
        for (int j = 0; j < 2; j++)
            #pragma unroll
            for (int q = 0; q < 4; q++) acc[i][j][q] = 0.f;

    #pragma unroll
    for (int ks = 0; ks < 4; ks++) {
        unsigned aF[2][4];
        #pragma unroll
        for (int i = 0; i < 2; i++) {
            int mb = (w * 2 + i) * 16 + g;
            float2 lo = *(const float2*)(&Hs[((ks * 4 + t4) * HSTR + mb) * 2]);
            float2 hi = *(const float2*)(&Hs[((ks * 4 + t4) * HSTR + mb + 8) * 2]);
            aF[i][0] = __float_as_uint(lo.x); aF[i][1] = __float_as_uint(hi.x);
            aF[i][2] = __float_as_uint(lo.y); aF[i][3] = __float_as_uint(hi.y);
        }
        unsigned bF[2][2];
        #pragma unroll
        for (int j = 0; j < 2; j++) {
            float2 bb = *(const float2*)(&Ps[((ks * 4 + t4) * PSTR + j * 8 + g) * 2]);
            bF[j][0] = __float_as_uint(bb.x); bF[j][1] = __float_as_uint(bb.y);
        }
        #pragma unroll
        for (int i = 0; i < 2; i++)
            #pragma unroll
            for (int j = 0; j < 2; j++)
                mma_tf32(acc[i][j], aF[i], bF[j]);
    }

    #pragma unroll
    for (int i = 0; i < 2; i++) {
        int p0 = (w * 2 + i) * 16 + g;
        int p1 = p0 + 8;
        int q_0 = q0 + (p0 >> 4), k_0 = k0 + (p0 & 15);
        int q_1 = q0 + (p1 >> 4), k_1 = k0 + (p1 & 15);
        #pragma unroll
        for (int j = 0; j < 2; j++) {
            int c0 = j * 8 + t4 * 2, c1 = c0 + 1;
            if (c0 < NH) {
                S[((size_t)(b*NH + c0) * LL + q_0) * LL + k_0] = acc[i][j][0] + sPb2[c0];
                S[((size_t)(b*NH + c0) * LL + q_1) * LL + k_1] = acc[i][j][2] + sPb2[c0];
            }
            if (c1 < NH) {
                S[((size_t)(b*NH + c1) * LL + q_0) * LL + k_0] = acc[i][j][1] + sPb2[c1];
                S[((size_t)(b*NH + c1) * LL + q_1) * LL + k_1] = acc[i][j][3] + sPb2[c1];
            }
        }
    }
}

// ---------------- layernorm over last dim (768) ----------------
__global__ __launch_bounds__(256) void layernorm_kernel(
    const float* __restrict__ X, const float* __restrict__ g, const float* __restrict__ be,
    float* __restrict__ Y)
{
    __shared__ float red[256];
    const size_t row = blockIdx.x;
    const float* p = X + row * DM;
    float* o = Y + row * DM;
    const int tid = threadIdx.x;
    float v[3];
    float s = 0.f;
    #pragma unroll
    for (int i = 0; i < 3; i++) { v[i] = p[tid + i*256]; s += v[i]; }
    red[tid] = s; __syncthreads();
    for (int st = 128; st > 0; st >>= 1) { if (tid < st) red[tid] += red[tid+st]; __syncthreads(); }
    float mean = red[0] * (1.f/DM); __syncthreads();
    float sq = 0.f;
    #pragma unroll
    for (int i = 0; i < 3; i++) { float d = v[i] - mean; sq += d*d; }
    red[tid] = sq; __syncthreads();
    for (int st = 128; st > 0; st >>= 1) { if (tid < st) red[tid] += red[tid+st]; __syncthreads(); }
    float rstd = rsqrtf(red[0] * (1.f/DM) + 1e-5f);
    #pragma unroll
    for (int i = 0; i < 3; i++) {
        int c = tid + i*256;
        o[c] = (v[i] - mean) * rstd * g[c] + be[c];
    }
}

// ---------------- launch ----------------
extern "C" void kernel_launch(void* const* d_in, const int* in_sizes, int n_in,
                              void* d_out, int out_size)
{
    const float* src = (const float*)d_in[0];
    const float* sx  = (const float*)d_in[1];
    const float* sy  = (const float*)d_in[2];
    const float* Wq  = (const float*)d_in[3];  const float* bq  = (const float*)d_in[4];
    const float* Wk  = (const float*)d_in[5];  const float* bk  = (const float*)d_in[6];
    const float* Wv  = (const float*)d_in[7];  const float* bv  = (const float*)d_in[8];
    const float* Wo  = (const float*)d_in[9];  const float* bo  = (const float*)d_in[10];
    const float* P1  = (const float*)d_in[11]; const float* pb1 = (const float*)d_in[12];
    const float* P2  = (const float*)d_in[13]; const float* pb2 = (const float*)d_in[14];
    const float* W1  = (const float*)d_in[15]; const float* b1  = (const float*)d_in[16];
    const float* W2  = (const float*)d_in[17]; const float* b2  = (const float*)d_in[18];
    const float* g1  = (const float*)d_in[19]; const float* be1 = (const float*)d_in[20];
    const float* g2  = (const float*)d_in[21]; const float* be2 = (const float*)d_in[22];
    float* out = (float*)d_out;

    float *Q, *K, *V, *S, *O, *Xres, *X1, *H1;
    cudaGetSymbolAddress((void**)&Q,    g_Q);
    cudaGetSymbolAddress((void**)&K,    g_K);
    cudaGetSymbolAddress((void**)&V,    g_V);
    cudaGetSymbolAddress((void**)&S,    g_S);
    cudaGetSymbolAddress((void**)&O,    g_O);
    cudaGetSymbolAddress((void**)&Xres, g_Xres);
    cudaGetSymbolAddress((void**)&X1,   g_X1);
    cudaGetSymbolAddress((void**)&H1,   g_H1);

    cudaFuncSetAttribute(flash64_kernel, cudaFuncAttributeMaxDynamicSharedMemorySize,
                         (int)FL64_SMEM_BYTES);
    cudaFuncSetAttribute(tgemm<3, 128, 128>, cudaFuncAttributeMaxDynamicSharedMemorySize,
                         TG_SMEM(128, 128));
    cudaFuncSetAttribute(tgemm<1, 128, 128>, cudaFuncAttributeMaxDynamicSharedMemorySize,
                         TG_SMEM(128, 128));
    cudaFuncSetAttribute(tgemm<2, 64, 64>, cudaFuncAttributeMaxDynamicSharedMemorySize,
                         TG_SMEM(64, 64));

    // 1) relative-position bias -> S
    posbias2_kernel<<<dim3(LL/16, LL/16, BB), 256>>>(sx, sy, P1, pb1, P2, pb2, S);

    // 2) fused QKV projections, scatter to (b,h,l,d)
    tgemm<3, 128, 128><<<dim3(18, ROWS/128, 1), 256, TG_SMEM(128, 128)>>>(
        src, DM, Wq, DM, bq, nullptr, Q, 0, DM,
        Wk, Wv, bk, bv, K, V);

    // 3) flash attention: softmax(QK^T/8 + bias) @ V -> O
    flash64_kernel<<<dim3(LL/64, BB*NH), 256, FL64_SMEM_BYTES>>>(S, Q, K, V, O);

    // 4) Xres = src + O @ Wo + bo ; LN1 -> X1
    tgemm<2, 64, 64><<<dim3(DM/64, ROWS/64, 1), 256, TG_SMEM(64, 64)>>>(
        O, DM, Wo, DM, bo, src, Xres, DM, DM,
        nullptr, nullptr, nullptr, nullptr, nullptr, nullptr);
    layernorm_kernel<<<ROWS, 256>>>(Xres, g1, be1, X1);

    // 5) FFN
    tgemm<1, 128, 128><<<dim3(FFD/128, ROWS/128, 1), 256, TG_SMEM(128, 128)>>>(
        X1, DM, W1, FFD, b1, nullptr, H1, FFD, DM,
        nullptr, nullptr, nullptr, nullptr, nullptr, nullptr);
    tgemm<2, 64, 64><<<dim3(DM/64, ROWS/64, 1), 256, TG_SMEM(64, 64)>>>(
        H1, FFD, W2, DM, b2, X1, Xres, DM, FFD,
        nullptr, nullptr, nullptr, nullptr, nullptr, nullptr);

    // 6) LN2 -> output
    layernorm_kernel<<<ROWS, 256>>>(Xres, g2, be2, out);
}

// round 10
// speedup vs baseline: 1.3160x; 1.0111x over previous
#include <cuda_runtime.h>
#include <math.h>

#define BB 2
#define LL 1024
#define DM 768
#define NH 12
#define DKK 64
#define FFD 3072
#define PH 32
#define ROWS (BB*LL)

// ---------------- scratch ----------------
__device__ float g_Q[BB*NH*LL*DKK];
__device__ float g_K[BB*NH*LL*DKK];
__device__ float g_V[BB*NH*LL*DKK];
__device__ float g_S[(size_t)BB*NH*LL*LL];
__device__ float g_O[BB*LL*DM];
__device__ float g_Xres[BB*LL*DM];
__device__ float g_X1[BB*LL*DM];
__device__ float g_H1[BB*LL*FFD];

// ---------------- helpers ----------------
__device__ __forceinline__ unsigned tf32u(float x) {
    unsigned u;
    asm("cvt.rna.tf32.f32 %0, %1;" : "=r"(u) : "f"(x));
    return u;
}
__device__ __forceinline__ float tf32f(float x) { return __uint_as_float(tf32u(x)); }

// mma consumes raw fp32 bits as tf32 (HW truncates low mantissa bits)
__device__ __forceinline__ void mma_tf32(float* c, const unsigned* a, const unsigned* b) {
    asm volatile(
        "mma.sync.aligned.m16n8k8.row.col.f32.tf32.tf32.f32 "
        "{%0,%1,%2,%3}, {%4,%5,%6,%7}, {%8,%9}, {%0,%1,%2,%3};"
        : "+f"(c[0]), "+f"(c[1]), "+f"(c[2]), "+f"(c[3])
        : "r"(a[0]), "r"(a[1]), "r"(a[2]), "r"(a[3]), "r"(b[0]), "r"(b[1]));
}

__device__ __forceinline__ void cp16(float* dst_smem, const float* src) {
    unsigned d = (unsigned)__cvta_generic_to_shared(dst_smem);
    asm volatile("cp.async.cg.shared.global [%0], [%1], 16;" :: "r"(d), "l"(src));
}
__device__ __forceinline__ void cp_commit() { asm volatile("cp.async.commit_group;"); }
template<int N> __device__ __forceinline__ void cp_wait() {
    asm volatile("cp.async.wait_group %0;" :: "n"(N));
}

// ---------------- tensor-core GEMM body: BK=32, 3-stage cp.async ----------------
// EPI 1: relu(+bias)  2: +bias +R residual  3: fused QKV scatter
// 8 warps = 2(m) x 4(n). Warp tile (BM/2) x (BN/4).
template<int EPI, int BM, int BN>
__device__ __forceinline__ void tgemm_body(
    int bxi, int byi,
    const float* __restrict__ A, int lda,
    const float* __restrict__ B, int ldb,
    const float* __restrict__ bias,
    const float* __restrict__ Rres,
    float* __restrict__ C, int ldc,
    int K,
    const float* __restrict__ B1, const float* __restrict__ B2,
    const float* __restrict__ bias1, const float* __restrict__ bias2,
    float* __restrict__ C1, float* __restrict__ C2,
    float* dynsm)
{
    constexpr int MI  = BM / 32;
    constexpr int NT  = BN / 32;
    constexpr int WNS = BN / 4;
    constexpr int AP  = 36;
    constexpr int BP  = BN + 8;
    constexpr int ASZ = BM * AP;
    constexpr int BSZ = 32 * BP;
    float* As = dynsm;
    float* Bs = dynsm + 3 * ASZ;

    const int tid = threadIdx.x;
    const int lane = tid & 31, w = tid >> 5;
    const int wm = w & 1, wn = w >> 1;
    const int g = lane >> 2, t4 = lane & 3;
    int bx = bxi;
    const int m0 = byi * BM;

    const float* Ap = A;
    const float* Bp = B; const float* biasp = bias; float* Cp = C;
    if (EPI == 3) {
        int sel = bx / 6; bx -= sel * 6;
        Bp    = sel == 0 ? B    : (sel == 1 ? B1    : B2);
        biasp = sel == 0 ? bias : (sel == 1 ? bias1 : bias2);
        Cp    = sel == 0 ? C    : (sel == 1 ? C1    : C2);
    }
    const int n0 = bx * BN;

    float acc[MI][NT][4];
    #pragma unroll
    for (int i = 0; i < MI; i++)
        #pragma unroll
        for (int j = 0; j < NT; j++)
            #pragma unroll
            for (int q = 0; q < 4; q++) acc[i][j][q] = 0.f;

    auto loadA = [&](int kt, int st) {
        #pragma unroll
        for (int i = 0; i < BM / 32; i++) {
            int idx = tid + i * 256;
            int m = idx >> 3, k4 = (idx & 7) << 2;
            cp16(&As[st * ASZ + m * AP + k4], Ap + (size_t)(m0 + m) * lda + kt + k4);
        }
    };
    auto loadB = [&](int kt, int st) {
        if (BN == 128) {
            #pragma unroll
            for (int i = 0; i < 4; i++) {
                int idx = tid + i * 256;
                int k = idx >> 5, n4 = (idx & 31) << 2;
                cp16(&Bs[st * BSZ + k * BP + n4], Bp + (size_t)(kt + k) * ldb + n0 + n4);
            }
        } else {
            #pragma unroll
            for (int i = 0; i < 2; i++) {
                int idx = tid + i * 256;
                int k = idx >> 4, n4 = (idx & 15) << 2;
                cp16(&Bs[st * BSZ + k * BP + n4], Bp + (size_t)(kt + k) * ldb + n0 + n4);
            }
        }
    };
    auto ldA = [&](int st, int kk, unsigned (&aF)[MI][4]) {
        const int kc = kk * 8 + t4;
        #pragma unroll
        for (int i = 0; i < MI; i++) {
            int mb = wm * (MI * 16) + i * 16 + g;
            aF[i][0] = __float_as_uint(As[st * ASZ + mb * AP + kc]);
            aF[i][1] = __float_as_uint(As[st * ASZ + (mb + 8) * AP + kc]);
            aF[i][2] = __float_as_uint(As[st * ASZ + mb * AP + kc + 4]);
            aF[i][3] = __float_as_uint(As[st * ASZ + (mb + 8) * AP + kc + 4]);
        }
    };
    auto ldB = [&](int st, int kk, unsigned (&bF)[NT][2]) {
        const int kc = kk * 8 + t4;
        #pragma unroll
        for (int j = 0; j < NT; j++) {
            int nb = wn * WNS + j * 8 + g;
            bF[j][0] = __float_as_uint(Bs[st * BSZ + kc * BP + nb]);
            bF[j][1] = __float_as_uint(Bs[st * BSZ + (kc + 4) * BP + nb]);
        }
    };
    auto compute = [&](int st) {
        unsigned aF[MI][4];
        unsigned bF[2][NT][2];
        ldB(st, 0, bF[0]);
        #pragma unroll
        for (int kk = 0; kk < 4; kk++) {
            const int cb = kk & 1;
            ldA(st, kk, aF);
            if (kk < 3) ldB(st, kk + 1, bF[cb ^ 1]);
            #pragma unroll
            for (int i = 0; i < MI; i++)
                #pragma unroll
                for (int j = 0; j < NT; j++)
                    mma_tf32(acc[i][j], aF[i], bF[cb][j]);
        }
    };

    const int nt = K >> 5;
    loadA(0, 0); loadB(0, 0); cp_commit();
    if (nt > 1) { loadA(32, 1); loadB(32, 1); cp_commit(); }
    for (int t = 0; t < nt; t++) {
        if (t + 1 < nt) cp_wait<1>(); else cp_wait<0>();
        __syncthreads();
        compute(t % 3);
        if (t + 2 < nt) {
            int st = (t + 2) % 3;
            loadA((t + 2) << 5, st);
            loadB((t + 2) << 5, st);
            cp_commit();
        }
    }

    auto epi = [&](int row, int col, float2 v) {
        float2 bb = *(const float2*)(biasp + col);
        v.x += bb.x; v.y += bb.y;
        if (EPI == 1) { v.x = fmaxf(v.x, 0.f); v.y = fmaxf(v.y, 0.f); }
        if (EPI == 2) {
            float2 r = *(const float2*)(Rres + (size_t)row * ldc + col);
            v.x += r.x; v.y += r.y;
        }
        if (EPI == 3) {
            int h = col >> 6, d = col & 63;
            float* dst = Cp + ((((size_t)(row >> 10) * NH + h) * LL + (row & 1023)) * DKK + d);
            *(float2*)dst = v;
            return;
        }
        *(float2*)(Cp + (size_t)row * ldc + col) = v;
    };

    #pragma unroll
    for (int i = 0; i < MI; i++) {
        int r0 = m0 + wm * (MI * 16) + i * 16 + g;
        #pragma unroll
        for (int j = 0; j < NT; j++) {
            int col = n0 + wn * WNS + j * 8 + t4 * 2;
            epi(r0,     col, make_float2(acc[i][j][0], acc[i][j][1]));
            epi(r0 + 8, col, make_float2(acc[i][j][2], acc[i][j][3]));
        }
    }
}

#define TG_SMEM(BM, BN) (3 * ((BM) * 36 + 32 * ((BN) + 8)) * 4)

template<int EPI, int BM, int BN>
__global__ __launch_bounds__(256, (BM == 64 && BN == 64) ? 3 : 2) void tgemm(
    const float* __restrict__ A, int lda,
    const float* __restrict__ B, int ldb,
    const float* __restrict__ bias,
    const float* __restrict__ Rres,
    float* __restrict__ C, int ldc,
    int K,
    const float* __restrict__ B1, const float* __restrict__ B2,
    const float* __restrict__ bias1, const float* __restrict__ bias2,
    float* __restrict__ C1, float* __restrict__ C2)
{
    extern __shared__ float dynsm[];
    tgemm_body<EPI, BM, BN>(blockIdx.x, blockIdx.y, A, lda, B, ldb, bias, Rres,
                            C, ldc, K, B1, B2, bias1, bias2, C1, C2, dynsm);
}

// ---------------- posbias body: layer-1 scalar, layer-2 via tf32 mma ----------------
__device__ __forceinline__ void posbias_body(
    int kx, int qy, int b,
    const float* __restrict__ sx, const float* __restrict__ sy,
    const float* __restrict__ P1, const float* __restrict__ pb1,
    const float* __restrict__ P2, const float* __restrict__ pb2,
    float* __restrict__ S, float* dynsm)
{
    constexpr int HSTR = 260;
    constexpr int PSTR = 20;
    float* Hs   = dynsm;                  // 16*260*2 = 8320
    float* Ps   = Hs + 16 * HSTR * 2;     // 16*20*2  = 640
    float* sP1  = Ps + 16 * PSTR * 2;     // 64
    float* sPb1 = sP1 + 64;               // 32
    float* sPb2 = sPb1 + 32;              // 16
    float* qx   = sPb2 + 16;
    float* qy_  = qx + 16;
    float* kxp  = qy_ + 16;
    float* kyp  = kxp + 16;

    const int q0 = qy * 16, k0 = kx * 16;
    const int tid = threadIdx.x;
    const int lane = tid & 31, w = tid >> 5;
    const int g = lane >> 2, t4 = lane & 3;

    if (tid < 64) sP1[tid] = P1[tid];
    if (tid < 32) sPb1[tid] = pb1[tid];
    if (tid < 16) {
        sPb2[tid] = tid < NH ? pb2[tid] : 0.f;
        qx[tid]  = sx[b*LL + q0 + tid];
        qy_[tid] = sy[b*LL + q0 + tid];
        kxp[tid] = sx[b*LL + k0 + tid];
        kyp[tid] = sy[b*LL + k0 + tid];
    }
    #pragma unroll
    for (int ii = 0; ii < 2; ii++) {
        int v = tid + ii * 256;
        int n = v & 15, k = v >> 4;
        float val = (n < NH) ? P2[k * NH + n] : 0.f;
        int kk = k >> 3, hh = (k >> 2) & 1, cc = k & 3;
        Ps[((kk * 4 + cc) * PSTR + n) * 2 + hh] = val;
    }
    __syncthreads();

    {
        int qq = tid >> 4, kq = tid & 15;
        float rx = fminf(fmaxf(qx[qq] - kxp[kq], -1000.f), 1000.f) * 0.001f;
        float ry = fminf(fmaxf(qy_[qq] - kyp[kq], -1000.f), 1000.f) * 0.001f;
        #pragma unroll
        for (int kk = 0; kk < 4; kk++)
            #pragma unroll
            for (int cc = 0; cc < 4; cc++) {
                int j0 = kk * 8 + cc, j1 = j0 + 4;
                float h0 = fmaxf(fmaf(rx, sP1[j0], fmaf(ry, sP1[32+j0], sPb1[j0])), 0.f);
                float h1 = fmaxf(fmaf(rx, sP1[j1], fmaf(ry, sP1[32+j1], sPb1[j1])), 0.f);
                *(float2*)(&Hs[((kk * 4 + cc) * HSTR + tid) * 2]) = make_float2(h0, h1);
            }
    }
    __syncthreads();

    float acc[2][2][4];
    #pragma unroll
    for (int i = 0; i < 2; i++)
        #pragma unroll
        for (int j = 0; j < 2; j++)
            #pragma unroll
            for (int q = 0; q < 4; q++) acc[i][j][q] = 0.f;

    #pragma unroll
    for (int ks = 0; ks < 4; ks++) {
        unsigned aF[2][4];
        #pragma unroll
        for (int i = 0; i < 2; i++) {
            int mb = (w * 2 + i) * 16 + g;
            float2 lo = *(const float2*)(&Hs[((ks * 4 + t4) * HSTR + mb) * 2]);
            float2 hi = *(const float2*)(&Hs[((ks * 4 + t4) * HSTR + mb + 8) * 2]);
            aF[i][0] = __float_as_uint(lo.x); aF[i][1] = __float_as_uint(hi.x);
            aF[i][2] = __float_as_uint(lo.y); aF[i][3] = __float_as_uint(hi.y);
        }
        unsigned bF[2][2];
        #pragma unroll
        for (int j = 0; j < 2; j++) {
            float2 bb = *(const float2*)(&Ps[((ks * 4 + t4) * PSTR + j * 8 + g) * 2]);
            bF[j][0] = __float_as_uint(bb.x); bF[j][1] = __float_as_uint(bb.y);
        }
        #pragma unroll
        for (int i = 0; i < 2; i++)
            #pragma unroll
            for (int j = 0; j < 2; j++)
                mma_tf32(acc[i][j], aF[i], bF[j]);
    }

    #pragma unroll
    for (int i = 0; i < 2; i++) {
        int p0 = (w * 2 + i) * 16 + g;
        int p1 = p0 + 8;
        int q_0 = q0 + (p0 >> 4), k_0 = k0 + (p0 & 15);
        int q_1 = q0 + (p1 >> 4), k_1 = k0 + (p1 & 15);
        #pragma unroll
        for (int j = 0; j < 2; j++) {
            int c0 = j * 8 + t4 * 2, c1 = c0 + 1;
            if (c0 < NH) {
                S[((size_t)(b*NH + c0) * LL + q_0) * LL + k_0] = acc[i][j][0] + sPb2[c0];
                S[((size_t)(b*NH + c0) * LL + q_1) * LL + k_1] = acc[i][j][2] + sPb2[c0];
            }
            if (c1 < NH) {
                S[((size_t)(b*NH + c1) * LL + q_0) * LL + k_0] = acc[i][j][1] + sPb2[c1];
                S[((size_t)(b*NH + c1) * LL + q_1) * LL + k_1] = acc[i][j][3] + sPb2[c1];
            }
        }
    }
}

// ---------------- fused posbias + QKV (heterogeneous grid) ----------------
// blocks [0,288): QKV tgemm<3,128,128> (grid 18 x 16 linearized)
// blocks [288,8480): posbias tiles (64k x 64q x 2b)
#define QKV_BLOCKS 288
#define PBQKV_GRID (QKV_BLOCKS + 64*64*BB)

__global__ __launch_bounds__(256, 2) void pbqkv_kernel(
    const float* __restrict__ src,
    const float* __restrict__ Wq, const float* __restrict__ bq,
    const float* __restrict__ Wk, const float* __restrict__ bk,
    const float* __restrict__ Wv, const float* __restrict__ bv,
    float* __restrict__ Q, float* __restrict__ Kq, float* __restrict__ V,
    const float* __restrict__ sx, const float* __restrict__ sy,
    const float* __restrict__ P1, const float* __restrict__ pb1,
    const float* __restrict__ P2, const float* __restrict__ pb2,
    float* __restrict__ S)
{
    extern __shared__ float dynsm[];
    const int bid = blockIdx.x;
    if (bid < QKV_BLOCKS) {
        tgemm_body<3, 128, 128>(bid % 18, bid / 18,
            src, DM, Wq, DM, bq, nullptr, Q, 0, DM,
            Wk, Wv, bk, bv, Kq, V, dynsm);
    } else {
        int p = bid - QKV_BLOCKS;
        posbias_body(p & 63, (p >> 6) & 63, p >> 12,
                     sx, sy, P1, pb1, P2, pb2, S, dynsm);
    }
}

// ---------------- flash64: QK^T + bias + online softmax + PV -----------------
#define FQSTR 68
struct Flash64Smem {
    float Qs[32*FQSTR*2];
    float Ss[32*FQSTR*2];
    float Ks[64*FQSTR];
    float Vs[64*FQSTR];
    float rowScale[64];
    float rowInv[64];
};
#define FL64_SMEM_BYTES sizeof(Flash64Smem)

__global__ __launch_bounds__(256, 3) void flash64_kernel(
    const float* __restrict__ S, const float* __restrict__ Q,
    const float* __restrict__ K, const float* __restrict__ V,
    float* __restrict__ O)
{
    extern __shared__ char smraw[];
    Flash64Smem& sm = *reinterpret_cast<Flash64Smem*>(smraw);

    const int tid = threadIdx.x;
    const int lane = tid & 31, w = tid >> 5;
    const int wm = w & 1, wn = w >> 1;
    const int g = lane >> 2, t4 = lane & 3;
    const int bh = blockIdx.y, b = bh / NH, h = bh % NH;
    const int q0 = blockIdx.x * 64;

    const float* Qp = Q + ((size_t)bh * LL + q0) * DKK;
    const float* Kp = K + (size_t)bh * LL * DKK;
    const float* Vp = V + (size_t)bh * LL * DKK;
    const float* Sb = S + ((size_t)bh * LL + q0) * LL;

    auto loadK = [&](int t) {
        #pragma unroll
        for (int i = 0; i < 4; i++) {
            int idx = tid + i * 256;
            int r = idx >> 4, d4 = (idx & 15) << 2;
            cp16(&sm.Ks[r * FQSTR + d4], Kp + (size_t)(t * 64 + r) * DKK + d4);
        }
        cp_commit();
    };
    auto loadV = [&](int t) {
        #pragma unroll
        for (int i = 0; i < 4; i++) {
            int idx = tid + i * 256;
            int r = idx >> 4, d4 = (idx & 15) << 2;
            cp16(&sm.Vs[r * FQSTR + d4], Vp + (size_t)(t * 64 + r) * DKK + d4);
        }
        cp_commit();
    };

    loadK(0);
    loadV(0);

    #pragma unroll
    for (int i = 0; i < 4; i++) {
        int idx = tid + i * 256;
        int r = idx >> 4, d4 = (idx & 15) << 2;
        float4 v = *(const float4*)(Qp + (size_t)r * DKK + d4);
        int kk = d4 >> 3, hh = (d4 >> 2) & 1;
        float* p = sm.Qs + ((kk * 4) * FQSTR + r) * 2 + hh;
        p[0]          = tf32f(v.x * 0.125f);
        p[FQSTR*2]    = tf32f(v.y * 0.125f);
        p[FQSTR*4]    = tf32f(v.z * 0.125f);
        p[FQSTR*6]    = tf32f(v.w * 0.125f);
    }

    float accO[2][2][4];
    #pragma unroll
    for (int i = 0; i < 2; i++)
        #pragma unroll
        for (int j = 0; j < 2; j++)
            #pragma unroll
            for (int q = 0; q < 4; q++) accO[i][j][q] = 0.f;

    float rowM = -1e30f, rowL = 0.f;
    const int myrow = tid >> 2, quarter = tid & 3;

    for (int t = 0; t < 16; t++) {
        float accS[2][2][4];
        const int kb = t * 64;
        #pragma unroll
        for (int i = 0; i < 2; i++) {
            int r = wm * 32 + i * 16 + g;
            #pragma unroll
            for (int j = 0; j < 2; j++) {
                int col = kb + wn * 16 + j * 8 + t4 * 2;
                float2 b0 = *(const float2*)(Sb + (size_t)r * LL + col);
                float2 b1 = *(const float2*)(Sb + (size_t)(r + 8) * LL + col);
                accS[i][j][0] = b0.x; accS[i][j][1] = b0.y;
                accS[i][j][2] = b1.x; accS[i][j][3] = b1.y;
            }
        }

        cp_wait<1>();
        __syncthreads();

        #pragma unroll
        for (int ks = 0; ks < 8; ks++) {
            const int kc = ks * 8 + t4;
            unsigned aF[2][4];
            #pragma unroll
            for (int i = 0; i < 2; i++) {
                int mb = wm * 32 + i * 16 + g;
                float2 lo = *(const float2*)(sm.Qs + ((ks * 4 + t4) * FQSTR + mb) * 2);
                float2 hi = *(const float2*)(sm.Qs + ((ks * 4 + t4) * FQSTR + mb + 8) * 2);
                aF[i][0] = __float_as_uint(lo.x); aF[i][1] = __float_as_uint(hi.x);
                aF[i][2] = __float_as_uint(lo.y); aF[i][3] = __float_as_uint(hi.y);
            }
            unsigned bF[2][2];
            #pragma unroll
            for (int j = 0; j < 2; j++) {
                int nb = wn * 16 + j * 8 + g;
                bF[j][0] = __float_as_uint(sm.Ks[nb * FQSTR + kc]);
                bF[j][1] = __float_as_uint(sm.Ks[nb * FQSTR + kc + 4]);
            }
            #pragma unroll
            for (int i = 0; i < 2; i++)
                #pragma unroll
                for (int j = 0; j < 2; j++)
                    mma_tf32(accS[i][j], aF[i], bF[j]);
        }

        {
            const int cc = (t4 & 1) * 2, hh = t4 >> 1;
            #pragma unroll
            for (int i = 0; i < 2; i++) {
                int r = wm * 32 + i * 16 + g;
                #pragma unroll
                for (int j = 0; j < 2; j++) {
                    int colk = (wn * 16 + j * 8 + t4 * 2) >> 3;
                    int e = (colk * 4 + cc) * FQSTR + r;
                    sm.Ss[e * 2 + hh]                 = accS[i][j][0];
                    sm.Ss[(e + FQSTR) * 2 + hh]       = accS[i][j][1];
                    sm.Ss[(e + 8) * 2 + hh]           = accS[i][j][2];
                    sm.Ss[(e + FQSTR + 8) * 2 + hh]   = accS[i][j][3];
                }
            }
        }
        __syncthreads();
        if (t + 1 < 16) loadK(t + 1);

        {
            float2 vals[8];
            float mx = -1e30f;
            #pragma unroll
            for (int e = 0; e < 8; e++) {
                int kk = 2 * quarter + (e >> 2), cc2 = e & 3;
                vals[e] = *(const float2*)(sm.Ss + ((kk * 4 + cc2) * FQSTR + myrow) * 2);
                mx = fmaxf(mx, fmaxf(vals[e].x, vals[e].y));
            }
            mx = fmaxf(mx, __shfl_xor_sync(0xffffffffu, mx, 1));
            mx = fmaxf(mx, __shfl_xor_sync(0xffffffffu, mx, 2));
            float mNew = fmaxf(rowM, mx);
            float scale = __expf(rowM - mNew);
            float sum = 0.f;
            #pragma unroll
            for (int e = 0; e < 8; e++) {
                vals[e].x = __expf(vals[e].x - mNew);
                vals[e].y = __expf(vals[e].y - mNew);
                sum += vals[e].x + vals[e].y;
                int kk = 2 * quarter + (e >> 2), cc2 = e & 3;
                *(float2*)(sm.Ss + ((kk * 4 + cc2) * FQSTR + myrow) * 2) =
                    make_float2(vals[e].x, vals[e].y);
            }
            sum += __shfl_xor_sync(0xffffffffu, sum, 1);
            sum += __shfl_xor_sync(0xffffffffu, sum, 2);
            rowL = rowL * scale + sum;
            rowM = mNew;
            if (quarter == 0) sm.rowScale[myrow] = scale;
        }
        if (t + 1 < 16) cp_wait<1>(); else cp_wait<0>();
        __syncthreads();

        #pragma unroll
        for (int i = 0; i < 2; i++) {
            int r = wm * 32 + i * 16 + g;
            float s0 = sm.rowScale[r], s1 = sm.rowScale[r + 8];
            #pragma unroll
            for (int j = 0; j < 2; j++) {
                accO[i][j][0] *= s0; accO[i][j][1] *= s0;
                accO[i][j][2] *= s1; accO[i][j][3] *= s1;
            }
        }

        #pragma unroll
        for (int ks = 0; ks < 8; ks++) {
            const int kc = ks * 8 + t4;
            unsigned aF[2][4];
            #pragma unroll
            for (int i = 0; i < 2; i++) {
                int mb = wm * 32 + i * 16 + g;
                float2 lo = *(const float2*)(sm.Ss + ((ks * 4 + t4) * FQSTR + mb) * 2);
                float2 hi = *(const float2*)(sm.Ss + ((ks * 4 + t4) * FQSTR + mb + 8) * 2);
                aF[i][0] = __float_as_uint(lo.x); aF[i][1] = __float_as_uint(hi.x);
                aF[i][2] = __float_as_uint(lo.y); aF[i][3] = __float_as_uint(hi.y);
            }
            unsigned bF[2][2];
            #pragma unroll
            for (int j = 0; j < 2; j++) {
                int nb = wn * 16 + j * 8 + g;
                bF[j][0] = __float_as_uint(sm.Vs[kc * FQSTR + nb]);
                bF[j][1] = __float_as_uint(sm.Vs[(kc + 4) * FQSTR + nb]);
            }
            #pragma unroll
            for (int i = 0; i < 2; i++)
                #pragma unroll
                for (int j = 0; j < 2; j++)
                    mma_tf32(accO[i][j], aF[i], bF[j]);
        }
        __syncthreads();
        if (t + 1 < 16) loadV(t + 1);
    }

    if (quarter == 0) sm.rowInv[myrow] = 1.f / rowL;
    __syncthreads();

    float* Op = O + ((size_t)b * LL + q0) * DM + h * DKK;
    #pragma unroll
    for (int i = 0; i < 2; i++) {
        int r = wm * 32 + i * 16 + g;
        float i0 = sm.rowInv[r], i1 = sm.rowInv[r + 8];
        #pragma unroll
        for (int j = 0; j < 2; j++) {
            int col = wn * 16 + j * 8 + t4 * 2;
            *(float2*)(Op + (size_t)r * DM + col) =
                make_float2(accO[i][j][0] * i0, accO[i][j][1] * i0);
            *(float2*)(Op + (size_t)(r + 8) * DM + col) =
                make_float2(accO[i][j][2] * i1, accO[i][j][3] * i1);
        }
    }
}

// ---------------- layernorm over last dim (768) ----------------
__global__ __launch_bounds__(256) void layernorm_kernel(
    const float* __restrict__ X, const float* __restrict__ g, const float* __restrict__ be,
    float* __restrict__ Y)
{
    __shared__ float red[256];
    const size_t row = blockIdx.x;
    const float* p = X + row * DM;
    float* o = Y + row * DM;
    const int tid = threadIdx.x;
    float v[3];
    float s = 0.f;
    #pragma unroll
    for (int i = 0; i < 3; i++) { v[i] = p[tid + i*256]; s += v[i]; }
    red[tid] = s; __syncthreads();
    for (int st = 128; st > 0; st >>= 1) { if (tid < st) red[tid] += red[tid+st]; __syncthreads(); }
    float mean = red[0] * (1.f/DM); __syncthreads();
    float sq = 0.f;
    #pragma unroll
    for (int i = 0; i < 3; i++) { float d = v[i] - mean; sq += d*d; }
    red[tid] = sq; __syncthreads();
    for (int st = 128; st > 0; st >>= 1) { if (tid < st) red[tid] += red[tid+st]; __syncthreads(); }
    float rstd = rsqrtf(red[0] * (1.f/DM) + 1e-5f);
    #pragma unroll
    for (int i = 0; i < 3; i++) {
        int c = tid + i*256;
        o[c] = (v[i] - mean) * rstd * g[c] + be[c];
    }
}

// ---------------- launch ----------------
extern "C" void kernel_launch(void* const* d_in, const int* in_sizes, int n_in,
                              void* d_out, int out_size)
{
    const float* src = (const float*)d_in[0];
    const float* sx  = (const float*)d_in[1];
    const float* sy  = (const float*)d_in[2];
    const float* Wq  = (const float*)d_in[3];  const float* bq  = (const float*)d_in[4];
    const float* Wk  = (const float*)d_in[5];  const float* bk  = (const float*)d_in[6];
    const float* Wv  = (const float*)d_in[7];  const float* bv  = (const float*)d_in[8];
    const float* Wo  = (const float*)d_in[9];  const float* bo  = (const float*)d_in[10];
    const float* P1  = (const float*)d_in[11]; const float* pb1 = (const float*)d_in[12];
    const float* P2  = (const float*)d_in[13]; const float* pb2 = (const float*)d_in[14];
    const float* W1  = (const float*)d_in[15]; const float* b1  = (const float*)d_in[16];
    const float* W2  = (const float*)d_in[17]; const float* b2  = (const float*)d_in[18];
    const float* g1  = (const float*)d_in[19]; const float* be1 = (const float*)d_in[20];
    const float* g2  = (const float*)d_in[21]; const float* be2 = (const float*)d_in[22];
    float* out = (float*)d_out;

    float *Q, *K, *V, *S, *O, *Xres, *X1, *H1;
    cudaGetSymbolAddress((void**)&Q,    g_Q);
    cudaGetSymbolAddress((void**)&K,    g_K);
    cudaGetSymbolAddress((void**)&V,    g_V);
    cudaGetSymbolAddress((void**)&S,    g_S);
    cudaGetSymbolAddress((void**)&O,    g_O);
    cudaGetSymbolAddress((void**)&Xres, g_Xres);
    cudaGetSymbolAddress((void**)&X1,   g_X1);
    cudaGetSymbolAddress((void**)&H1,   g_H1);

    cudaFuncSetAttribute(flash64_kernel, cudaFuncAttributeMaxDynamicSharedMemorySize,
                         (int)FL64_SMEM_BYTES);
    cudaFuncSetAttribute(pbqkv_kernel, cudaFuncAttributeMaxDynamicSharedMemorySize,
                         TG_SMEM(128, 128));
    cudaFuncSetAttribute(tgemm<1, 128, 128>, cudaFuncAttributeMaxDynamicSharedMemorySize,
                         TG_SMEM(128, 128));
    cudaFuncSetAttribute(tgemm<2, 64, 64>, cudaFuncAttributeMaxDynamicSharedMemorySize,
                         TG_SMEM(64, 64));

    // 1) fused: relative-position bias -> S  ||  QKV projections -> Q,K,V
    pbqkv_kernel<<<PBQKV_GRID, 256, TG_SMEM(128, 128)>>>(
        src, Wq, bq, Wk, bk, Wv, bv, Q, K, V,
        sx, sy, P1, pb1, P2, pb2, S);

    // 2) flash attention: softmax(QK^T/8 + bias) @ V -> O
    flash64_kernel<<<dim3(LL/64, BB*NH), 256, FL64_SMEM_BYTES>>>(S, Q, K, V, O);

    // 3) Xres = src + O @ Wo + bo ; LN1 -> X1
    tgemm<2, 64, 64><<<dim3(DM/64, ROWS/64, 1), 256, TG_SMEM(64, 64)>>>(
        O, DM, Wo, DM, bo, src, Xres, DM, DM,
        nullptr, nullptr, nullptr, nullptr, nullptr, nullptr);
    layernorm_kernel<<<ROWS, 256>>>(Xres, g1, be1, X1);

    // 4) FFN
    tgemm<1, 128, 128><<<dim3(FFD/128, ROWS/128, 1), 256, TG_SMEM(128, 128)>>>(
        X1, DM, W1, FFD, b1, nullptr, H1, FFD, DM,
        nullptr, nullptr, nullptr, nullptr, nullptr, nullptr);
    tgemm<2, 64, 64><<<dim3(DM/64, ROWS/64, 1), 256, TG_SMEM(64, 64)>>>(
        H1, FFD, W2, DM, b2, X1, Xres, DM, FFD,
        nullptr, nullptr, nullptr, nullptr, nullptr, nullptr);

    // 5) LN2 -> output
    layernorm_kernel<<<ROWS, 256>>>(Xres, g2, be2, out);
}

// round 11
// speedup vs baseline: 1.3385x; 1.0171x over previous
#include <cuda_runtime.h>
#include <math.h>

#define BB 2
#define LL 1024
#define DM 768
#define NH 12
#define DKK 64
#define FFD 3072
#define PH 32
#define ROWS (BB*LL)

// ---------------- scratch ----------------
__device__ float g_Q[BB*NH*LL*DKK];
__device__ float g_K[BB*NH*LL*DKK];
__device__ float g_V[BB*NH*LL*DKK];
__device__ float g_S[(size_t)BB*NH*LL*LL];
__device__ float g_O[BB*LL*DM];
__device__ float g_Xres[BB*LL*DM];
__device__ float g_X1[BB*LL*DM];
__device__ float g_H1[BB*LL*FFD];

// ---------------- helpers ----------------
__device__ __forceinline__ unsigned tf32u(float x) {
    unsigned u;
    asm("cvt.rna.tf32.f32 %0, %1;" : "=r"(u) : "f"(x));
    return u;
}
__device__ __forceinline__ float tf32f(float x) { return __uint_as_float(tf32u(x)); }

// mma consumes raw fp32 bits as tf32 (HW truncates low mantissa bits)
__device__ __forceinline__ void mma_tf32(float* c, const unsigned* a, const unsigned* b) {
    asm volatile(
        "mma.sync.aligned.m16n8k8.row.col.f32.tf32.tf32.f32 "
        "{%0,%1,%2,%3}, {%4,%5,%6,%7}, {%8,%9}, {%0,%1,%2,%3};"
        : "+f"(c[0]), "+f"(c[1]), "+f"(c[2]), "+f"(c[3])
        : "r"(a[0]), "r"(a[1]), "r"(a[2]), "r"(a[3]), "r"(b[0]), "r"(b[1]));
}

// one ldmatrix.x4 loads a full tf32 16x8 A-fragment (fp32 bits as b16 pairs)
__device__ __forceinline__ void ldmatrix_x4(unsigned& r0, unsigned& r1,
                                            unsigned& r2, unsigned& r3, unsigned addr) {
    asm volatile("ldmatrix.sync.aligned.m8n8.x4.shared.b16 {%0,%1,%2,%3}, [%4];"
        : "=r"(r0), "=r"(r1), "=r"(r2), "=r"(r3) : "r"(addr));
}

__device__ __forceinline__ unsigned smem_u32(const void* p) {
    return (unsigned)__cvta_generic_to_shared(p);
}

__device__ __forceinline__ void cp16(float* dst_smem, const float* src) {
    unsigned d = (unsigned)__cvta_generic_to_shared(dst_smem);
    asm volatile("cp.async.cg.shared.global [%0], [%1], 16;" :: "r"(d), "l"(src));
}
__device__ __forceinline__ void cp_commit() { asm volatile("cp.async.commit_group;"); }
template<int N> __device__ __forceinline__ void cp_wait() {
    asm volatile("cp.async.wait_group %0;" :: "n"(N));
}

// ---------------- tensor-core GEMM body: BK=32, 3-stage cp.async, ldmatrix A --------
// EPI 1: relu(+bias)  2: +bias +R residual  3: fused QKV scatter
// 8 warps = 2(m) x 4(n). Warp tile (BM/2) x (BN/4).
template<int EPI, int BM, int BN>
__device__ __forceinline__ void tgemm_body(
    int bxi, int byi,
    const float* __restrict__ A, int lda,
    const float* __restrict__ B, int ldb,
    const float* __restrict__ bias,
    const float* __restrict__ Rres,
    float* __restrict__ C, int ldc,
    int K,
    const float* __restrict__ B1, const float* __restrict__ B2,
    const float* __restrict__ bias1, const float* __restrict__ bias2,
    float* __restrict__ C1, float* __restrict__ C2,
    float* dynsm)
{
    constexpr int MI  = BM / 32;
    constexpr int NT  = BN / 32;
    constexpr int WNS = BN / 4;
    constexpr int AP  = 36;
    constexpr int BP  = BN + 8;
    constexpr int ASZ = BM * AP;
    constexpr int BSZ = 32 * BP;
    float* As = dynsm;
    float* Bs = dynsm + 3 * ASZ;

    const int tid = threadIdx.x;
    const int lane = tid & 31, w = tid >> 5;
    const int wm = w & 1, wn = w >> 1;
    const int g = lane >> 2, t4 = lane & 3;
    int bx = bxi;
    const int m0 = byi * BM;

    const float* Ap = A;
    const float* Bp = B; const float* biasp = bias; float* Cp = C;
    if (EPI == 3) {
        int sel = bx / 6; bx -= sel * 6;
        Bp    = sel == 0 ? B    : (sel == 1 ? B1    : B2);
        biasp = sel == 0 ? bias : (sel == 1 ? bias1 : bias2);
        Cp    = sel == 0 ? C    : (sel == 1 ? C1    : C2);
    }
    const int n0 = bx * BN;

    float acc[MI][NT][4];
    #pragma unroll
    for (int i = 0; i < MI; i++)
        #pragma unroll
        for (int j = 0; j < NT; j++)
            #pragma unroll
            for (int q = 0; q < 4; q++) acc[i][j][q] = 0.f;

    auto loadA = [&](int kt, int st) {
        #pragma unroll
        for (int i = 0; i < BM / 32; i++) {
            int idx = tid + i * 256;
            int m = idx >> 3, k4 = (idx & 7) << 2;
            cp16(&As[st * ASZ + m * AP + k4], Ap + (size_t)(m0 + m) * lda + kt + k4);
        }
    };
    auto loadB = [&](int kt, int st) {
        if (BN == 128) {
            #pragma unroll
            for (int i = 0; i < 4; i++) {
                int idx = tid + i * 256;
                int k = idx >> 5, n4 = (idx & 31) << 2;
                cp16(&Bs[st * BSZ + k * BP + n4], Bp + (size_t)(kt + k) * ldb + n0 + n4);
            }
        } else {
            #pragma unroll
            for (int i = 0; i < 2; i++) {
                int idx = tid + i * 256;
                int k = idx >> 4, n4 = (idx & 15) << 2;
                cp16(&Bs[st * BSZ + k * BP + n4], Bp + (size_t)(kt + k) * ldb + n0 + n4);
            }
        }
    };
    // per-thread fixed part of the ldmatrix address (row within 16x8 tile + k-half)
    const int lmRow = lane & 15;            // row 0..15 within tile
    const int lmCol = (lane >> 4) << 2;     // 0 or 4 (k-half)
    auto ldA = [&](int st, int kk, unsigned (&aF)[MI][4]) {
        #pragma unroll
        for (int i = 0; i < MI; i++) {
            int mb0 = wm * (MI * 16) + i * 16;
            unsigned addr = smem_u32(
                &As[st * ASZ + (mb0 + lmRow) * AP + kk * 8 + lmCol]);
            ldmatrix_x4(aF[i][0], aF[i][1], aF[i][2], aF[i][3], addr);
        }
    };
    auto ldB = [&](int st, int kk, unsigned (&bF)[NT][2]) {
        const int kc = kk * 8 + t4;
        #pragma unroll
        for (int j = 0; j < NT; j++) {
            int nb = wn * WNS + j * 8 + g;
            bF[j][0] = __float_as_uint(Bs[st * BSZ + kc * BP + nb]);
            bF[j][1] = __float_as_uint(Bs[st * BSZ + (kc + 4) * BP + nb]);
        }
    };
    auto compute = [&](int st) {
        unsigned aF[MI][4];
        unsigned bF[2][NT][2];
        ldB(st, 0, bF[0]);
        #pragma unroll
        for (int kk = 0; kk < 4; kk++) {
            const int cb = kk & 1;
            ldA(st, kk, aF);
            if (kk < 3) ldB(st, kk + 1, bF[cb ^ 1]);
            #pragma unroll
            for (int i = 0; i < MI; i++)
                #pragma unroll
                for (int j = 0; j < NT; j++)
                    mma_tf32(acc[i][j], aF[i], bF[cb][j]);
        }
    };

    const int nt = K >> 5;
    loadA(0, 0); loadB(0, 0); cp_commit();
    if (nt > 1) { loadA(32, 1); loadB(32, 1); cp_commit(); }
    for (int t = 0; t < nt; t++) {
        if (t + 1 < nt) cp_wait<1>(); else cp_wait<0>();
        __syncthreads();
        compute(t % 3);
        if (t + 2 < nt) {
            int st = (t + 2) % 3;
            loadA((t + 2) << 5, st);
            loadB((t + 2) << 5, st);
            cp_commit();
        }
    }

    auto epi = [&](int row, int col, float2 v) {
        float2 bb = *(const float2*)(biasp + col);
        v.x += bb.x; v.y += bb.y;
        if (EPI == 1) { v.x = fmaxf(v.x, 0.f); v.y = fmaxf(v.y, 0.f); }
        if (EPI == 2) {
            float2 r = *(const float2*)(Rres + (size_t)row * ldc + col);
            v.x += r.x; v.y += r.y;
        }
        if (EPI == 3) {
            int h = col >> 6, d = col & 63;
            float* dst = Cp + ((((size_t)(row >> 10) * NH + h) * LL + (row & 1023)) * DKK + d);
            *(float2*)dst = v;
            return;
        }
        *(float2*)(Cp + (size_t)row * ldc + col) = v;
    };

    #pragma unroll
    for (int i = 0; i < MI; i++) {
        int r0 = m0 + wm * (MI * 16) + i * 16 + g;
        #pragma unroll
        for (int j = 0; j < NT; j++) {
            int col = n0 + wn * WNS + j * 8 + t4 * 2;
            epi(r0,     col, make_float2(acc[i][j][0], acc[i][j][1]));
            epi(r0 + 8, col, make_float2(acc[i][j][2], acc[i][j][3]));
        }
    }
}

#define TG_SMEM(BM, BN) (3 * ((BM) * 36 + 32 * ((BN) + 8)) * 4)

template<int EPI, int BM, int BN>
__global__ __launch_bounds__(256, (BM == 64 && BN == 64) ? 3 : 2) void tgemm(
    const float* __restrict__ A, int lda,
    const float* __restrict__ B, int ldb,
    const float* __restrict__ bias,
    const float* __restrict__ Rres,
    float* __restrict__ C, int ldc,
    int K,
    const float* __restrict__ B1, const float* __restrict__ B2,
    const float* __restrict__ bias1, const float* __restrict__ bias2,
    float* __restrict__ C1, float* __restrict__ C2)
{
    extern __shared__ float dynsm[];
    tgemm_body<EPI, BM, BN>(blockIdx.x, blockIdx.y, A, lda, B, ldb, bias, Rres,
                            C, ldc, K, B1, B2, bias1, bias2, C1, C2, dynsm);
}

// ---------------- posbias body: layer-1 scalar, layer-2 via tf32 mma ----------------
__device__ __forceinline__ void posbias_body(
    int kx, int qy, int b,
    const float* __restrict__ sx, const float* __restrict__ sy,
    const float* __restrict__ P1, const float* __restrict__ pb1,
    const float* __restrict__ P2, const float* __restrict__ pb2,
    float* __restrict__ S, float* dynsm)
{
    constexpr int HSTR = 260;
    constexpr int PSTR = 20;
    float* Hs   = dynsm;
    float* Ps   = Hs + 16 * HSTR * 2;
    float* sP1  = Ps + 16 * PSTR * 2;
    float* sPb1 = sP1 + 64;
    float* sPb2 = sPb1 + 32;
    float* qx   = sPb2 + 16;
    float* qy_  = qx + 16;
    float* kxp  = qy_ + 16;
    float* kyp  = kxp + 16;

    const int q0 = qy * 16, k0 = kx * 16;
    const int tid = threadIdx.x;
    const int lane = tid & 31, w = tid >> 5;
    const int g = lane >> 2, t4 = lane & 3;

    if (tid < 64) sP1[tid] = P1[tid];
    if (tid < 32) sPb1[tid] = pb1[tid];
    if (tid < 16) {
        sPb2[tid] = tid < NH ? pb2[tid] : 0.f;
        qx[tid]  = sx[b*LL + q0 + tid];
        qy_[tid] = sy[b*LL + q0 + tid];
        kxp[tid] = sx[b*LL + k0 + tid];
        kyp[tid] = sy[b*LL + k0 + tid];
    }
    #pragma unroll
    for (int ii = 0; ii < 2; ii++) {
        int v = tid + ii * 256;
        int n = v & 15, k = v >> 4;
        float val = (n < NH) ? P2[k * NH + n] : 0.f;
        int kk = k >> 3, hh = (k >> 2) & 1, cc = k & 3;
        Ps[((kk * 4 + cc) * PSTR + n) * 2 + hh] = val;
    }
    __syncthreads();

    {
        int qq = tid >> 4, kq = tid & 15;
        float rx = fminf(fmaxf(qx[qq] - kxp[kq], -1000.f), 1000.f) * 0.001f;
        float ry = fminf(fmaxf(qy_[qq] - kyp[kq], -1000.f), 1000.f) * 0.001f;
        #pragma unroll
        for (int kk = 0; kk < 4; kk++)
            #pragma unroll
            for (int cc = 0; cc < 4; cc++) {
                int j0 = kk * 8 + cc, j1 = j0 + 4;
                float h0 = fmaxf(fmaf(rx, sP1[j0], fmaf(ry, sP1[32+j0], sPb1[j0])), 0.f);
                float h1 = fmaxf(fmaf(rx, sP1[j1], fmaf(ry, sP1[32+j1], sPb1[j1])), 0.f);
                *(float2*)(&Hs[((kk * 4 + cc) * HSTR + tid) * 2]) = make_float2(h0, h1);
            }
    }
    __syncthreads();

    float acc[2][2][4];
    #pragma unroll
    for (int i = 0; i < 2; i++)
        #pragma unroll
        for (int j = 0; j < 2; j++)
            #pragma unroll
            for (int q = 0; q < 4; q++) acc[i][j][q] = 0.f;

    #pragma unroll
    for (int ks = 0; ks < 4; ks++) {
        unsigned aF[2][4];
        #pragma unroll
        for (int i = 0; i < 2; i++) {
            int mb = (w * 2 + i) * 16 + g;
            float2 lo = *(const float2*)(&Hs[((ks * 4 + t4) * HSTR + mb) * 2]);
            float2 hi = *(const float2*)(&Hs[((ks * 4 + t4) * HSTR + mb + 8) * 2]);
            aF[i][0] = __float_as_uint(lo.x); aF[i][1] = __float_as_uint(hi.x);
            aF[i][2] = __float_as_uint(lo.y); aF[i][3] = __float_as_uint(hi.y);
        }
        unsigned bF[2][2];
        #pragma unroll
        for (int j = 0; j < 2; j++) {
            float2 bb = *(const float2*)(&Ps[((ks * 4 + t4) * PSTR + j * 8 + g) * 2]);
            bF[j][0] = __float_as_uint(bb.x); bF[j][1] = __float_as_uint(bb.y);
        }
        #pragma unroll
        for (int i = 0; i < 2; i++)
            #pragma unroll
            for (int j = 0; j < 2; j++)
                mma_tf32(acc[i][j], aF[i], bF[j]);
    }

    #pragma unroll
    for (int i = 0; i < 2; i++) {
        int p0 = (w * 2 + i) * 16 + g;
        int p1 = p0 + 8;
        int q_0 = q0 + (p0 >> 4), k_0 = k0 + (p0 & 15);
        int q_1 = q0 + (p1 >> 4), k_1 = k0 + (p1 & 15);
        #pragma unroll
        for (int j = 0; j < 2; j++) {
            int c0 = j * 8 + t4 * 2, c1 = c0 + 1;
            if (c0 < NH) {
                S[((size_t)(b*NH + c0) * LL + q_0) * LL + k_0] = acc[i][j][0] + sPb2[c0];
                S[((size_t)(b*NH + c0) * LL + q_1) * LL + k_1] = acc[i][j][2] + sPb2[c0];
            }
            if (c1 < NH) {
                S[((size_t)(b*NH + c1) * LL + q_0) * LL + k_0] = acc[i][j][1] + sPb2[c1];
                S[((size_t)(b*NH + c1) * LL + q_1) * LL + k_1] = acc[i][j][3] + sPb2[c1];
            }
        }
    }
}

// ---------------- fused posbias + QKV (heterogeneous grid) ----------------
#define QKV_BLOCKS 288
#define PBQKV_GRID (QKV_BLOCKS + 64*64*BB)

__global__ __launch_bounds__(256, 2) void pbqkv_kernel(
    const float* __restrict__ src,
    const float* __restrict__ Wq, const float* __restrict__ bq,
    const float* __restrict__ Wk, const float* __restrict__ bk,
    const float* __restrict__ Wv, const float* __restrict__ bv,
    float* __restrict__ Q, float* __restrict__ Kq, float* __restrict__ V,
    const float* __restrict__ sx, const float* __restrict__ sy,
    const float* __restrict__ P1, const float* __restrict__ pb1,
    const float* __restrict__ P2, const float* __restrict__ pb2,
    float* __restrict__ S)
{
    extern __shared__ float dynsm[];
    const int bid = blockIdx.x;
    if (bid < QKV_BLOCKS) {
        tgemm_body<3, 128, 128>(bid % 18, bid / 18,
            src, DM, Wq, DM, bq, nullptr, Q, 0, DM,
            Wk, Wv, bk, bv, Kq, V, dynsm);
    } else {
        int p = bid - QKV_BLOCKS;
        posbias_body(p & 63, (p >> 6) & 63, p >> 12,
                     sx, sy, P1, pb1, P2, pb2, S, dynsm);
    }
}

// ---------------- flash64: QK^T + bias + online softmax + PV -----------------
#define FQSTR 68
struct Flash64Smem {
    float Qs[32*FQSTR*2];
    float Ss[32*FQSTR*2];
    float Ks[64*FQSTR];
    float Vs[64*FQSTR];
    float rowScale[64];
    float rowInv[64];
};
#define FL64_SMEM_BYTES sizeof(Flash64Smem)

__global__ __launch_bounds__(256, 3) void flash64_kernel(
    const float* __restrict__ S, const float* __restrict__ Q,
    const float* __restrict__ K, const float* __restrict__ V,
    float* __restrict__ O)
{
    extern __shared__ char smraw[];
    Flash64Smem& sm = *reinterpret_cast<Flash64Smem*>(smraw);

    const int tid = threadIdx.x;
    const int lane = tid & 31, w = tid >> 5;
    const int wm = w & 1, wn = w >> 1;
    const int g = lane >> 2, t4 = lane & 3;
    const int bh = blockIdx.y, b = bh / NH, h = bh % NH;
    const int q0 = blockIdx.x * 64;

    const float* Qp = Q + ((size_t)bh * LL + q0) * DKK;
    const float* Kp = K + (size_t)bh * LL * DKK;
    const float* Vp = V + (size_t)bh * LL * DKK;
    const float* Sb = S + ((size_t)bh * LL + q0) * LL;

    auto loadK = [&](int t) {
        #pragma unroll
        for (int i = 0; i < 4; i++) {
            int idx = tid + i * 256;
            int r = idx >> 4, d4 = (idx & 15) << 2;
            cp16(&sm.Ks[r * FQSTR + d4], Kp + (size_t)(t * 64 + r) * DKK + d4);
        }
        cp_commit();
    };
    auto loadV = [&](int t) {
        #pragma unroll
        for (int i = 0; i < 4; i++) {
            int idx = tid + i * 256;
            int r = idx >> 4, d4 = (idx & 15) << 2;
            cp16(&sm.Vs[r * FQSTR + d4], Vp + (size_t)(t * 64 + r) * DKK + d4);
        }
        cp_commit();
    };

    loadK(0);
    loadV(0);

    #pragma unroll
    for (int i = 0; i < 4; i++) {
        int idx = tid + i * 256;
        int r = idx >> 4, d4 = (idx & 15) << 2;
        float4 v = *(const float4*)(Qp + (size_t)r * DKK + d4);
        int kk = d4 >> 3, hh = (d4 >> 2) & 1;
        float* p = sm.Qs + ((kk * 4) * FQSTR + r) * 2 + hh;
        p[0]          = tf32f(v.x * 0.125f);
        p[FQSTR*2]    = tf32f(v.y * 0.125f);
        p[FQSTR*4]    = tf32f(v.z * 0.125f);
        p[FQSTR*6]    = tf32f(v.w * 0.125f);
    }

    float accO[2][2][4];
    #pragma unroll
    for (int i = 0; i < 2; i++)
        #pragma unroll
        for (int j = 0; j < 2; j++)
            #pragma unroll
            for (int q = 0; q < 4; q++) accO[i][j][q] = 0.f;

    float rowM = -1e30f, rowL = 0.f;
    const int myrow = tid >> 2, quarter = tid & 3;

    for (int t = 0; t < 16; t++) {
        float accS[2][2][4];
        const int kb = t * 64;
        #pragma unroll
        for (int i = 0; i < 2; i++) {
            int r = wm * 32 + i * 16 + g;
            #pragma unroll
            for (int j = 0; j < 2; j++) {
                int col = kb + wn * 16 + j * 8 + t4 * 2;
                float2 b0 = *(const float2*)(Sb + (size_t)r * LL + col);
                float2 b1 = *(const float2*)(Sb + (size_t)(r + 8) * LL + col);
                accS[i][j][0] = b0.x; accS[i][j][1] = b0.y;
                accS[i][j][2] = b1.x; accS[i][j][3] = b1.y;
            }
        }

        cp_wait<1>();
        __syncthreads();

        #pragma unroll
        for (int ks = 0; ks < 8; ks++) {
            const int kc = ks * 8 + t4;
            unsigned aF[2][4];
            #pragma unroll
            for (int i = 0; i < 2; i++) {
                int mb = wm * 32 + i * 16 + g;
                float2 lo = *(const float2*)(sm.Qs + ((ks * 4 + t4) * FQSTR + mb) * 2);
                float2 hi = *(const float2*)(sm.Qs + ((ks * 4 + t4) * FQSTR + mb + 8) * 2);
                aF[i][0] = __float_as_uint(lo.x); aF[i][1] = __float_as_uint(hi.x);
                aF[i][2] = __float_as_uint(lo.y); aF[i][3] = __float_as_uint(hi.y);
            }
            unsigned bF[2][2];
            #pragma unroll
            for (int j = 0; j < 2; j++) {
                int nb = wn * 16 + j * 8 + g;
                bF[j][0] = __float_as_uint(sm.Ks[nb * FQSTR + kc]);
                bF[j][1] = __float_as_uint(sm.Ks[nb * FQSTR + kc + 4]);
            }
            #pragma unroll
            for (int i = 0; i < 2; i++)
                #pragma unroll
                for (int j = 0; j < 2; j++)
                    mma_tf32(accS[i][j], aF[i], bF[j]);
        }

        {
            const int cc = (t4 & 1) * 2, hh = t4 >> 1;
            #pragma unroll
            for (int i = 0; i < 2; i++) {
                int r = wm * 32 + i * 16 + g;
                #pragma unroll
                for (int j = 0; j < 2; j++) {
                    int colk = (wn * 16 + j * 8 + t4 * 2) >> 3;
                    int e = (colk * 4 + cc) * FQSTR + r;
                    sm.Ss[e * 2 + hh]                 = accS[i][j][0];
                    sm.Ss[(e + FQSTR) * 2 + hh]       = accS[i][j][1];
                    sm.Ss[(e + 8) * 2 + hh]           = accS[i][j][2];
                    sm.Ss[(e + FQSTR + 8) * 2 + hh]   = accS[i][j][3];
                }
            }
        }
        __syncthreads();
        if (t + 1 < 16) loadK(t + 1);

        {
            float2 vals[8];
            float mx = -1e30f;
            #pragma unroll
            for (int e = 0; e < 8; e++) {
                int kk = 2 * quarter + (e >> 2), cc2 = e & 3;
                vals[e] = *(const float2*)(sm.Ss + ((kk * 4 + cc2) * FQSTR + myrow) * 2);
                mx = fmaxf(mx, fmaxf(vals[e].x, vals[e].y));
            }
            mx = fmaxf(mx, __shfl_xor_sync(0xffffffffu, mx, 1));
            mx = fmaxf(mx, __shfl_xor_sync(0xffffffffu, mx, 2));
            float mNew = fmaxf(rowM, mx);
            float scale = __expf(rowM - mNew);
            float sum = 0.f;
            #pragma unroll
            for (int e = 0; e < 8; e++) {
                vals[e].x = __expf(vals[e].x - mNew);
                vals[e].y = __expf(vals[e].y - mNew);
                sum += vals[e].x + vals[e].y;
                int kk = 2 * quarter + (e >> 2), cc2 = e & 3;
                *(float2*)(sm.Ss + ((kk * 4 + cc2) * FQSTR + myrow) * 2) =
                    make_float2(vals[e].x, vals[e].y);
            }
            sum += __shfl_xor_sync(0xffffffffu, sum, 1);
            sum += __shfl_xor_sync(0xffffffffu, sum, 2);
            rowL = rowL * scale + sum;
            rowM = mNew;
            if (quarter == 0) sm.rowScale[myrow] = scale;
        }
        if (t + 1 < 16) cp_wait<1>(); else cp_wait<0>();
        __syncthreads();

        #pragma unroll
        for (int i = 0; i < 2; i++) {
            int r = wm * 32 + i * 16 + g;
            float s0 = sm.rowScale[r], s1 = sm.rowScale[r + 8];
            #pragma unroll
            for (int j = 0; j < 2; j++) {
                accO[i][j][0] *= s0; accO[i][j][1] *= s0;
                accO[i][j][2] *= s1; accO[i][j][3] *= s1;
            }
        }

        #pragma unroll
        for (int ks = 0; ks < 8; ks++) {
            const int kc = ks * 8 + t4;
            unsigned aF[2][4];
            #pragma unroll
            for (int i = 0; i < 2; i++) {
                int mb = wm * 32 + i * 16 + g;
                float2 lo = *(const float2*)(sm.Ss + ((ks * 4 + t4) * FQSTR + mb) * 2);
                float2 hi = *(const float2*)(sm.Ss + ((ks * 4 + t4) * FQSTR + mb + 8) * 2);
                aF[i][0] = __float_as_uint(lo.x); aF[i][1] = __float_as_uint(hi.x);
                aF[i][2] = __float_as_uint(lo.y); aF[i][3] = __float_as_uint(hi.y);
            }
            unsigned bF[2][2];
            #pragma unroll
            for (int j = 0; j < 2; j++) {
                int nb = wn * 16 + j * 8 + g;
                bF[j][0] = __float_as_uint(sm.Vs[kc * FQSTR + nb]);
                bF[j][1] = __float_as_uint(sm.Vs[(kc + 4) * FQSTR + nb]);
            }
            #pragma unroll
            for (int i = 0; i < 2; i++)
                #pragma unroll
                for (int j = 0; j < 2; j++)
                    mma_tf32(accO[i][j], aF[i], bF[j]);
        }
        __syncthreads();
        if (t + 1 < 16) loadV(t + 1);
    }

    if (quarter == 0) sm.rowInv[myrow] = 1.f / rowL;
    __syncthreads();

    float* Op = O + ((size_t)b * LL + q0) * DM + h * DKK;
    #pragma unroll
    for (int i = 0; i < 2; i++) {
        int r = wm * 32 + i * 16 + g;
        float i0 = sm.rowInv[r], i1 = sm.rowInv[r + 8];
        #pragma unroll
        for (int j = 0; j < 2; j++) {
            int col = wn * 16 + j * 8 + t4 * 2;
            *(float2*)(Op + (size_t)r * DM + col) =
                make_float2(accO[i][j][0] * i0, accO[i][j][1] * i0);
            *(float2*)(Op + (size_t)(r + 8) * DM + col) =
                make_float2(accO[i][j][2] * i1, accO[i][j][3] * i1);
        }
    }
}

// ---------------- layernorm over last dim (768) ----------------
__global__ __launch_bounds__(256) void layernorm_kernel(
    const float* __restrict__ X, const float* __restrict__ g, const float* __restrict__ be,
    float* __restrict__ Y)
{
    __shared__ float red[256];
    const size_t row = blockIdx.x;
    const float* p = X + row * DM;
    float* o = Y + row * DM;
    const int tid = threadIdx.x;
    float v[3];
    float s = 0.f;
    #pragma unroll
    for (int i = 0; i < 3; i++) { v[i] = p[tid + i*256]; s += v[i]; }
    red[tid] = s; __syncthreads();
    for (int st = 128; st > 0; st >>= 1) { if (tid < st) red[tid] += red[tid+st]; __syncthreads(); }
    float mean = red[0] * (1.f/DM); __syncthreads();
    float sq = 0.f;
    #pragma unroll
    for (int i = 0; i < 3; i++) { float d = v[i] - mean; sq += d*d; }
    red[tid] = sq; __syncthreads();
    for (int st = 128; st > 0; st >>= 1) { if (tid < st) red[tid] += red[tid+st]; __syncthreads(); }
    float rstd = rsqrtf(red[0] * (1.f/DM) + 1e-5f);
    #pragma unroll
    for (int i = 0; i < 3; i++) {
        int c = tid + i*256;
        o[c] = (v[i] - mean) * rstd * g[c] + be[c];
    }
}

// ---------------- launch ----------------
extern "C" void kernel_launch(void* const* d_in, const int* in_sizes, int n_in,
                              void* d_out, int out_size)
{
    const float* src = (const float*)d_in[0];
    const float* sx  = (const float*)d_in[1];
    const float* sy  = (const float*)d_in[2];
    const float* Wq  = (const float*)d_in[3];  const float* bq  = (const float*)d_in[4];
    const float* Wk  = (const float*)d_in[5];  const float* bk  = (const float*)d_in[6];
    const float* Wv  = (const float*)d_in[7];  const float* bv  = (const float*)d_in[8];
    const float* Wo  = (const float*)d_in[9];  const float* bo  = (const float*)d_in[10];
    const float* P1  = (const float*)d_in[11]; const float* pb1 = (const float*)d_in[12];
    const float* P2  = (const float*)d_in[13]; const float* pb2 = (const float*)d_in[14];
    const float* W1  = (const float*)d_in[15]; const float* b1  = (const float*)d_in[16];
    const float* W2  = (const float*)d_in[17]; const float* b2  = (const float*)d_in[18];
    const float* g1  = (const float*)d_in[19]; const float* be1 = (const float*)d_in[20];
    const float* g2  = (const float*)d_in[21]; const float* be2 = (const float*)d_in[22];
    float* out = (float*)d_out;

    float *Q, *K, *V, *S, *O, *Xres, *X1, *H1;
    cudaGetSymbolAddress((void**)&Q,    g_Q);
    cudaGetSymbolAddress((void**)&K,    g_K);
    cudaGetSymbolAddress((void**)&V,    g_V);
    cudaGetSymbolAddress((void**)&S,    g_S);
    cudaGetSymbolAddress((void**)&O,    g_O);
    cudaGetSymbolAddress((void**)&Xres, g_Xres);
    cudaGetSymbolAddress((void**)&X1,   g_X1);
    cudaGetSymbolAddress((void**)&H1,   g_H1);

    cudaFuncSetAttribute(flash64_kernel, cudaFuncAttributeMaxDynamicSharedMemorySize,
                         (int)FL64_SMEM_BYTES);
    cudaFuncSetAttribute(pbqkv_kernel, cudaFuncAttributeMaxDynamicSharedMemorySize,
                         TG_SMEM(128, 128));
    cudaFuncSetAttribute(tgemm<1, 128, 128>, cudaFuncAttributeMaxDynamicSharedMemorySize,
                         TG_SMEM(128, 128));
    cudaFuncSetAttribute(tgemm<2, 64, 64>, cudaFuncAttributeMaxDynamicSharedMemorySize,
                         TG_SMEM(64, 64));

    // 1) fused: relative-position bias -> S  ||  QKV projections -> Q,K,V
    pbqkv_kernel<<<PBQKV_GRID, 256, TG_SMEM(128, 128)>>>(
        src, Wq, bq, Wk, bk, Wv, bv, Q, K, V,
        sx, sy, P1, pb1, P2, pb2, S);

    // 2) flash attention: softmax(QK^T/8 + bias) @ V -> O
    flash64_kernel<<<dim3(LL/64, BB*NH), 256, FL64_SMEM_BYTES>>>(S, Q, K, V, O);

    // 3) Xres = src + O @ Wo + bo ; LN1 -> X1
    tgemm<2, 64, 64><<<dim3(DM/64, ROWS/64, 1), 256, TG_SMEM(64, 64)>>>(
        O, DM, Wo, DM, bo, src, Xres, DM, DM,
        nullptr, nullptr, nullptr, nullptr, nullptr, nullptr);
    layernorm_kernel<<<ROWS, 256>>>(Xres, g1, be1, X1);

    // 4) FFN
    tgemm<1, 128, 128><<<dim3(FFD/128, ROWS/128, 1), 256, TG_SMEM(128, 128)>>>(
        X1, DM, W1, FFD, b1, nullptr, H1, FFD, DM,
        nullptr, nullptr, nullptr, nullptr, nullptr, nullptr);
    tgemm<2, 64, 64><<<dim3(DM/64, ROWS/64, 1), 256, TG_SMEM(64, 64)>>>(
        H1, FFD, W2, DM, b2, X1, Xres, DM, FFD,
        nullptr, nullptr, nullptr, nullptr, nullptr, nullptr);

    // 5) LN2 -> output
    layernorm_kernel<<<ROWS, 256>>>(Xres, g2, be2, out);
}

// round 13
// speedup vs baseline: 1.3451x; 1.0050x over previous
#include <cuda_runtime.h>
#include <math.h>

#define BB 2
#define LL 1024
#define DM 768
#define NH 12
#define DKK 64
#define FFD 3072
#define PH 32
#define ROWS (BB*LL)

// ---------------- scratch ----------------
__device__ float g_Q[BB*NH*LL*DKK];
__device__ float g_K[BB*NH*LL*DKK];
__device__ float g_V[BB*NH*LL*DKK];
__device__ float g_S[(size_t)BB*NH*LL*LL];
__device__ float g_O[BB*LL*DM];
__device__ float g_Xres[BB*LL*DM];
__device__ float g_X1[BB*LL*DM];
__device__ float g_H1[BB*LL*FFD];

// ---------------- helpers ----------------
__device__ __forceinline__ unsigned tf32u(float x) {
    unsigned u;
    asm("cvt.rna.tf32.f32 %0, %1;" : "=r"(u) : "f"(x));
    return u;
}
__device__ __forceinline__ float tf32f(float x) { return __uint_as_float(tf32u(x)); }

// mma consumes raw fp32 bits as tf32 (HW truncates low mantissa bits)
__device__ __forceinline__ void mma_tf32(float* c, const unsigned* a, const unsigned* b) {
    asm volatile(
        "mma.sync.aligned.m16n8k8.row.col.f32.tf32.tf32.f32 "
        "{%0,%1,%2,%3}, {%4,%5,%6,%7}, {%8,%9}, {%0,%1,%2,%3};"
        : "+f"(c[0]), "+f"(c[1]), "+f"(c[2]), "+f"(c[3])
        : "r"(a[0]), "r"(a[1]), "r"(a[2]), "r"(a[3]), "r"(b[0]), "r"(b[1]));
}

__device__ __forceinline__ void ldmatrix_x4(unsigned& r0, unsigned& r1,
                                            unsigned& r2, unsigned& r3, unsigned addr) {
    asm volatile("ldmatrix.sync.aligned.m8n8.x4.shared.b16 {%0,%1,%2,%3}, [%4];"
        : "=r"(r0), "=r"(r1), "=r"(r2), "=r"(r3) : "r"(addr));
}

__device__ __forceinline__ unsigned smem_u32(const void* p) {
    return (unsigned)__cvta_generic_to_shared(p);
}

__device__ __forceinline__ void cp16(float* dst_smem, const float* src) {
    unsigned d = (unsigned)__cvta_generic_to_shared(dst_smem);
    asm volatile("cp.async.cg.shared.global [%0], [%1], 16;" :: "r"(d), "l"(src));
}
__device__ __forceinline__ void cp_commit() { asm volatile("cp.async.commit_group;"); }
template<int N> __device__ __forceinline__ void cp_wait() {
    asm volatile("cp.async.wait_group %0;" :: "n"(N));
}

// ---------------- tensor-core GEMM body: BK=32, multi-stage cp.async, ldmatrix A ----
// EPI 1: relu(+bias)  2: +bias +R residual  3: fused QKV scatter
// 8 warps = 2(m) x 4(n). Warp tile (BM/2) x (BN/4).
// (64,64) config uses a 4-stage pipeline (3 tiles in flight); others 3-stage.
template<int EPI, int BM, int BN>
__device__ __forceinline__ void tgemm_body(
    int bxi, int byi,
    const float* __restrict__ A, int lda,
    const float* __restrict__ B, int ldb,
    const float* __restrict__ bias,
    const float* __restrict__ Rres,
    float* __restrict__ C, int ldc,
    int K,
    const float* __restrict__ B1, const float* __restrict__ B2,
    const float* __restrict__ bias1, const float* __restrict__ bias2,
    float* __restrict__ C1, float* __restrict__ C2,
    float* dynsm)
{
    constexpr int MI  = BM / 32;
    constexpr int NT  = BN / 32;
    constexpr int WNS = BN / 4;
    constexpr int ST  = (BM == 64 && BN == 64) ? 4 : 3;
    constexpr int AP  = 36;
    constexpr int BP  = BN + 8;
    constexpr int ASZ = BM * AP;
    constexpr int BSZ = 32 * BP;
    float* As = dynsm;
    float* Bs = dynsm + ST * ASZ;

    const int tid = threadIdx.x;
    const int lane = tid & 31, w = tid >> 5;
    const int wm = w & 1, wn = w >> 1;
    const int g = lane >> 2, t4 = lane & 3;
    int bx = bxi;
    const int m0 = byi * BM;

    const float* Ap = A;
    const float* Bp = B; const float* biasp = bias; float* Cp = C;
    if (EPI == 3) {
        int sel = bx / 6; bx -= sel * 6;
        Bp    = sel == 0 ? B    : (sel == 1 ? B1    : B2);
        biasp = sel == 0 ? bias : (sel == 1 ? bias1 : bias2);
        Cp    = sel == 0 ? C    : (sel == 1 ? C1    : C2);
    }
    const int n0 = bx * BN;

    float acc[MI][NT][4];
    #pragma unroll
    for (int i = 0; i < MI; i++)
        #pragma unroll
        for (int j = 0; j < NT; j++)
            #pragma unroll
            for (int q = 0; q < 4; q++) acc[i][j][q] = 0.f;

    auto loadA = [&](int kt, int st) {
        #pragma unroll
        for (int i = 0; i < BM / 32; i++) {
            int idx = tid + i * 256;
            int m = idx >> 3, k4 = (idx & 7) << 2;
            cp16(&As[st * ASZ + m * AP + k4], Ap + (size_t)(m0 + m) * lda + kt + k4);
        }
    };
    auto loadB = [&](int kt, int st) {
        if (BN == 128) {
            #pragma unroll
            for (int i = 0; i < 4; i++) {
                int idx = tid + i * 256;
                int k = idx >> 5, n4 = (idx & 31) << 2;
                cp16(&Bs[st * BSZ + k * BP + n4], Bp + (size_t)(kt + k) * ldb + n0 + n4);
            }
        } else {
            #pragma unroll
            for (int i = 0; i < 2; i++) {
                int idx = tid + i * 256;
                int k = idx >> 4, n4 = (idx & 15) << 2;
                cp16(&Bs[st * BSZ + k * BP + n4], Bp + (size_t)(kt + k) * ldb + n0 + n4);
            }
        }
    };
    const int lmRow = lane & 15;
    const int lmCol = (lane >> 4) << 2;
    auto ldA = [&](int st, int kk, unsigned (&aF)[MI][4]) {
        #pragma unroll
        for (int i = 0; i < MI; i++) {
            int mb0 = wm * (MI * 16) + i * 16;
            unsigned addr = smem_u32(
                &As[st * ASZ + (mb0 + lmRow) * AP + kk * 8 + lmCol]);
            ldmatrix_x4(aF[i][0], aF[i][1], aF[i][2], aF[i][3], addr);
        }
    };
    auto ldB = [&](int st, int kk, unsigned (&bF)[NT][2]) {
        const int kc = kk * 8 + t4;
        #pragma unroll
        for (int j = 0; j < NT; j++) {
            int nb = wn * WNS + j * 8 + g;
            bF[j][0] = __float_as_uint(Bs[st * BSZ + kc * BP + nb]);
            bF[j][1] = __float_as_uint(Bs[st * BSZ + (kc + 4) * BP + nb]);
        }
    };
    auto compute = [&](int st) {
        unsigned aF[MI][4];
        unsigned bF[2][NT][2];
        ldB(st, 0, bF[0]);
        #pragma unroll
        for (int kk = 0; kk < 4; kk++) {
            const int cb = kk & 1;
            ldA(st, kk, aF);
            if (kk < 3) ldB(st, kk + 1, bF[cb ^ 1]);
            #pragma unroll
            for (int i = 0; i < MI; i++)
                #pragma unroll
                for (int j = 0; j < NT; j++)
                    mma_tf32(acc[i][j], aF[i], bF[cb][j]);
        }
    };

    const int nt = K >> 5;
    loadA(0, 0); loadB(0, 0); cp_commit();
    if (nt > 1) { loadA(32, 1); loadB(32, 1); cp_commit(); }
    if (ST == 4 && nt > 2) { loadA(64, 2); loadB(64, 2); cp_commit(); }
    for (int t = 0; t < nt; t++) {
        if (t + ST - 1 < nt)                 cp_wait<ST - 2>();
        else if (ST == 4 && t + 2 < nt)      cp_wait<1>();
        else                                 cp_wait<0>();
        __syncthreads();
        compute(t % ST);
        if (t + ST - 1 < nt) {
            int st = (t + ST - 1) % ST;
            loadA((t + ST - 1) << 5, st);
            loadB((t + ST - 1) << 5, st);
            cp_commit();
        }
    }

    auto epi = [&](int row, int col, float2 v) {
        float2 bb = *(const float2*)(biasp + col);
        v.x += bb.x; v.y += bb.y;
        if (EPI == 1) { v.x = fmaxf(v.x, 0.f); v.y = fmaxf(v.y, 0.f); }
        if (EPI == 2) {
            float2 r = *(const float2*)(Rres + (size_t)row * ldc + col);
            v.x += r.x; v.y += r.y;
        }
        if (EPI == 3) {
            int h = col >> 6, d = col & 63;
            float* dst = Cp + ((((size_t)(row >> 10) * NH + h) * LL + (row & 1023)) * DKK + d);
            *(float2*)dst = v;
            return;
        }
        *(float2*)(Cp + (size_t)row * ldc + col) = v;
    };

    #pragma unroll
    for (int i = 0; i < MI; i++) {
        int r0 = m0 + wm * (MI * 16) + i * 16 + g;
        #pragma unroll
        for (int j = 0; j < NT; j++) {
            int col = n0 + wn * WNS + j * 8 + t4 * 2;
            epi(r0,     col, make_float2(acc[i][j][0], acc[i][j][1]));
            epi(r0 + 8, col, make_float2(acc[i][j][2], acc[i][j][3]));
        }
    }
}

#define TG_SMEM(BM, BN) ((((BM) == 64 && (BN) == 64) ? 4 : 3) * ((BM) * 36 + 32 * ((BN) + 8)) * 4)

template<int EPI, int BM, int BN>
__global__ __launch_bounds__(256, (BM == 64 && BN == 64) ? 3 : 2) void tgemm(
    const float* __restrict__ A, int lda,
    const float* __restrict__ B, int ldb,
    const float* __restrict__ bias,
    const float* __restrict__ Rres,
    float* __restrict__ C, int ldc,
    int K,
    const float* __restrict__ B1, const float* __restrict__ B2,
    const float* __restrict__ bias1, const float* __restrict__ bias2,
    float* __restrict__ C1, float* __restrict__ C2)
{
    extern __shared__ float dynsm[];
    tgemm_body<EPI, BM, BN>(blockIdx.x, blockIdx.y, A, lda, B, ldb, bias, Rres,
                            C, ldc, K, B1, B2, bias1, bias2, C1, C2, dynsm);
}

// ---------------- posbias body: layer-1 scalar, layer-2 via tf32 mma ----------------
__device__ __forceinline__ void posbias_body(
    int kx, int qy, int b,
    const float* __restrict__ sx, const float* __restrict__ sy,
    const float* __restrict__ P1, const float* __restrict__ pb1,
    const float* __restrict__ P2, const float* __restrict__ pb2,
    float* __restrict__ S, float* dynsm)
{
    constexpr int HSTR = 260;
    constexpr int PSTR = 20;
    float* Hs   = dynsm;
    float* Ps   = Hs + 16 * HSTR * 2;
    float* sP1  = Ps + 16 * PSTR * 2;
    float* sPb1 = sP1 + 64;
    float* sPb2 = sPb1 + 32;
    float* qx   = sPb2 + 16;
    float* qy_  = qx + 16;
    float* kxp  = qy_ + 16;
    float* kyp  = kxp + 16;

    const int q0 = qy * 16, k0 = kx * 16;
    const int tid = threadIdx.x;
    const int lane = tid & 31, w = tid >> 5;
    const int g = lane >> 2, t4 = lane & 3;

    if (tid < 64) sP1[tid] = P1[tid];
    if (tid < 32) sPb1[tid] = pb1[tid];
    if (tid < 16) {
        sPb2[tid] = tid < NH ? pb2[tid] : 0.f;
        qx[tid]  = sx[b*LL + q0 + tid];
        qy_[tid] = sy[b*LL + q0 + tid];
        kxp[tid] = sx[b*LL + k0 + tid];
        kyp[tid] = sy[b*LL + k0 + tid];
    }
    #pragma unroll
    for (int ii = 0; ii < 2; ii++) {
        int v = tid + ii * 256;
        int n = v & 15, k = v >> 4;
        float val = (n < NH) ? P2[k * NH + n] : 0.f;
        int kk = k >> 3, hh = (k >> 2) & 1, cc = k & 3;
        Ps[((kk * 4 + cc) * PSTR + n) * 2 + hh] = val;
    }
    __syncthreads();

    {
        int qq = tid >> 4, kq = tid & 15;
        float rx = fminf(fmaxf(qx[qq] - kxp[kq], -1000.f), 1000.f) * 0.001f;
        float ry = fminf(fmaxf(qy_[qq] - kyp[kq], -1000.f), 1000.f) * 0.001f;
        #pragma unroll
        for (int kk = 0; kk < 4; kk++)
            #pragma unroll
            for (int cc = 0; cc < 4; cc++) {
                int j0 = kk * 8 + cc, j1 = j0 + 4;
                float h0 = fmaxf(fmaf(rx, sP1[j0], fmaf(ry, sP1[32+j0], sPb1[j0])), 0.f);
                float h1 = fmaxf(fmaf(rx, sP1[j1], fmaf(ry, sP1[32+j1], sPb1[j1])), 0.f);
                *(float2*)(&Hs[((kk * 4 + cc) * HSTR + tid) * 2]) = make_float2(h0, h1);
            }
    }
    __syncthreads();

    float acc[2][2][4];
    #pragma unroll
    for (int i = 0; i < 2; i++)
        #pragma unroll
        for (int j = 0; j < 2; j++)
            #pragma unroll
            for (int q = 0; q < 4; q++) acc[i][j][q] = 0.f;

    #pragma unroll
    for (int ks = 0; ks < 4; ks++) {
        unsigned aF[2][4];
        #pragma unroll
        for (int i = 0; i < 2; i++) {
            int mb = (w * 2 + i) * 16 + g;
            float2 lo = *(const float2*)(&Hs[((ks * 4 + t4) * HSTR + mb) * 2]);
            float2 hi = *(const float2*)(&Hs[((ks * 4 + t4) * HSTR + mb + 8) * 2]);
            aF[i][0] = __float_as_uint(lo.x); aF[i][1] = __float_as_uint(hi.x);
            aF[i][2] = __float_as_uint(lo.y); aF[i][3] = __float_as_uint(hi.y);
        }
        unsigned bF[2][2];
        #pragma unroll
        for (int j = 0; j < 2; j++) {
            float2 bb = *(const float2*)(&Ps[((ks * 4 + t4) * PSTR + j * 8 + g) * 2]);
            bF[j][0] = __float_as_uint(bb.x); bF[j][1] = __float_as_uint(bb.y);
        }
        #pragma unroll
        for (int i = 0; i < 2; i++)
            #pragma unroll
            for (int j = 0; j < 2; j++)
                mma_tf32(acc[i][j], aF[i], bF[j]);
    }

    #pragma unroll
    for (int i = 0; i < 2; i++) {
        int p0 = (w * 2 + i) * 16 + g;
        int p1 = p0 + 8;
        int q_0 = q0 + (p0 >> 4), k_0 = k0 + (p0 & 15);
        int q_1 = q0 + (p1 >> 4), k_1 = k0 + (p1 & 15);
        #pragma unroll
        for (int j = 0; j < 2; j++) {
            int c0 = j * 8 + t4 * 2, c1 = c0 + 1;
            if (c0 < NH) {
                S[((size_t)(b*NH + c0) * LL + q_0) * LL + k_0] = acc[i][j][0] + sPb2[c0];
                S[((size_t)(b*NH + c0) * LL + q_1) * LL + k_1] = acc[i][j][2] + sPb2[c0];
            }
            if (c1 < NH) {
                S[((size_t)(b*NH + c1) * LL + q_0) * LL + k_0] = acc[i][j][1] + sPb2[c1];
                S[((size_t)(b*NH + c1) * LL + q_1) * LL + k_1] = acc[i][j][3] + sPb2[c1];
            }
        }
    }
}

// ---------------- fused posbias + QKV (heterogeneous grid) ----------------
#define QKV_BLOCKS 288
#define PBQKV_GRID (QKV_BLOCKS + 64*64*BB)

__global__ __launch_bounds__(256, 2) void pbqkv_kernel(
    const float* __restrict__ src,
    const float* __restrict__ Wq, const float* __restrict__ bq,
    const float* __restrict__ Wk, const float* __restrict__ bk,
    const float* __restrict__ Wv, const float* __restrict__ bv,
    float* __restrict__ Q, float* __restrict__ Kq, float* __restrict__ V,
    const float* __restrict__ sx, const float* __restrict__ sy,
    const float* __restrict__ P1, const float* __restrict__ pb1,
    const float* __restrict__ P2, const float* __restrict__ pb2,
    float* __restrict__ S)
{
    extern __shared__ float dynsm[];
    const int bid = blockIdx.x;
    if (bid < QKV_BLOCKS) {
        tgemm_body<3, 128, 128>(bid % 18, bid / 18,
            src, DM, Wq, DM, bq, nullptr, Q, 0, DM,
            Wk, Wv, bk, bv, Kq, V, dynsm);
    } else {
        int p = bid - QKV_BLOCKS;
        posbias_body(p & 63, (p >> 6) & 63, p >> 12,
                     sx, sy, P1, pb1, P2, pb2, S, dynsm);
    }
}

// ---------------- flash64: QK^T + bias + online softmax + PV -----------------
#define FQSTR 68
struct Flash64Smem {
    float Qs[32*FQSTR*2];
    float Ss[32*FQSTR*2];
    float Ks[64*FQSTR];
    float Vs[64*FQSTR];
    float rowScale[64];
    float rowInv[64];
};
#define FL64_SMEM_BYTES sizeof(Flash64Smem)

__global__ __launch_bounds__(256, 3) void flash64_kernel(
    const float* __restrict__ S, const float* __restrict__ Q,
    const float* __restrict__ K, const float* __restrict__ V,
    float* __restrict__ O)
{
    extern __shared__ char smraw[];
    Flash64Smem& sm = *reinterpret_cast<Flash64Smem*>(smraw);

    const int tid = threadIdx.x;
    const int lane = tid & 31, w = tid >> 5;
    const int wm = w & 1, wn = w >> 1;
    const int g = lane >> 2, t4 = lane & 3;
    const int bh = blockIdx.y, b = bh / NH, h = bh % NH;
    const int q0 = blockIdx.x * 64;

    const float* Qp = Q + ((size_t)bh * LL + q0) * DKK;
    const float* Kp = K + (size_t)bh * LL * DKK;
    const float* Vp = V + (size_t)bh * LL * DKK;
    const float* Sb = S + ((size_t)bh * LL + q0) * LL;

    auto loadK = [&](int t) {
        #pragma unroll
        for (int i = 0; i < 4; i++) {
            int idx = tid + i * 256;
            int r = idx >> 4, d4 = (idx & 15) << 2;
            cp16(&sm.Ks[r * FQSTR + d4], Kp + (size_t)(t * 64 + r) * DKK + d4);
        }
        cp_commit();
    };
    auto loadV = [&](int t) {
        #pragma unroll
        for (int i = 0; i < 4; i++) {
            int idx = tid + i * 256;
            int r = idx >> 4, d4 = (idx & 15) << 2;
            cp16(&sm.Vs[r * FQSTR + d4], Vp + (size_t)(t * 64 + r) * DKK + d4);
        }
        cp_commit();
    };

    loadK(0);
    loadV(0);

    #pragma unroll
    for (int i = 0; i < 4; i++) {
        int idx = tid + i * 256;
        int r = idx >> 4, d4 = (idx & 15) << 2;
        float4 v = *(const float4*)(Qp + (size_t)r * DKK + d4);
        int kk = d4 >> 3, hh = (d4 >> 2) & 1;
        float* p = sm.Qs + ((kk * 4) * FQSTR + r) * 2 + hh;
        p[0]          = tf32f(v.x * 0.125f);
        p[FQSTR*2]    = tf32f(v.y * 0.125f);
        p[FQSTR*4]    = tf32f(v.z * 0.125f);
        p[FQSTR*6]    = tf32f(v.w * 0.125f);
    }

    float accO[2][2][4];
    #pragma unroll
    for (int i = 0; i < 2; i++)
        #pragma unroll
        for (int j = 0; j < 2; j++)
            #pragma unroll
            for (int q = 0; q < 4; q++) accO[i][j][q] = 0.f;

    float rowM = -1e30f, rowL = 0.f;
    const int myrow = tid >> 2, quarter = tid & 3;

    for (int t = 0; t < 16; t++) {
        float accS[2][2][4];
        const int kb = t * 64;
        #pragma unroll
        for (int i = 0; i < 2; i++) {
            int r = wm * 32 + i * 16 + g;
            #pragma unroll
            for (int j = 0; j < 2; j++) {
                int col = kb + wn * 16 + j * 8 + t4 * 2;
                float2 b0 = *(const float2*)(Sb + (size_t)r * LL + col);
                float2 b1 = *(const float2*)(Sb + (size_t)(r + 8) * LL + col);
                accS[i][j][0] = b0.x; accS[i][j][1] = b0.y;
                accS[i][j][2] = b1.x; accS[i][j][3] = b1.y;
            }
        }

        cp_wait<1>();
        __syncthreads();

        #pragma unroll
        for (int ks = 0; ks < 8; ks++) {
            const int kc = ks * 8 + t4;
            unsigned aF[2][4];
            #pragma unroll
            for (int i = 0; i < 2; i++) {
                int mb = wm * 32 + i * 16 + g;
                float2 lo = *(const float2*)(sm.Qs + ((ks * 4 + t4) * FQSTR + mb) * 2);
                float2 hi = *(const float2*)(sm.Qs + ((ks * 4 + t4) * FQSTR + mb + 8) * 2);
                aF[i][0] = __float_as_uint(lo.x); aF[i][1] = __float_as_uint(hi.x);
                aF[i][2] = __float_as_uint(lo.y); aF[i][3] = __float_as_uint(hi.y);
            }
            unsigned bF[2][2];
            #pragma unroll
            for (int j = 0; j < 2; j++) {
                int nb = wn * 16 + j * 8 + g;
                bF[j][0] = __float_as_uint(sm.Ks[nb * FQSTR + kc]);
                bF[j][1] = __float_as_uint(sm.Ks[nb * FQSTR + kc + 4]);
            }
            #pragma unroll
            for (int i = 0; i < 2; i++)
                #pragma unroll
                for (int j = 0; j < 2; j++)
                    mma_tf32(accS[i][j], aF[i], bF[j]);
        }

        {
            const int cc = (t4 & 1) * 2, hh = t4 >> 1;
            #pragma unroll
            for (int i = 0; i < 2; i++) {
                int r = wm * 32 + i * 16 + g;
                #pragma unroll
                for (int j = 0; j < 2; j++) {
                    int colk = (wn * 16 + j * 8 + t4 * 2) >> 3;
                    int e = (colk * 4 + cc) * FQSTR + r;
                    sm.Ss[e * 2 + hh]                 = accS[i][j][0];
                    sm.Ss[(e + FQSTR) * 2 + hh]       = accS[i][j][1];
                    sm.Ss[(e + 8) * 2 + hh]           = accS[i][j][2];
                    sm.Ss[(e + FQSTR + 8) * 2 + hh]   = accS[i][j][3];
                }
            }
        }
        __syncthreads();
        if (t + 1 < 16) loadK(t + 1);

        {
            float2 vals[8];
            float mx = -1e30f;
            #pragma unroll
            for (int e = 0; e < 8; e++) {
                int kk = 2 * quarter + (e >> 2), cc2 = e & 3;
                vals[e] = *(const float2*)(sm.Ss + ((kk * 4 + cc2) * FQSTR + myrow) * 2);
                mx = fmaxf(mx, fmaxf(vals[e].x, vals[e].y));
            }
            mx = fmaxf(mx, __shfl_xor_sync(0xffffffffu, mx, 1));
            mx = fmaxf(mx, __shfl_xor_sync(0xffffffffu, mx, 2));
            float mNew = fmaxf(rowM, mx);
            float scale = __expf(rowM - mNew);
            float sum = 0.f;
            #pragma unroll
            for (int e = 0; e < 8; e++) {
                vals[e].x = __expf(vals[e].x - mNew);
                vals[e].y = __expf(vals[e].y - mNew);
                sum += vals[e].x + vals[e].y;
                int kk = 2 * quarter + (e >> 2), cc2 = e & 3;
                *(float2*)(sm.Ss + ((kk * 4 + cc2) * FQSTR + myrow) * 2) =
                    make_float2(vals[e].x, vals[e].y);
            }
            sum += __shfl_xor_sync(0xffffffffu, sum, 1);
            sum += __shfl_xor_sync(0xffffffffu, sum, 2);
            rowL = rowL * scale + sum;
            rowM = mNew;
            if (quarter == 0) sm.rowScale[myrow] = scale;
        }
        if (t + 1 < 16) cp_wait<1>(); else cp_wait<0>();
        __syncthreads();

        #pragma unroll
        for (int i = 0; i < 2; i++) {
            int r = wm * 32 + i * 16 + g;
            float s0 = sm.rowScale[r], s1 = sm.rowScale[r + 8];
            #pragma unroll
            for (int j = 0; j < 2; j++) {
                accO[i][j][0] *= s0; accO[i][j][1] *= s0;
                accO[i][j][2] *= s1; accO[i][j][3] *= s1;
            }
        }

        #pragma unroll
        for (int ks = 0; ks < 8; ks++) {
            const int kc = ks * 8 + t4;
            unsigned aF[2][4];
            #pragma unroll
            for (int i = 0; i < 2; i++) {
                int mb = wm * 32 + i * 16 + g;
                float2 lo = *(const float2*)(sm.Ss + ((ks * 4 + t4) * FQSTR + mb) * 2);
                float2 hi = *(const float2*)(sm.Ss + ((ks * 4 + t4) * FQSTR + mb + 8) * 2);
                aF[i][0] = __float_as_uint(lo.x); aF[i][1] = __float_as_uint(hi.x);
                aF[i][2] = __float_as_uint(lo.y); aF[i][3] = __float_as_uint(hi.y);
            }
            unsigned bF[2][2];
            #pragma unroll
            for (int j = 0; j < 2; j++) {
                int nb = wn * 16 + j * 8 + g;
                bF[j][0] = __float_as_uint(sm.Vs[kc * FQSTR + nb]);
                bF[j][1] = __float_as_uint(sm.Vs[(kc + 4) * FQSTR + nb]);
            }
            #pragma unroll
            for (int i = 0; i < 2; i++)
                #pragma unroll
                for (int j = 0; j < 2; j++)
                    mma_tf32(accO[i][j], aF[i], bF[j]);
        }
        __syncthreads();
        if (t + 1 < 16) loadV(t + 1);
    }

    if (quarter == 0) sm.rowInv[myrow] = 1.f / rowL;
    __syncthreads();

    float* Op = O + ((size_t)b * LL + q0) * DM + h * DKK;
    #pragma unroll
    for (int i = 0; i < 2; i++) {
        int r = wm * 32 + i * 16 + g;
        float i0 = sm.rowInv[r], i1 = sm.rowInv[r + 8];
        #pragma unroll
        for (int j = 0; j < 2; j++) {
            int col = wn * 16 + j * 8 + t4 * 2;
            *(float2*)(Op + (size_t)r * DM + col) =
                make_float2(accO[i][j][0] * i0, accO[i][j][1] * i0);
            *(float2*)(Op + (size_t)(r + 8) * DM + col) =
                make_float2(accO[i][j][2] * i1, accO[i][j][3] * i1);
        }
    }
}

// ---------------- layernorm over last dim (768) ----------------
__global__ __launch_bounds__(256) void layernorm_kernel(
    const float* __restrict__ X, const float* __restrict__ g, const float* __restrict__ be,
    float* __restrict__ Y)
{
    __shared__ float red[256];
    const size_t row = blockIdx.x;
    const float* p = X + row * DM;
    float* o = Y + row * DM;
    const int tid = threadIdx.x;
    float v[3];
    float s = 0.f;
    #pragma unroll
    for (int i = 0; i < 3; i++) { v[i] = p[tid + i*256]; s += v[i]; }
    red[tid] = s; __syncthreads();
    for (int st = 128; st > 0; st >>= 1) { if (tid < st) red[tid] += red[tid+st]; __syncthreads(); }
    float mean = red[0] * (1.f/DM); __syncthreads();
    float sq = 0.f;
    #pragma unroll
    for (int i = 0; i < 3; i++) { float d = v[i] - mean; sq += d*d; }
    red[tid] = sq; __syncthreads();
    for (int st = 128; st > 0; st >>= 1) { if (tid < st) red[tid] += red[tid+st]; __syncthreads(); }
    float rstd = rsqrtf(red[0] * (1.f/DM) + 1e-5f);
    #pragma unroll
    for (int i = 0; i < 3; i++) {
        int c = tid + i*256;
        o[c] = (v[i] - mean) * rstd * g[c] + be[c];
    }
}

// ---------------- launch ----------------
extern "C" void kernel_launch(void* const* d_in, const int* in_sizes, int n_in,
                              void* d_out, int out_size)
{
    const float* src = (const float*)d_in[0];
    const float* sx  = (const float*)d_in[1];
    const float* sy  = (const float*)d_in[2];
    const float* Wq  = (const float*)d_in[3];  const float* bq  = (const float*)d_in[4];
    const float* Wk  = (const float*)d_in[5];  const float* bk  = (const float*)d_in[6];
    const float* Wv  = (const float*)d_in[7];  const float* bv  = (const float*)d_in[8];
    const float* Wo  = (const float*)d_in[9];  const float* bo  = (const float*)d_in[10];
    const float* P1  = (const float*)d_in[11]; const float* pb1 = (const float*)d_in[12];
    const float* P2  = (const float*)d_in[13]; const float* pb2 = (const float*)d_in[14];
    const float* W1  = (const float*)d_in[15]; const float* b1  = (const float*)d_in[16];
    const float* W2  = (const float*)d_in[17]; const float* b2  = (const float*)d_in[18];
    const float* g1  = (const float*)d_in[19]; const float* be1 = (const float*)d_in[20];
    const float* g2  = (const float*)d_in[21]; const float* be2 = (const float*)d_in[22];
    float* out = (float*)d_out;

    float *Q, *K, *V, *S, *O, *Xres, *X1, *H1;
    cudaGetSymbolAddress((void**)&Q,    g_Q);
    cudaGetSymbolAddress((void**)&K,    g_K);
    cudaGetSymbolAddress((void**)&V,    g_V);
    cudaGetSymbolAddress((void**)&S,    g_S);
    cudaGetSymbolAddress((void**)&O,    g_O);
    cudaGetSymbolAddress((void**)&Xres, g_Xres);
    cudaGetSymbolAddress((void**)&X1,   g_X1);
    cudaGetSymbolAddress((void**)&H1,   g_H1);

    cudaFuncSetAttribute(flash64_kernel, cudaFuncAttributeMaxDynamicSharedMemorySize,
                         (int)FL64_SMEM_BYTES);
    cudaFuncSetAttribute(pbqkv_kernel, cudaFuncAttributeMaxDynamicSharedMemorySize,
                         TG_SMEM(128, 128));
    cudaFuncSetAttribute(tgemm<1, 128, 128>, cudaFuncAttributeMaxDynamicSharedMemorySize,
                         TG_SMEM(128, 128));
    cudaFuncSetAttribute(tgemm<2, 64, 64>, cudaFuncAttributeMaxDynamicSharedMemorySize,
                         TG_SMEM(64, 64));

    // 1) fused: relative-position bias -> S  ||  QKV projections -> Q,K,V
    pbqkv_kernel<<<PBQKV_GRID, 256, TG_SMEM(128, 128)>>>(
        src, Wq, bq, Wk, bk, Wv, bv, Q, K, V,
        sx, sy, P1, pb1, P2, pb2, S);

    // 2) flash attention: softmax(QK^T/8 + bias) @ V -> O
    flash64_kernel<<<dim3(LL/64, BB*NH), 256, FL64_SMEM_BYTES>>>(S, Q, K, V, O);

    // 3) Xres = src + O @ Wo + bo ; LN1 -> X1
    tgemm<2, 64, 64><<<dim3(DM/64, ROWS/64, 1), 256, TG_SMEM(64, 64)>>>(
        O, DM, Wo, DM, bo, src, Xres, DM, DM,
        nullptr, nullptr, nullptr, nullptr, nullptr, nullptr);
    layernorm_kernel<<<ROWS, 256>>>(Xres, g1, be1, X1);

    // 4) FFN
    tgemm<1, 128, 128><<<dim3(FFD/128, ROWS/128, 1), 256, TG_SMEM(128, 128)>>>(
        X1, DM, W1, FFD, b1, nullptr, H1, FFD, DM,
        nullptr, nullptr, nullptr, nullptr, nullptr, nullptr);
    tgemm<2, 64, 64><<<dim3(DM/64, ROWS/64, 1), 256, TG_SMEM(64, 64)>>>(
        H1, FFD, W2, DM, b2, X1, Xres, DM, FFD,
        nullptr, nullptr, nullptr, nullptr, nullptr, nullptr);

    // 5) LN2 -> output
    layernorm_kernel<<<ROWS, 256>>>(Xres, g2, be2, out);
}